// round 10
// baseline (speedup 1.0000x reference)
#include <cuda_runtime.h>
#include <cuda_fp16.h>
#include <math.h>
#include <stdint.h>

#define CK_B   4
#define CK_S   512
#define CK_D   2048
#define CK_H   16
#define CK_KV  4
#define CK_HD  128
#define CK_T   2048          // B*S
#define CK_FFN 5632
#define CK_E   8
#define CK_R   16
#define CK_LS  2.0f          // 32/16

// ---------------------------------------------------------------------------
// fp32 scratch
// ---------------------------------------------------------------------------
__device__ float g_hn  [CK_T*CK_D];
__device__ float g_sc  [(size_t)CK_B*CK_H*CK_S*CK_S];
__device__ float g_d2  [CK_T*CK_D];
__device__ float g_route[CK_T*CK_E];
__device__ float g_v2  [CK_T*CK_E*CK_R];
__device__ float g_fpre[CK_T*CK_D];
__device__ float g_Uqkv[CK_T*128];
__device__ float g_Uo  [CK_T*128];
__device__ float g_Ue  [CK_T*512];
__device__ int   g_cnt [8];
__device__ int   g_listE[8*2048];
__device__ float g_wgtE [8*2048];
__device__ int   g_slotE[8*2048];

// ---------------------------------------------------------------------------
// fp16 scratch
// ---------------------------------------------------------------------------
#define NWQ (CK_D*CK_D)
#define NWK (512*CK_D)
#define NW1 (CK_FFN*CK_D)
#define NEB (CK_E*CK_FFN*CK_R)
#define NB2 (CK_E*CK_D*CK_R)
__device__ __align__(16) __half g_wqh[NWQ];
__device__ __align__(16) __half g_wkh[NWK];
__device__ __align__(16) __half g_wvh[NWK];
__device__ __align__(16) __half g_woh[NWQ];
__device__ __align__(16) __half g_w1h[NW1];
__device__ __align__(16) __half g_w3h[NW1];
__device__ __align__(16) __half g_w2h[NW1];
__device__ __align__(16) __half g_xh [CK_T*CK_D];               // h  fp16
__device__ __align__(16) __half g_aoh[CK_T*CK_D];               // ao fp16
__device__ __align__(16) __half g_hnh[CK_T*CK_D];               // hn fp16
__device__ __align__(16) __half g_gsh[(size_t)CK_T*CK_FFN];     // ghs fp16
__device__ __align__(16) __half g_xqp[CK_T*CK_D];               // q pre-rope
__device__ __align__(16) __half g_xkp[CK_T*512];                // k pre-rope
__device__ __align__(16) __half g_xvh[CK_T*512];                // v fp16
__device__ __align__(16) __half g_xqh[CK_T*CK_D];               // rope(q)
__device__ __align__(16) __half g_xkh[CK_T*512];                // rope(k)
__device__ __align__(16) __half g_vth[CK_T*512];                // V^T
__device__ __align__(16) __half g_sch[(size_t)CK_B*CK_H*CK_S*CK_S]; // attn
__device__ __align__(16) __half g_h1h[(size_t)CK_T*CK_FFN];
__device__ __align__(16) __half g_h3h[(size_t)CK_T*CK_FFN];
__device__ __align__(16) __half g_gp [(size_t)2*CK_T*CK_FFN];   // per-slot gh
__device__ __align__(16) __half g_eB1h[NEB], g_eB3h[NEB];
__device__ __align__(16) __half g_eA2t[NEB];                    // transposed [e][f][16]
__device__ __align__(16) __half g_eB2h[NB2];
__device__ __align__(16) __half g_Aqkv[128*CK_D];
__device__ __align__(16) __half g_Ao  [128*CK_D];
__device__ __align__(16) __half g_Ae  [512*CK_D];

// ===========================================================================
// helpers
// ===========================================================================
__device__ __forceinline__ uint32_t smem_u32(const void* p) {
    uint32_t a;
    asm("{ .reg .u64 t; cvta.to.shared.u64 t, %1; cvt.u32.u64 %0, t; }" : "=r"(a) : "l"(p));
    return a;
}
#define CP_ASYNC16(dst_u32, src_ptr) \
    asm volatile("cp.async.cg.shared.global [%0], [%1], 16;" :: "r"(dst_u32), "l"(src_ptr))
#define CP_COMMIT() asm volatile("cp.async.commit_group;" ::: "memory")
#define CP_WAIT(n)  asm volatile("cp.async.wait_group %0;" :: "n"(n) : "memory")

__device__ __forceinline__ void mma16816(float* d, const uint32_t* a,
                                         uint32_t b0, uint32_t b1) {
    asm volatile(
        "mma.sync.aligned.m16n8k16.row.col.f32.f16.f16.f32 "
        "{%0,%1,%2,%3}, {%4,%5,%6,%7}, {%8,%9}, {%0,%1,%2,%3};"
        : "+f"(d[0]), "+f"(d[1]), "+f"(d[2]), "+f"(d[3])
        : "r"(a[0]), "r"(a[1]), "r"(a[2]), "r"(a[3]), "r"(b0), "r"(b1));
}

__device__ __forceinline__ void store4h(__half* p, float4 v) {
    *(__half2*)(p + 0) = __floats2half2_rn(v.x, v.y);
    *(__half2*)(p + 2) = __floats2half2_rn(v.z, v.w);
}

// MUFU-free e^x (bit-trick 2^n scaling + deg-5 poly; rel err ~2e-6; clamped)
__device__ __forceinline__ float fexp(float x) {
    float t = fminf(fmaxf(x * 1.4426950408889634f, -30.f), 30.f);
    float n = rintf(t);
    float f = t - n;
    float p = 1.f + f*(0.6931471806f + f*(0.2402265069f + f*(0.0555041087f
            + f*(0.0096181291f + f*0.0013333558f))));
    return __int_as_float(((int)n + 127) << 23) * p;
}

// fp32 -> fp16, 16 elems/thread
__global__ void k_half16(const float* __restrict__ x, __half* __restrict__ h, int n) {
    int i = (blockIdx.x*256 + threadIdx.x)*16;
    if (i >= n) return;
    #pragma unroll
    for (int q = 0; q < 4; q++) store4h(h + i + q*4, *(const float4*)(x + i + q*4));
}

// pack up to 3 fp32 [16*k, D] mats into a zero-padded fp16 [rows, D]
__global__ void k_pack3(const float* __restrict__ s0, const float* __restrict__ s1,
                        const float* __restrict__ s2, int r0, int r1, int r2,
                        __half* __restrict__ dst, int rows) {
    int i = (blockIdx.x*256 + threadIdx.x)*8;
    if (i >= rows*CK_D) return;
    int row = i >> 11;
    const float* src = nullptr; int off = 0;
    if (row < r0)            { src = s0; off = row*CK_D; }
    else if (row < r0+r1)    { src = s1; off = (row-r0)*CK_D; }
    else if (row < r0+r1+r2) { src = s2; off = (row-r0-r1)*CK_D; }
    int col = i & 2047;
    if (src) {
        store4h(dst+i,   *(const float4*)(src+off+col));
        store4h(dst+i+4, *(const float4*)(src+off+col+4));
    } else {
        *(uint4*)(dst+i) = make_uint4(0,0,0,0);
    }
}

// eA2[e][r][f] fp32 -> eA2t[e][f][r] fp16
__global__ void k_trA2(const float* __restrict__ a2, __half* __restrict__ dst) {
    int e = blockIdx.y;
    int f = blockIdx.x*256 + threadIdx.x;
    const float* src = a2 + (size_t)e*16*CK_FFN + f;
    __half* d = dst + ((size_t)e*CK_FFN + f)*16;
    #pragma unroll
    for (int r = 0; r < 16; r++) d[r] = __float2half_rn(src[(size_t)r*CK_FFN]);
}

__global__ void k_zero8(int* c) { if (threadIdx.x < 8) c[threadIdx.x] = 0; }

// ===========================================================================
// k_hgemm4: 1-pass fp16 tensor-core GEMM, cp.async double-buffered
//   out = A @ W^T [+ lscale*U@V^T] ; out -> C fp32 (+res) or Ch fp16
// ===========================================================================
#define HG_LD   40
#define HG_TILE (128*HG_LD)
#define HG_TILEB (HG_TILE*2)
#define HG_SMEM (4*HG_TILEB)     // 40960 bytes

__global__ void __launch_bounds__(256, 2) k_hgemm4(
    const __half* __restrict__ A, const __half* __restrict__ W,
    float* __restrict__ C, __half* __restrict__ Ch, int M, int N, int K,
    const float* __restrict__ U, int ustride, const float* __restrict__ V,
    float lscale, const float* __restrict__ res)
{
    extern __shared__ __align__(16) __half sm[];
    __half* pA = sm;
    __half* pW = sm + 2*HG_TILE;
    const uint32_t sbA = smem_u32(sm);
    const uint32_t sbW = sbA + 2*HG_TILEB;

    const int tid  = threadIdx.x;
    const int wid  = tid >> 5, lane = tid & 31;
    const int g    = lane >> 2, tg = lane & 3;
    const int warpM = wid & 3;
    const int warpN = wid >> 2;
    const int bm = blockIdx.y * 128;
    const int bn = blockIdx.x * 128;

    float acc[2][8][4];
    #pragma unroll
    for (int mi = 0; mi < 2; mi++)
        #pragma unroll
        for (int ni = 0; ni < 8; ni++)
            #pragma unroll
            for (int q = 0; q < 4; q++) acc[mi][ni][q] = 0.f;

    const int NC = K / 32;
    const int total = NC + (U ? 1 : 0);

    auto load_async = [&](int c, int buf) {
        const int k0 = c * 32;
        const uint32_t bo = (uint32_t)buf * HG_TILEB;
        #pragma unroll
        for (int it = 0; it < 2; it++) {
            int id = it*256 + tid;
            int r = id >> 2, sg = (id & 3) * 8;
            uint32_t so = bo + (uint32_t)(r*HG_LD + sg)*2;
            CP_ASYNC16(sbA + so, A + (size_t)(bm + r)*K + k0 + sg);
            CP_ASYNC16(sbW + so, W + (size_t)(bn + r)*K + k0 + sg);
        }
        CP_COMMIT();
    };

    auto load_lora = [&](int buf) {
        __half* dA = pA + buf*HG_TILE;
        __half* dW = pW + buf*HG_TILE;
        #pragma unroll
        for (int l = 0; l < 4; l++) {
            int id = l*256 + tid;
            int r = id >> 3, c4 = (id & 7)*4;
            float4 va = make_float4(0.f,0.f,0.f,0.f);
            float4 vw = make_float4(0.f,0.f,0.f,0.f);
            if (c4 < 16) {
                va = *(const float4*)(U + (size_t)(bm + r)*ustride + c4);
                va.x *= lscale; va.y *= lscale; va.z *= lscale; va.w *= lscale;
                vw = *(const float4*)(V + (size_t)(bn + r)*16 + c4);
            }
            store4h(dA + r*HG_LD + c4, va);
            store4h(dW + r*HG_LD + c4, vw);
        }
    };

    load_async(0, 0);

    for (int c = 0; c < total; c++) {
        const int cur = c & 1, nb = (c + 1) & 1;
        const bool have_next = (c + 1 < total);
        const bool next_async = (c + 1 < NC);
        if (have_next) {
            if (next_async) load_async(c + 1, nb);
            else            load_lora(nb);
        }
        if (c < NC) {
            if (have_next && next_async) { CP_WAIT(1); }
            else                         { CP_WAIT(0); }
        }
        __syncthreads();

        const __half* bA = pA + cur*HG_TILE;
        const __half* bW = pW + cur*HG_TILE;

        #pragma unroll
        for (int ks = 0; ks < 2; ks++) {
            const int col0 = ks*16 + tg*2;
            uint32_t a[2][4];
            #pragma unroll
            for (int mi = 0; mi < 2; mi++) {
                int r0 = warpM*32 + mi*16 + g;
                a[mi][0] = *(const uint32_t*)(bA + r0*HG_LD + col0);
                a[mi][1] = *(const uint32_t*)(bA + (r0+8)*HG_LD + col0);
                a[mi][2] = *(const uint32_t*)(bA + r0*HG_LD + col0 + 8);
                a[mi][3] = *(const uint32_t*)(bA + (r0+8)*HG_LD + col0 + 8);
            }
            #pragma unroll
            for (int ni = 0; ni < 8; ni++) {
                int rn = warpN*64 + ni*8 + g;
                uint32_t b0 = *(const uint32_t*)(bW + rn*HG_LD + col0);
                uint32_t b1 = *(const uint32_t*)(bW + rn*HG_LD + col0 + 8);
                #pragma unroll
                for (int mi = 0; mi < 2; mi++)
                    mma16816(acc[mi][ni], a[mi], b0, b1);
            }
        }
        __syncthreads();
    }

    #pragma unroll
    for (int mi = 0; mi < 2; mi++) {
        size_t r0 = (size_t)(bm + warpM*32 + mi*16 + g);
        #pragma unroll
        for (int ni = 0; ni < 8; ni++) {
            size_t c0 = (size_t)(bn + warpN*64 + ni*8 + tg*2);
            if (Ch) {
                *(__half2*)(Ch + r0*N + c0) =
                    __floats2half2_rn(acc[mi][ni][0], acc[mi][ni][1]);
                *(__half2*)(Ch + (r0+8)*N + c0) =
                    __floats2half2_rn(acc[mi][ni][2], acc[mi][ni][3]);
            } else {
                float2 o0 = make_float2(acc[mi][ni][0], acc[mi][ni][1]);
                float2 o1 = make_float2(acc[mi][ni][2], acc[mi][ni][3]);
                if (res) {
                    float2 r0v = *(const float2*)(res + r0*N + c0);
                    float2 r1v = *(const float2*)(res + (r0+8)*N + c0);
                    o0.x += r0v.x; o0.y += r0v.y;
                    o1.x += r1v.x; o1.y += r1v.y;
                }
                *(float2*)(C + r0*N + c0)     = o0;
                *(float2*)(C + (r0+8)*N + c0) = o1;
            }
        }
    }
}

// ===========================================================================
// k_scores_h: scores = Q@K^T / sqrt(HD), fp16 tensor cores, causal tile skip
// ===========================================================================
#define SC_LD 136
#define SC_SMEM (2*128*SC_LD*2)

__global__ void __launch_bounds__(256) k_scores_h(const __half* __restrict__ q,
                                                  const __half* __restrict__ k,
                                                  float* __restrict__ sc) {
    const int t0 = blockIdx.x*128, s0 = blockIdx.y*128;
    if (t0 > s0) return;
    const int bh = blockIdx.z, b = bh >> 4, h = bh & 15, kv = h >> 2;
    extern __shared__ __align__(16) __half sm[];
    __half* Qs = sm;
    __half* Ks = sm + 128*SC_LD;

    const int tid = threadIdx.x;
    const int wid = tid >> 5, lane = tid & 31;
    const int g = lane >> 2, tg = lane & 3;
    const int warpM = wid & 3, warpN = wid >> 2;

    #pragma unroll
    for (int it = 0; it < 8; it++) {
        int id = it*256 + tid;
        int r = id >> 4, c8 = (id & 15)*8;
        *(uint4*)(Qs + r*SC_LD + c8) =
            *(const uint4*)(q + ((size_t)(b*CK_S + s0 + r)*CK_D + h*CK_HD + c8));
        *(uint4*)(Ks + r*SC_LD + c8) =
            *(const uint4*)(k + ((size_t)(b*CK_S + t0 + r)*(CK_KV*CK_HD) + kv*CK_HD + c8));
    }
    __syncthreads();

    float acc[2][8][4];
    #pragma unroll
    for (int mi = 0; mi < 2; mi++)
        #pragma unroll
        for (int ni = 0; ni < 8; ni++)
            #pragma unroll
            for (int qq = 0; qq < 4; qq++) acc[mi][ni][qq] = 0.f;

    #pragma unroll
    for (int ks = 0; ks < 8; ks++) {
        const int col0 = ks*16 + tg*2;
        uint32_t a[2][4];
        #pragma unroll
        for (int mi = 0; mi < 2; mi++) {
            int r0 = warpM*32 + mi*16 + g;
            a[mi][0] = *(const uint32_t*)(Qs + r0*SC_LD + col0);
            a[mi][1] = *(const uint32_t*)(Qs + (r0+8)*SC_LD + col0);
            a[mi][2] = *(const uint32_t*)(Qs + r0*SC_LD + col0 + 8);
            a[mi][3] = *(const uint32_t*)(Qs + (r0+8)*SC_LD + col0 + 8);
        }
        #pragma unroll
        for (int ni = 0; ni < 8; ni++) {
            int rn = warpN*64 + ni*8 + g;
            uint32_t b0 = *(const uint32_t*)(Ks + rn*SC_LD + col0);
            uint32_t b1 = *(const uint32_t*)(Ks + rn*SC_LD + col0 + 8);
            #pragma unroll
            for (int mi = 0; mi < 2; mi++)
                mma16816(acc[mi][ni], a[mi], b0, b1);
        }
    }

    const float scl = 0.08838834764831845f;
    float* out = sc + (size_t)bh*CK_S*CK_S;
    #pragma unroll
    for (int mi = 0; mi < 2; mi++) {
        size_t r0 = (size_t)(s0 + warpM*32 + mi*16 + g);
        #pragma unroll
        for (int ni = 0; ni < 8; ni++) {
            size_t c0 = (size_t)(t0 + warpN*64 + ni*8 + tg*2);
            *(float2*)(out + r0*CK_S + c0) =
                make_float2(acc[mi][ni][0]*scl, acc[mi][ni][1]*scl);
            *(float2*)(out + (r0+8)*CK_S + c0) =
                make_float2(acc[mi][ni][2]*scl, acc[mi][ni][3]*scl);
        }
    }
}

// ===========================================================================
// k_avh: out(fp16) = attn(fp16) @ V^T(fp16), causal K-bound
// ===========================================================================
__global__ void __launch_bounds__(256, 2) k_avh(const __half* __restrict__ attn,
                                                const __half* __restrict__ vt,
                                                __half* __restrict__ outh) {
    extern __shared__ __align__(16) __half sm[];
    __half* pA = sm;
    __half* pW = sm + 2*HG_TILE;
    const uint32_t sbA = smem_u32(sm);
    const uint32_t sbW = sbA + 2*HG_TILEB;

    const int s0 = blockIdx.y * 128;
    const int bh = blockIdx.z, b = bh >> 4, h = bh & 15, kv = h >> 2;
    const __half* Ab = attn + (size_t)bh*CK_S*CK_S;
    const __half* Wb = vt + ((size_t)(b*CK_KV + kv)*CK_HD)*CK_S;

    const int tid = threadIdx.x;
    const int wid = tid >> 5, lane = tid & 31;
    const int g = lane >> 2, tg = lane & 3;
    const int warpM = wid & 3, warpN = wid >> 2;

    float acc[2][8][4];
    #pragma unroll
    for (int mi = 0; mi < 2; mi++)
        #pragma unroll
        for (int ni = 0; ni < 8; ni++)
            #pragma unroll
            for (int q = 0; q < 4; q++) acc[mi][ni][q] = 0.f;

    const int NC = (s0 + 128) / 32;

    auto load_async = [&](int c, int buf) {
        const int k0 = c * 32;
        const uint32_t bo = (uint32_t)buf * HG_TILEB;
        #pragma unroll
        for (int it = 0; it < 2; it++) {
            int id = it*256 + tid;
            int r = id >> 2, sg = (id & 3) * 8;
            uint32_t so = bo + (uint32_t)(r*HG_LD + sg)*2;
            CP_ASYNC16(sbA + so, Ab + (size_t)(s0 + r)*CK_S + k0 + sg);
            CP_ASYNC16(sbW + so, Wb + (size_t)r*CK_S + k0 + sg);
        }
        CP_COMMIT();
    };

    load_async(0, 0);
    for (int c = 0; c < NC; c++) {
        const int cur = c & 1;
        if (c + 1 < NC) { load_async(c + 1, (c+1)&1); CP_WAIT(1); }
        else            { CP_WAIT(0); }
        __syncthreads();

        const __half* bA = pA + cur*HG_TILE;
        const __half* bW = pW + cur*HG_TILE;
        #pragma unroll
        for (int ks = 0; ks < 2; ks++) {
            const int col0 = ks*16 + tg*2;
            uint32_t a[2][4];
            #pragma unroll
            for (int mi = 0; mi < 2; mi++) {
                int r0 = warpM*32 + mi*16 + g;
                a[mi][0] = *(const uint32_t*)(bA + r0*HG_LD + col0);
                a[mi][1] = *(const uint32_t*)(bA + (r0+8)*HG_LD + col0);
                a[mi][2] = *(const uint32_t*)(bA + r0*HG_LD + col0 + 8);
                a[mi][3] = *(const uint32_t*)(bA + (r0+8)*HG_LD + col0 + 8);
            }
            #pragma unroll
            for (int ni = 0; ni < 8; ni++) {
                int rn = warpN*64 + ni*8 + g;
                uint32_t b0 = *(const uint32_t*)(bW + rn*HG_LD + col0);
                uint32_t b1 = *(const uint32_t*)(bW + rn*HG_LD + col0 + 8);
                #pragma unroll
                for (int mi = 0; mi < 2; mi++)
                    mma16816(acc[mi][ni], a[mi], b0, b1);
            }
        }
        __syncthreads();
    }

    #pragma unroll
    for (int mi = 0; mi < 2; mi++) {
        int s = s0 + warpM*32 + mi*16 + g;
        #pragma unroll
        for (int ni = 0; ni < 8; ni++) {
            int c0 = warpN*64 + ni*8 + tg*2;
            size_t off0 = ((size_t)(b*CK_S + s)*CK_H + h)*CK_HD + c0;
            size_t off1 = ((size_t)(b*CK_S + s + 8)*CK_H + h)*CK_HD + c0;
            *(__half2*)(outh + off0) = __floats2half2_rn(acc[mi][ni][0], acc[mi][ni][1]);
            *(__half2*)(outh + off1) = __floats2half2_rn(acc[mi][ni][2], acc[mi][ni][3]);
        }
    }
}

// ---------------------------------------------------------------------------
// k_vt: V fp16 [t][kv*HD] -> V^T fp16 [b][kv][hd][s]
// ---------------------------------------------------------------------------
__global__ void k_vt(const __half* __restrict__ xv, __half* __restrict__ vt) {
    int bkv = blockIdx.z, b = bkv >> 2, kv = bkv & 3;
    int s0 = blockIdx.x*32, h0 = blockIdx.y*32;
    __shared__ __half t[32][33];
    int x = threadIdx.x & 31, y = threadIdx.x >> 5;
    for (int i = y; i < 32; i += 8)
        t[i][x] = xv[(size_t)(b*CK_S + s0 + i)*(CK_KV*CK_HD) + kv*CK_HD + h0 + x];
    __syncthreads();
    for (int i = y; i < 32; i += 8)
        vt[((size_t)bkv*CK_HD + h0 + i)*CK_S + s0 + x] = t[x][i];
}

// ---------------------------------------------------------------------------
// RMSNorm (fp32 out optional + fp16 out)
// ---------------------------------------------------------------------------
__global__ void k_rmsnorm(const float* __restrict__ x, const float* __restrict__ w,
                          float* __restrict__ o, __half* __restrict__ oh) {
    int t = blockIdx.x;
    const float* xr = x + (size_t)t*CK_D;
    float ss = 0.f;
    for (int i = threadIdx.x; i < CK_D; i += 256) { float v = xr[i]; ss += v*v; }
    __shared__ float red[256];
    red[threadIdx.x] = ss; __syncthreads();
    for (int s = 128; s > 0; s >>= 1) {
        if (threadIdx.x < s) red[threadIdx.x] += red[threadIdx.x+s];
        __syncthreads();
    }
    float sc = rsqrtf(red[0]/(float)CK_D + 1e-5f);
    __half* hrow = oh + (size_t)t*CK_D;
    for (int i = threadIdx.x; i < CK_D; i += 256) {
        float r = xr[i]*sc*w[i];
        if (o) o[(size_t)t*CK_D + i] = r;
        hrow[i] = __float2half_rn(r);
    }
}

// ---------------------------------------------------------------------------
// RoPE: fp16 in/out
// ---------------------------------------------------------------------------
__global__ void k_rope_h(const __half* __restrict__ x, const float* __restrict__ cs,
                         const float* __restrict__ sn, int nh, int total,
                         __half* __restrict__ oh) {
    int i = blockIdx.x*256 + threadIdx.x;
    if (i >= total) return;
    int d2 = i & 63;
    int h  = (i >> 6) % nh;
    int t  = i / (64*nh);
    int s  = t & (CK_S - 1);
    float c  = cs[s*64 + d2];
    float si = sn[s*64 + d2];
    size_t off = ((size_t)t*nh + h)*CK_HD + 2*d2;
    __half2 v = *(const __half2*)(x + off);
    float x1 = __low2float(v), x2 = __high2float(v);
    *(__half2*)(oh + off) = __floats2half2_rn(x1*c - x2*si, x1*si + x2*c);
}

// ---------------------------------------------------------------------------
// Causal softmax (MUFU-free exp): fp32 scores in, fp16 attn out
// ---------------------------------------------------------------------------
__global__ void k_softmax(const float* __restrict__ sc, __half* __restrict__ sch) {
    int row = blockIdx.x;
    int s = row & (CK_S - 1);
    const float* p = sc + (size_t)row*CK_S;
    __half* ph = sch + (size_t)row*CK_S;
    int L = s + 1;
    int tid = threadIdx.x;
    float v0 = (tid       < L) ? p[tid]       : -1e30f;
    float v1 = (tid + 256 < L) ? p[tid + 256] : -1e30f;
    __shared__ float red[256];
    red[tid] = fmaxf(v0, v1); __syncthreads();
    for (int st = 128; st; st >>= 1) {
        if (tid < st) red[tid] = fmaxf(red[tid], red[tid+st]);
        __syncthreads();
    }
    float m = red[0]; __syncthreads();
    float e0 = (tid       < L) ? fexp(v0 - m) : 0.f;
    float e1 = (tid + 256 < L) ? fexp(v1 - m) : 0.f;
    red[tid] = e0 + e1; __syncthreads();
    for (int st = 128; st; st >>= 1) {
        if (tid < st) red[tid] += red[tid+st];
        __syncthreads();
    }
    float inv = 1.f / red[0];
    ph[tid]       = __float2half_rn(e0 * inv);
    ph[tid + 256] = __float2half_rn(e1 * inv);
}

// ---------------------------------------------------------------------------
// Gate: logits -> top2 route + per-expert token lists
// ---------------------------------------------------------------------------
__global__ void k_gate(const float* __restrict__ hn, const float* __restrict__ gw,
                       float* __restrict__ route, int* __restrict__ cnt,
                       int* __restrict__ list, float* __restrict__ wgt,
                       int* __restrict__ slot) {
    int t = blockIdx.x;
    __shared__ float sl[8];
    int w = threadIdx.x >> 5, lane = threadIdx.x & 31;
    const float* xr = hn + (size_t)t*CK_D;
    const float* gr = gw + (size_t)w*CK_D;
    float p = 0.f;
    for (int d = lane; d < CK_D; d += 32) p += xr[d]*gr[d];
    for (int o = 16; o; o >>= 1) p += __shfl_down_sync(0xffffffffu, p, o);
    if (lane == 0) sl[w] = p;
    __syncthreads();
    if (threadIdx.x == 0) {
        int i0 = 0;
        for (int e = 1; e < 8; e++) if (sl[e] > sl[i0]) i0 = e;
        int i1 = -1;
        for (int e = 0; e < 8; e++) { if (e == i0) continue; if (i1 < 0 || sl[e] > sl[i1]) i1 = e; }
        float m = sl[i0];
        float v0 = expf(sl[i0]-m), v1 = expf(sl[i1]-m);
        float inv = 1.f/(v0+v1);
        float* rr = route + (size_t)t*CK_E;
        #pragma unroll
        for (int e = 0; e < 8; e++) rr[e] = 0.f;
        rr[i0] = v0*inv; rr[i1] = v1*inv;
        int p0 = atomicAdd(&cnt[i0], 1);
        list[i0*2048 + p0] = t; wgt[i0*2048 + p0] = v0*inv; slot[i0*2048 + p0] = 0;
        int p1 = atomicAdd(&cnt[i1], 1);
        list[i1*2048 + p1] = t; wgt[i1*2048 + p1] = v1*inv; slot[i1*2048 + p1] = 1;
    }
}

// ===========================================================================
// k_moe_em: expert-major MoE. 64 tokens/block share expert-mat smem tiles.
//   gp[slot][t][f] = w*silu(g1)*g3 ; v2[t][e][r] = w*LS*sum_f gh*A2[r][f]
// ===========================================================================
#define EM_FC 512
#define EM_SMEM (3*EM_FC*16*2 + 3*64*16*4 + 64*12)   // 62208

__global__ void __launch_bounds__(256, 2) k_moe_em(
    const __half* __restrict__ h1, const __half* __restrict__ h3,
    const float* __restrict__ Ue,
    const __half* __restrict__ eB1, const __half* __restrict__ eB3,
    const __half* __restrict__ eA2t,
    const int* __restrict__ cnt, const int* __restrict__ list,
    const float* __restrict__ wgt, const int* __restrict__ slot,
    __half* __restrict__ gp, float* __restrict__ v2)
{
    const int e = blockIdx.y;
    const int n = cnt[e];
    const int t0 = blockIdx.x * 64;
    if (t0 >= n) return;
    const int nt = min(64, n - t0);

    extern __shared__ __align__(16) char smraw[];
    __half* B1s = (__half*)smraw;
    __half* B3s = B1s + EM_FC*16;
    __half* A2s = B3s + EM_FC*16;
    float*  u1s = (float*)(A2s + EM_FC*16);
    float*  u3s = u1s + 64*16;
    float*  acc2 = u3s + 64*16;
    int*    toks = (int*)(acc2 + 64*16);
    float*  wgts = (float*)(toks + 64);
    int*    slts = (int*)(wgts + 64);

    const int tid = threadIdx.x;
    const int wid = tid >> 5, lane = tid & 31;

    if (tid < nt) {
        int idx = e*2048 + t0 + tid;
        toks[tid] = list[idx];
        wgts[tid] = wgt[idx];
        slts[tid] = slot[idx];
    }
    __syncthreads();
    for (int i = tid; i < nt*16; i += 256) {
        int j = i >> 4, r = i & 15;
        int t = toks[j];
        u1s[i] = Ue[(size_t)t*512 + e*16 + r];
        u3s[i] = Ue[(size_t)t*512 + 256 + e*16 + r];
        acc2[i] = 0.f;
    }

    for (int fc = 0; fc < CK_FFN; fc += EM_FC) {
        __syncthreads();
        const uint4* gB1 = (const uint4*)(eB1 + ((size_t)e*CK_FFN + fc)*16);
        const uint4* gB3 = (const uint4*)(eB3 + ((size_t)e*CK_FFN + fc)*16);
        const uint4* gA2 = (const uint4*)(eA2t + ((size_t)e*CK_FFN + fc)*16);
        uint4* sB1 = (uint4*)B1s;
        uint4* sB3 = (uint4*)B3s;
        uint4* sA2 = (uint4*)A2s;
        #pragma unroll
        for (int i = tid; i < EM_FC*2; i += 256) {   // EM_FC*16/8 = 1024
            sB1[i] = gB1[i]; sB3[i] = gB3[i]; sA2[i] = gA2[i];
        }
        __syncthreads();

        for (int j = wid; j < nt; j += 8) {
            const int t = toks[j];
            const __half* h1r = h1 + (size_t)t*CK_FFN + fc;
            const __half* h3r = h3 + (size_t)t*CK_FFN + fc;
            __half* gout = gp + ((size_t)slts[j]*CK_T + t)*CK_FFN + fc;
            const float w = wgts[j];
            float u1r[16], u3r[16];
            #pragma unroll
            for (int r = 0; r < 16; r++) { u1r[r] = u1s[j*16+r]; u3r[r] = u3s[j*16+r]; }
            float accr[16];
            #pragma unroll
            for (int r = 0; r < 16; r++) accr[r] = 0.f;

            #pragma unroll
            for (int itg = 0; itg < 4; itg++) {
                float g1v[4], g3v[4], ev[4];
                const int flb = itg*128 + lane;
                #pragma unroll
                for (int q = 0; q < 4; q++) {
                    int fl = flb + q*32;
                    const __half2* b1p = (const __half2*)(B1s + fl*16);
                    const __half2* b3p = (const __half2*)(B3s + fl*16);
                    float b1 = 0.f, b3 = 0.f;
                    #pragma unroll
                    for (int qq = 0; qq < 8; qq++) {
                        float2 x1 = __half22float2(b1p[qq]);
                        float2 x3 = __half22float2(b3p[qq]);
                        b1 += u1r[2*qq]*x1.x + u1r[2*qq+1]*x1.y;
                        b3 += u3r[2*qq]*x3.x + u3r[2*qq+1]*x3.y;
                    }
                    g1v[q] = __half2float(h1r[fl]) + CK_LS*b1;
                    g3v[q] = __half2float(h3r[fl]) + CK_LS*b3;
                    ev[q]  = fexp(-g1v[q]);
                }
                // batched reciprocal: one rcp.approx for 4 sigmoids
                float d0 = 1.f+ev[0], d1 = 1.f+ev[1], d2v = 1.f+ev[2], d3 = 1.f+ev[3];
                float rall;
                asm("rcp.approx.f32 %0, %1;" : "=f"(rall) : "f"(d0*d1*d2v*d3));
                float r01 = rall*d2v*d3, r23 = rall*d0*d1;
                float inv[4] = { r01*d1, r01*d0, r23*d3, r23*d2v };
                #pragma unroll
                for (int q = 0; q < 4; q++) {
                    int fl = flb + q*32;
                    float gh = g1v[q]*inv[q]*g3v[q];
                    gout[fl] = __float2half_rn(w*gh);
                    const __half2* a2p = (const __half2*)(A2s + fl*16);
                    #pragma unroll
                    for (int qq = 0; qq < 8; qq++) {
                        float2 a2 = __half22float2(a2p[qq]);
                        accr[2*qq]   += gh*a2.x;
                        accr[2*qq+1] += gh*a2.y;
                    }
                }
            }
            #pragma unroll
            for (int r = 0; r < 16; r++) {
                float v = accr[r];
                #pragma unroll
                for (int o = 16; o; o >>= 1) v += __shfl_down_sync(0xffffffffu, v, o);
                if (lane == 0) acc2[j*16+r] += v;
            }
        }
    }
    __syncthreads();
    for (int i = tid; i < nt*16; i += 256) {
        int j = i >> 4, r = i & 15;
        v2[((size_t)toks[j]*CK_E + e)*16 + r] = wgts[j]*CK_LS*acc2[i];
    }
}

// ---------------------------------------------------------------------------
// k_combine: ghs = gp[0] + gp[1]
// ---------------------------------------------------------------------------
__global__ void k_combine(const __half* __restrict__ gp, __half* __restrict__ o) {
    size_t i = ((size_t)blockIdx.x*256 + threadIdx.x)*8;
    uint4 a = *(const uint4*)(gp + i);
    uint4 b = *(const uint4*)(gp + (size_t)CK_T*CK_FFN + i);
    const __half2* ah = (const __half2*)&a;
    const __half2* bh = (const __half2*)&b;
    uint4 c;
    __half2* chp = (__half2*)&c;
    #pragma unroll
    for (int q = 0; q < 4; q++) chp[q] = __hadd2(ah[q], bh[q]);
    *(uint4*)(o + i) = c;
}

// ---------------------------------------------------------------------------
// fpre = data2 + v2 @ eB2^T
// ---------------------------------------------------------------------------
__device__ __forceinline__ void h8f(const __half* p, float* f) {
    uint4 q = *(const uint4*)p;
    const __half2* hp = (const __half2*)&q;
    #pragma unroll
    for (int j = 0; j < 4; j++) {
        float2 t = __half22float2(hp[j]);
        f[2*j] = t.x; f[2*j+1] = t.y;
    }
}

__global__ void k_moe_up(const float* __restrict__ d2, const float* __restrict__ v2,
                         const __half* __restrict__ eB2, const float* __restrict__ route,
                         float* __restrict__ out) {
    int t = blockIdx.x, tid = threadIdx.x;
    __shared__ float sv[128];
    __shared__ int act[8];
    if (tid < 128) sv[tid] = v2[(size_t)t*128 + tid];
    if (tid < 8)   act[tid] = (route[t*CK_E + tid] != 0.f) ? 1 : 0;
    __syncthreads();
    for (int d = tid; d < CK_D; d += 256) {
        float s = d2[(size_t)t*CK_D + d];
        #pragma unroll 1
        for (int e = 0; e < 8; e++) {
            if (!act[e]) continue;
            float bv[16];
            const __half* bp = eB2 + ((size_t)e*CK_D + d)*16;
            h8f(bp, bv); h8f(bp + 8, bv + 8);
            #pragma unroll
            for (int r = 0; r < 16; r++) s += sv[e*16+r]*bv[r];
        }
        out[(size_t)t*CK_D + d] = s;
    }
}

// ---------------------------------------------------------------------------
// Launch
// ---------------------------------------------------------------------------
extern "C" void kernel_launch(void* const* d_in, const int* in_sizes, int n_in,
                              void* d_out, int out_size) {
    (void)in_sizes; (void)n_in; (void)out_size;
    const float* data  = (const float*)d_in[0];
    const float* rc    = (const float*)d_in[2];
    const float* rs    = (const float*)d_in[3];
    const float* att_w = (const float*)d_in[4];
    const float* ffn_w = (const float*)d_in[5];
    const float* wq    = (const float*)d_in[6];
    const float* wk    = (const float*)d_in[7];
    const float* wv    = (const float*)d_in[8];
    const float* wo    = (const float*)d_in[9];
    const float* lqA   = (const float*)d_in[10];
    const float* lqB   = (const float*)d_in[11];
    const float* lkA   = (const float*)d_in[12];
    const float* lkB   = (const float*)d_in[13];
    const float* lvA   = (const float*)d_in[14];
    const float* lvB   = (const float*)d_in[15];
    const float* loA   = (const float*)d_in[16];
    const float* loB   = (const float*)d_in[17];
    const float* w1    = (const float*)d_in[18];
    const float* w2    = (const float*)d_in[19];
    const float* w3    = (const float*)d_in[20];
    const float* gatew = (const float*)d_in[21];
    const float* eA1   = (const float*)d_in[22];
    const float* eB1   = (const float*)d_in[23];
    const float* eA2   = (const float*)d_in[24];
    const float* eB2   = (const float*)d_in[25];
    const float* eA3   = (const float*)d_in[26];
    const float* eB3   = (const float*)d_in[27];
    float* out = (float*)d_out;

    float *p_hn,*p_sc,*p_d2,*p_route,*p_v2,*p_fpre,*p_Uqkv,*p_Uo,*p_Ue;
    float *p_wgtE;
    int *p_cnt,*p_listE,*p_slotE;
    cudaGetSymbolAddress((void**)&p_hn,   g_hn);
    cudaGetSymbolAddress((void**)&p_sc,   g_sc);
    cudaGetSymbolAddress((void**)&p_d2,   g_d2);
    cudaGetSymbolAddress((void**)&p_route,g_route);
    cudaGetSymbolAddress((void**)&p_v2,   g_v2);
    cudaGetSymbolAddress((void**)&p_fpre, g_fpre);
    cudaGetSymbolAddress((void**)&p_Uqkv, g_Uqkv);
    cudaGetSymbolAddress((void**)&p_Uo,   g_Uo);
    cudaGetSymbolAddress((void**)&p_Ue,   g_Ue);
    cudaGetSymbolAddress((void**)&p_cnt,  g_cnt);
    cudaGetSymbolAddress((void**)&p_listE,g_listE);
    cudaGetSymbolAddress((void**)&p_wgtE, g_wgtE);
    cudaGetSymbolAddress((void**)&p_slotE,g_slotE);

    __half *wqh,*wkh,*wvh,*woh,*w1h,*w3h,*w2h;
    __half *xh,*aoh,*hnh,*gsh,*xqp,*xkp,*xvh,*xqh,*xkh,*vth,*sch;
    __half *h1h,*h3h,*gp,*eB1h,*eB3h,*eA2t,*eB2h,*Aqkv,*Ao,*Ae;
    cudaGetSymbolAddress((void**)&wqh, g_wqh);
    cudaGetSymbolAddress((void**)&wkh, g_wkh);
    cudaGetSymbolAddress((void**)&wvh, g_wvh);
    cudaGetSymbolAddress((void**)&woh, g_woh);
    cudaGetSymbolAddress((void**)&w1h, g_w1h);
    cudaGetSymbolAddress((void**)&w3h, g_w3h);
    cudaGetSymbolAddress((void**)&w2h, g_w2h);
    cudaGetSymbolAddress((void**)&xh,  g_xh);
    cudaGetSymbolAddress((void**)&aoh, g_aoh);
    cudaGetSymbolAddress((void**)&hnh, g_hnh);
    cudaGetSymbolAddress((void**)&gsh, g_gsh);
    cudaGetSymbolAddress((void**)&xqp, g_xqp);
    cudaGetSymbolAddress((void**)&xkp, g_xkp);
    cudaGetSymbolAddress((void**)&xvh, g_xvh);
    cudaGetSymbolAddress((void**)&xqh, g_xqh);
    cudaGetSymbolAddress((void**)&xkh, g_xkh);
    cudaGetSymbolAddress((void**)&vth, g_vth);
    cudaGetSymbolAddress((void**)&sch, g_sch);
    cudaGetSymbolAddress((void**)&h1h, g_h1h);
    cudaGetSymbolAddress((void**)&h3h, g_h3h);
    cudaGetSymbolAddress((void**)&gp,  g_gp);
    cudaGetSymbolAddress((void**)&eB1h, g_eB1h);
    cudaGetSymbolAddress((void**)&eB3h, g_eB3h);
    cudaGetSymbolAddress((void**)&eA2t, g_eA2t);
    cudaGetSymbolAddress((void**)&eB2h, g_eB2h);
    cudaGetSymbolAddress((void**)&Aqkv, g_Aqkv);
    cudaGetSymbolAddress((void**)&Ao,   g_Ao);
    cudaGetSymbolAddress((void**)&Ae,   g_Ae);

    cudaFuncSetAttribute(k_hgemm4,   cudaFuncAttributeMaxDynamicSharedMemorySize, HG_SMEM);
    cudaFuncSetAttribute(k_scores_h, cudaFuncAttributeMaxDynamicSharedMemorySize, SC_SMEM);
    cudaFuncSetAttribute(k_avh,      cudaFuncAttributeMaxDynamicSharedMemorySize, HG_SMEM);
    cudaFuncSetAttribute(k_moe_em,   cudaFuncAttributeMaxDynamicSharedMemorySize, EM_SMEM);

    // --- conversions / packing ---
    k_half16<<<NWQ/4096,256>>>(wq, wqh, NWQ);
    k_half16<<<NWK/4096,256>>>(wk, wkh, NWK);
    k_half16<<<NWK/4096,256>>>(wv, wvh, NWK);
    k_half16<<<NWQ/4096,256>>>(wo, woh, NWQ);
    k_half16<<<NW1/4096,256>>>(w1, w1h, NW1);
    k_half16<<<NW1/4096,256>>>(w3, w3h, NW1);
    k_half16<<<NW1/4096,256>>>(w2, w2h, NW1);
    k_half16<<<NEB/4096,256>>>(eB1, eB1h, NEB);
    k_half16<<<NEB/4096,256>>>(eB3, eB3h, NEB);
    k_half16<<<NB2/4096,256>>>(eB2, eB2h, NB2);
    k_trA2<<<dim3(CK_FFN/256, CK_E),256>>>(eA2, eA2t);
    k_pack3<<<128,256>>>(lqA, lkA, lvA, 16,16,16, Aqkv, 128);
    k_pack3<<<128,256>>>(loA, nullptr, nullptr, 16,0,0, Ao, 128);
    k_pack3<<<512,256>>>(eA1, eA3, nullptr, 256,256,0, Ae, 512);
    k_zero8<<<1,32>>>(p_cnt);

    // --- attention path ---
    k_rmsnorm<<<CK_T,256>>>(data, att_w, nullptr, xh);
    k_hgemm4<<<dim3(1, CK_T/128),256,HG_SMEM>>>(xh, Aqkv, p_Uqkv, nullptr, CK_T, 128, CK_D, nullptr,0,nullptr,0.f, nullptr);
    k_hgemm4<<<dim3(CK_D/128, CK_T/128),256,HG_SMEM>>>(xh, wqh, nullptr, xqp, CK_T, CK_D, CK_D, p_Uqkv,    128, lqB, CK_LS, nullptr);
    k_hgemm4<<<dim3(512/128,  CK_T/128),256,HG_SMEM>>>(xh, wkh, nullptr, xkp, CK_T, 512,  CK_D, p_Uqkv+16, 128, lkB, CK_LS, nullptr);
    k_hgemm4<<<dim3(512/128,  CK_T/128),256,HG_SMEM>>>(xh, wvh, nullptr, xvh, CK_T, 512,  CK_D, p_Uqkv+32, 128, lvB, CK_LS, nullptr);
    k_rope_h<<<(CK_T*CK_H*64 + 255)/256, 256>>>(xqp, rc, rs, CK_H,  CK_T*CK_H*64,  xqh);
    k_rope_h<<<(CK_T*CK_KV*64 + 255)/256,256>>>(xkp, rc, rs, CK_KV, CK_T*CK_KV*64, xkh);
    k_vt<<<dim3(CK_S/32, CK_HD/32, CK_B*CK_KV),256>>>(xvh, vth);
    k_scores_h<<<dim3(CK_S/128, CK_S/128, CK_B*CK_H),256,SC_SMEM>>>(xqh, xkh, p_sc);
    k_softmax<<<CK_B*CK_H*CK_S,256>>>(p_sc, sch);
    k_avh<<<dim3(1, CK_S/128, CK_B*CK_H),256,HG_SMEM>>>(sch, vth, aoh);
    k_hgemm4<<<dim3(1, CK_T/128),256,HG_SMEM>>>(aoh, Ao, p_Uo, nullptr, CK_T, 128, CK_D, nullptr,0,nullptr,0.f, nullptr);
    k_hgemm4<<<dim3(CK_D/128, CK_T/128),256,HG_SMEM>>>(aoh, woh, p_d2, nullptr, CK_T, CK_D, CK_D, p_Uo, 128, loB, CK_LS, data);

    // --- MoE path ---
    k_rmsnorm<<<CK_T,256>>>(p_d2, ffn_w, p_hn, hnh);
    k_gate<<<CK_T,256>>>(p_hn, gatew, p_route, p_cnt, p_listE, p_wgtE, p_slotE);
    k_hgemm4<<<dim3(512/128, CK_T/128),256,HG_SMEM>>>(hnh, Ae, p_Ue, nullptr, CK_T, 512, CK_D, nullptr,0,nullptr,0.f, nullptr);
    k_hgemm4<<<dim3(CK_FFN/128, CK_T/128),256,HG_SMEM>>>(hnh, w1h, nullptr, h1h, CK_T, CK_FFN, CK_D, nullptr,0,nullptr,0.f, nullptr);
    k_hgemm4<<<dim3(CK_FFN/128, CK_T/128),256,HG_SMEM>>>(hnh, w3h, nullptr, h3h, CK_T, CK_FFN, CK_D, nullptr,0,nullptr,0.f, nullptr);
    k_moe_em<<<dim3(32, CK_E),256,EM_SMEM>>>(h1h, h3h, p_Ue, eB1h, eB3h, eA2t,
                                             p_cnt, p_listE, p_wgtE, p_slotE, gp, p_v2);
    k_combine<<<(int)(((size_t)CK_T*CK_FFN)/2048),256>>>(gp, gsh);
    k_moe_up<<<CK_T,256>>>(p_d2, p_v2, eB2h, p_route, p_fpre);
    k_hgemm4<<<dim3(CK_D/128, CK_T/128),256,HG_SMEM>>>(gsh, w2h, out, nullptr, CK_T, CK_D, CK_FFN, nullptr,0,nullptr,0.f, p_fpre);
}

// round 11
// speedup vs baseline: 1.7869x; 1.7869x over previous
#include <cuda_runtime.h>
#include <cuda_fp16.h>
#include <math.h>
#include <stdint.h>

#define CK_B   4
#define CK_S   512
#define CK_D   2048
#define CK_H   16
#define CK_KV  4
#define CK_HD  128
#define CK_T   2048          // B*S
#define CK_FFN 5632
#define CK_E   8
#define CK_R   16
#define CK_LS  2.0f          // 32/16

// ---------------------------------------------------------------------------
// fp32 scratch
// ---------------------------------------------------------------------------
__device__ float g_h   [CK_T*CK_D];
__device__ float g_hn  [CK_T*CK_D];
__device__ float g_xq  [CK_T*CK_D];
__device__ float g_xk  [CK_T*CK_KV*CK_HD];
__device__ float g_xv  [CK_T*CK_KV*CK_HD];
__device__ float g_sc  [(size_t)CK_B*CK_H*CK_S*CK_S];
__device__ float g_ao  [CK_T*CK_D];
__device__ float g_d2  [CK_T*CK_D];
__device__ float g_uq  [CK_T*CK_R];
__device__ float g_uk  [CK_T*CK_R];
__device__ float g_uv  [CK_T*CK_R];
__device__ float g_uo  [CK_T*CK_R];
__device__ float g_route[CK_T*CK_E];
__device__ float g_ua1 [CK_T*CK_E*CK_R];
__device__ float g_ua3 [CK_T*CK_E*CK_R];
__device__ float g_v2  [CK_T*CK_E*CK_R];
__device__ float g_fpre[CK_T*CK_D];

// ---------------------------------------------------------------------------
// fp16 scratch
// ---------------------------------------------------------------------------
#define NWQ (CK_D*CK_D)
#define NWK (512*CK_D)
#define NW1 (CK_FFN*CK_D)
#define NEB (CK_E*CK_FFN*CK_R)
#define NB2 (CK_E*CK_D*CK_R)
__device__ __align__(16) __half g_wqh[NWQ];
__device__ __align__(16) __half g_wkh[NWK];
__device__ __align__(16) __half g_wvh[NWK];
__device__ __align__(16) __half g_woh[NWQ];
__device__ __align__(16) __half g_w1h[NW1];
__device__ __align__(16) __half g_w3h[NW1];
__device__ __align__(16) __half g_w2h[NW1];
__device__ __align__(16) __half g_xh [CK_T*CK_D];
__device__ __align__(16) __half g_aoh[CK_T*CK_D];
__device__ __align__(16) __half g_hnh[CK_T*CK_D];
__device__ __align__(16) __half g_gsh[(size_t)CK_T*CK_FFN];
__device__ __align__(16) __half g_xqh[CK_T*CK_D];
__device__ __align__(16) __half g_xkh[CK_T*CK_KV*CK_HD];
__device__ __align__(16) __half g_vth[CK_T*CK_KV*CK_HD];
__device__ __align__(16) __half g_sch[(size_t)CK_B*CK_H*CK_S*CK_S];
__device__ __align__(16) __half g_h1h[(size_t)CK_T*CK_FFN];
__device__ __align__(16) __half g_h3h[(size_t)CK_T*CK_FFN];
__device__ __align__(16) __half g_eB1h[NEB], g_eB3h[NEB], g_eA2h[NEB];
__device__ __align__(16) __half g_eB2h[NB2];

// ===========================================================================
// helpers
// ===========================================================================
__device__ __forceinline__ uint32_t smem_u32(const void* p) {
    uint32_t a;
    asm("{ .reg .u64 t; cvta.to.shared.u64 t, %1; cvt.u32.u64 %0, t; }" : "=r"(a) : "l"(p));
    return a;
}
#define CP_ASYNC16(dst_u32, src_ptr) \
    asm volatile("cp.async.cg.shared.global [%0], [%1], 16;" :: "r"(dst_u32), "l"(src_ptr))
#define CP_COMMIT() asm volatile("cp.async.commit_group;" ::: "memory")
#define CP_WAIT(n)  asm volatile("cp.async.wait_group %0;" :: "n"(n) : "memory")

__device__ __forceinline__ void mma16816(float* d, const uint32_t* a,
                                         uint32_t b0, uint32_t b1) {
    asm volatile(
        "mma.sync.aligned.m16n8k16.row.col.f32.f16.f16.f32 "
        "{%0,%1,%2,%3}, {%4,%5,%6,%7}, {%8,%9}, {%0,%1,%2,%3};"
        : "+f"(d[0]), "+f"(d[1]), "+f"(d[2]), "+f"(d[3])
        : "r"(a[0]), "r"(a[1]), "r"(a[2]), "r"(a[3]), "r"(b0), "r"(b1));
}

__device__ __forceinline__ void store4h(__half* p, float4 v) {
    *(__half2*)(p + 0) = __floats2half2_rn(v.x, v.y);
    *(__half2*)(p + 2) = __floats2half2_rn(v.z, v.w);
}

// MUFU-free e^x (bit-trick 2^n scaling + deg-5 poly; rel err ~2e-6; clamped)
__device__ __forceinline__ float fexp(float x) {
    float t = fminf(fmaxf(x * 1.4426950408889634f, -30.f), 30.f);
    float n = rintf(t);
    float f = t - n;
    float p = 1.f + f*(0.6931471806f + f*(0.2402265069f + f*(0.0555041087f
            + f*(0.0096181291f + f*0.0013333558f))));
    return __int_as_float(((int)n + 127) << 23) * p;
}

// fp32 -> fp16, 8 elems/thread
__global__ void k_half(const float* __restrict__ x, __half* __restrict__ h, int n) {
    int i = (blockIdx.x*256 + threadIdx.x)*8;
    if (i >= n) return;
    store4h(h + i,     *(const float4*)(x + i));
    store4h(h + i + 4, *(const float4*)(x + i + 4));
}

// ===========================================================================
// k_hgemm4: 1-pass fp16 tensor-core GEMM, cp.async double-buffered
//   out = A @ W^T [+ lscale*U@V^T] ; out -> C fp32 (+res) or Ch fp16
// ===========================================================================
#define HG_LD   40
#define HG_TILE (128*HG_LD)
#define HG_TILEB (HG_TILE*2)
#define HG_SMEM (4*HG_TILEB)     // 40960 bytes

__global__ void __launch_bounds__(256, 2) k_hgemm4(
    const __half* __restrict__ A, const __half* __restrict__ W,
    float* __restrict__ C, __half* __restrict__ Ch, int M, int N, int K,
    const float* __restrict__ U, int ustride, const float* __restrict__ V,
    float lscale, const float* __restrict__ res)
{
    extern __shared__ __align__(16) __half sm[];
    __half* pA = sm;
    __half* pW = sm + 2*HG_TILE;
    const uint32_t sbA = smem_u32(sm);
    const uint32_t sbW = sbA + 2*HG_TILEB;

    const int tid  = threadIdx.x;
    const int wid  = tid >> 5, lane = tid & 31;
    const int g    = lane >> 2, tg = lane & 3;
    const int warpM = wid & 3;
    const int warpN = wid >> 2;
    const int bm = blockIdx.y * 128;
    const int bn = blockIdx.x * 128;

    float acc[2][8][4];
    #pragma unroll
    for (int mi = 0; mi < 2; mi++)
        #pragma unroll
        for (int ni = 0; ni < 8; ni++)
            #pragma unroll
            for (int q = 0; q < 4; q++) acc[mi][ni][q] = 0.f;

    const int NC = K / 32;
    const int total = NC + (U ? 1 : 0);

    auto load_async = [&](int c, int buf) {
        const int k0 = c * 32;
        const uint32_t bo = (uint32_t)buf * HG_TILEB;
        #pragma unroll
        for (int it = 0; it < 2; it++) {
            int id = it*256 + tid;
            int r = id >> 2, sg = (id & 3) * 8;
            uint32_t so = bo + (uint32_t)(r*HG_LD + sg)*2;
            CP_ASYNC16(sbA + so, A + (size_t)(bm + r)*K + k0 + sg);
            CP_ASYNC16(sbW + so, W + (size_t)(bn + r)*K + k0 + sg);
        }
        CP_COMMIT();
    };

    auto load_lora = [&](int buf) {
        __half* dA = pA + buf*HG_TILE;
        __half* dW = pW + buf*HG_TILE;
        #pragma unroll
        for (int l = 0; l < 4; l++) {
            int id = l*256 + tid;
            int r = id >> 3, c4 = (id & 7)*4;
            float4 va = make_float4(0.f,0.f,0.f,0.f);
            float4 vw = make_float4(0.f,0.f,0.f,0.f);
            if (c4 < 16) {
                va = *(const float4*)(U + (size_t)(bm + r)*ustride + c4);
                va.x *= lscale; va.y *= lscale; va.z *= lscale; va.w *= lscale;
                vw = *(const float4*)(V + (size_t)(bn + r)*16 + c4);
            }
            store4h(dA + r*HG_LD + c4, va);
            store4h(dW + r*HG_LD + c4, vw);
        }
    };

    load_async(0, 0);

    for (int c = 0; c < total; c++) {
        const int cur = c & 1, nb = (c + 1) & 1;
        const bool have_next = (c + 1 < total);
        const bool next_async = (c + 1 < NC);
        if (have_next) {
            if (next_async) load_async(c + 1, nb);
            else            load_lora(nb);
        }
        if (c < NC) {
            if (have_next && next_async) { CP_WAIT(1); }
            else                         { CP_WAIT(0); }
        }
        __syncthreads();

        const __half* bA = pA + cur*HG_TILE;
        const __half* bW = pW + cur*HG_TILE;

        #pragma unroll
        for (int ks = 0; ks < 2; ks++) {
            const int col0 = ks*16 + tg*2;
            uint32_t a[2][4];
            #pragma unroll
            for (int mi = 0; mi < 2; mi++) {
                int r0 = warpM*32 + mi*16 + g;
                a[mi][0] = *(const uint32_t*)(bA + r0*HG_LD + col0);
                a[mi][1] = *(const uint32_t*)(bA + (r0+8)*HG_LD + col0);
                a[mi][2] = *(const uint32_t*)(bA + r0*HG_LD + col0 + 8);
                a[mi][3] = *(const uint32_t*)(bA + (r0+8)*HG_LD + col0 + 8);
            }
            #pragma unroll
            for (int ni = 0; ni < 8; ni++) {
                int rn = warpN*64 + ni*8 + g;
                uint32_t b0 = *(const uint32_t*)(bW + rn*HG_LD + col0);
                uint32_t b1 = *(const uint32_t*)(bW + rn*HG_LD + col0 + 8);
                #pragma unroll
                for (int mi = 0; mi < 2; mi++)
                    mma16816(acc[mi][ni], a[mi], b0, b1);
            }
        }
        __syncthreads();
    }

    #pragma unroll
    for (int mi = 0; mi < 2; mi++) {
        size_t r0 = (size_t)(bm + warpM*32 + mi*16 + g);
        #pragma unroll
        for (int ni = 0; ni < 8; ni++) {
            size_t c0 = (size_t)(bn + warpN*64 + ni*8 + tg*2);
            if (Ch) {
                *(__half2*)(Ch + r0*N + c0) =
                    __floats2half2_rn(acc[mi][ni][0], acc[mi][ni][1]);
                *(__half2*)(Ch + (r0+8)*N + c0) =
                    __floats2half2_rn(acc[mi][ni][2], acc[mi][ni][3]);
            } else {
                float2 o0 = make_float2(acc[mi][ni][0], acc[mi][ni][1]);
                float2 o1 = make_float2(acc[mi][ni][2], acc[mi][ni][3]);
                if (res) {
                    float2 r0v = *(const float2*)(res + r0*N + c0);
                    float2 r1v = *(const float2*)(res + (r0+8)*N + c0);
                    o0.x += r0v.x; o0.y += r0v.y;
                    o1.x += r1v.x; o1.y += r1v.y;
                }
                *(float2*)(C + r0*N + c0)     = o0;
                *(float2*)(C + (r0+8)*N + c0) = o1;
            }
        }
    }
}

// ===========================================================================
// k_scores_h: scores = Q@K^T / sqrt(HD), fp16 tensor cores, causal tile skip
// ===========================================================================
#define SC_LD 136
#define SC_SMEM (2*128*SC_LD*2)

__global__ void __launch_bounds__(256) k_scores_h(const __half* __restrict__ q,
                                                  const __half* __restrict__ k,
                                                  float* __restrict__ sc) {
    const int t0 = blockIdx.x*128, s0 = blockIdx.y*128;
    if (t0 > s0) return;
    const int bh = blockIdx.z, b = bh >> 4, h = bh & 15, kv = h >> 2;
    extern __shared__ __align__(16) __half sm[];
    __half* Qs = sm;
    __half* Ks = sm + 128*SC_LD;

    const int tid = threadIdx.x;
    const int wid = tid >> 5, lane = tid & 31;
    const int g = lane >> 2, tg = lane & 3;
    const int warpM = wid & 3, warpN = wid >> 2;

    #pragma unroll
    for (int it = 0; it < 8; it++) {
        int id = it*256 + tid;
        int r = id >> 4, c8 = (id & 15)*8;
        *(uint4*)(Qs + r*SC_LD + c8) =
            *(const uint4*)(q + ((size_t)(b*CK_S + s0 + r)*CK_D + h*CK_HD + c8));
        *(uint4*)(Ks + r*SC_LD + c8) =
            *(const uint4*)(k + ((size_t)(b*CK_S + t0 + r)*(CK_KV*CK_HD) + kv*CK_HD + c8));
    }
    __syncthreads();

    float acc[2][8][4];
    #pragma unroll
    for (int mi = 0; mi < 2; mi++)
        #pragma unroll
        for (int ni = 0; ni < 8; ni++)
            #pragma unroll
            for (int qq = 0; qq < 4; qq++) acc[mi][ni][qq] = 0.f;

    #pragma unroll
    for (int ks = 0; ks < 8; ks++) {
        const int col0 = ks*16 + tg*2;
        uint32_t a[2][4];
        #pragma unroll
        for (int mi = 0; mi < 2; mi++) {
            int r0 = warpM*32 + mi*16 + g;
            a[mi][0] = *(const uint32_t*)(Qs + r0*SC_LD + col0);
            a[mi][1] = *(const uint32_t*)(Qs + (r0+8)*SC_LD + col0);
            a[mi][2] = *(const uint32_t*)(Qs + r0*SC_LD + col0 + 8);
            a[mi][3] = *(const uint32_t*)(Qs + (r0+8)*SC_LD + col0 + 8);
        }
        #pragma unroll
        for (int ni = 0; ni < 8; ni++) {
            int rn = warpN*64 + ni*8 + g;
            uint32_t b0 = *(const uint32_t*)(Ks + rn*SC_LD + col0);
            uint32_t b1 = *(const uint32_t*)(Ks + rn*SC_LD + col0 + 8);
            #pragma unroll
            for (int mi = 0; mi < 2; mi++)
                mma16816(acc[mi][ni], a[mi], b0, b1);
        }
    }

    const float scl = 0.08838834764831845f;
    float* out = sc + (size_t)bh*CK_S*CK_S;
    #pragma unroll
    for (int mi = 0; mi < 2; mi++) {
        size_t r0 = (size_t)(s0 + warpM*32 + mi*16 + g);
        #pragma unroll
        for (int ni = 0; ni < 8; ni++) {
            size_t c0 = (size_t)(t0 + warpN*64 + ni*8 + tg*2);
            *(float2*)(out + r0*CK_S + c0) =
                make_float2(acc[mi][ni][0]*scl, acc[mi][ni][1]*scl);
            *(float2*)(out + (r0+8)*CK_S + c0) =
                make_float2(acc[mi][ni][2]*scl, acc[mi][ni][3]*scl);
        }
    }
}

// ===========================================================================
// k_avh: out = attn(fp16) @ V^T(fp16), causal K-bound, fp32+fp16 outputs
// ===========================================================================
__global__ void __launch_bounds__(256, 2) k_avh(const __half* __restrict__ attn,
                                                const __half* __restrict__ vt,
                                                float* __restrict__ out,
                                                __half* __restrict__ outh) {
    extern __shared__ __align__(16) __half sm[];
    __half* pA = sm;
    __half* pW = sm + 2*HG_TILE;
    const uint32_t sbA = smem_u32(sm);
    const uint32_t sbW = sbA + 2*HG_TILEB;

    const int s0 = blockIdx.y * 128;
    const int bh = blockIdx.z, b = bh >> 4, h = bh & 15, kv = h >> 2;
    const __half* Ab = attn + (size_t)bh*CK_S*CK_S;
    const __half* Wb = vt + ((size_t)(b*CK_KV + kv)*CK_HD)*CK_S;

    const int tid = threadIdx.x;
    const int wid = tid >> 5, lane = tid & 31;
    const int g = lane >> 2, tg = lane & 3;
    const int warpM = wid & 3, warpN = wid >> 2;

    float acc[2][8][4];
    #pragma unroll
    for (int mi = 0; mi < 2; mi++)
        #pragma unroll
        for (int ni = 0; ni < 8; ni++)
            #pragma unroll
            for (int q = 0; q < 4; q++) acc[mi][ni][q] = 0.f;

    const int NC = (s0 + 128) / 32;

    auto load_async = [&](int c, int buf) {
        const int k0 = c * 32;
        const uint32_t bo = (uint32_t)buf * HG_TILEB;
        #pragma unroll
        for (int it = 0; it < 2; it++) {
            int id = it*256 + tid;
            int r = id >> 2, sg = (id & 3) * 8;
            uint32_t so = bo + (uint32_t)(r*HG_LD + sg)*2;
            CP_ASYNC16(sbA + so, Ab + (size_t)(s0 + r)*CK_S + k0 + sg);
            CP_ASYNC16(sbW + so, Wb + (size_t)r*CK_S + k0 + sg);
        }
        CP_COMMIT();
    };

    load_async(0, 0);
    for (int c = 0; c < NC; c++) {
        const int cur = c & 1;
        if (c + 1 < NC) { load_async(c + 1, (c+1)&1); CP_WAIT(1); }
        else            { CP_WAIT(0); }
        __syncthreads();

        const __half* bA = pA + cur*HG_TILE;
        const __half* bW = pW + cur*HG_TILE;
        #pragma unroll
        for (int ks = 0; ks < 2; ks++) {
            const int col0 = ks*16 + tg*2;
            uint32_t a[2][4];
            #pragma unroll
            for (int mi = 0; mi < 2; mi++) {
                int r0 = warpM*32 + mi*16 + g;
                a[mi][0] = *(const uint32_t*)(bA + r0*HG_LD + col0);
                a[mi][1] = *(const uint32_t*)(bA + (r0+8)*HG_LD + col0);
                a[mi][2] = *(const uint32_t*)(bA + r0*HG_LD + col0 + 8);
                a[mi][3] = *(const uint32_t*)(bA + (r0+8)*HG_LD + col0 + 8);
            }
            #pragma unroll
            for (int ni = 0; ni < 8; ni++) {
                int rn = warpN*64 + ni*8 + g;
                uint32_t b0 = *(const uint32_t*)(bW + rn*HG_LD + col0);
                uint32_t b1 = *(const uint32_t*)(bW + rn*HG_LD + col0 + 8);
                #pragma unroll
                for (int mi = 0; mi < 2; mi++)
                    mma16816(acc[mi][ni], a[mi], b0, b1);
            }
        }
        __syncthreads();
    }

    #pragma unroll
    for (int mi = 0; mi < 2; mi++) {
        int s = s0 + warpM*32 + mi*16 + g;
        #pragma unroll
        for (int ni = 0; ni < 8; ni++) {
            int c0 = warpN*64 + ni*8 + tg*2;
            size_t off0 = ((size_t)(b*CK_S + s)*CK_H + h)*CK_HD + c0;
            size_t off1 = ((size_t)(b*CK_S + s + 8)*CK_H + h)*CK_HD + c0;
            *(float2*)(out + off0) = make_float2(acc[mi][ni][0], acc[mi][ni][1]);
            *(float2*)(out + off1) = make_float2(acc[mi][ni][2], acc[mi][ni][3]);
            *(__half2*)(outh + off0) = __floats2half2_rn(acc[mi][ni][0], acc[mi][ni][1]);
            *(__half2*)(outh + off1) = __floats2half2_rn(acc[mi][ni][2], acc[mi][ni][3]);
        }
    }
}

// ---------------------------------------------------------------------------
// k_vt: V fp32 [t][kv*HD] -> V^T fp16 [b][kv][hd][s]
// ---------------------------------------------------------------------------
__global__ void k_vt(const float* __restrict__ xv, __half* __restrict__ vt) {
    int bkv = blockIdx.z, b = bkv >> 2, kv = bkv & 3;
    int s0 = blockIdx.x*32, h0 = blockIdx.y*32;
    __shared__ __half t[32][33];
    int x = threadIdx.x & 31, y = threadIdx.x >> 5;
    for (int i = y; i < 32; i += 8)
        t[i][x] = __float2half_rn(
            xv[(size_t)(b*CK_S + s0 + i)*(CK_KV*CK_HD) + kv*CK_HD + h0 + x]);
    __syncthreads();
    for (int i = y; i < 32; i += 8)
        vt[((size_t)bkv*CK_HD + h0 + i)*CK_S + s0 + x] = t[x][i];
}

// ---------------------------------------------------------------------------
// RMSNorm (fp32 out + fp16 out)
// ---------------------------------------------------------------------------
__global__ void k_rmsnorm(const float* __restrict__ x, const float* __restrict__ w,
                          float* __restrict__ o, __half* __restrict__ oh) {
    int t = blockIdx.x;
    const float* xr = x + (size_t)t*CK_D;
    float ss = 0.f;
    for (int i = threadIdx.x; i < CK_D; i += 256) { float v = xr[i]; ss += v*v; }
    __shared__ float red[256];
    red[threadIdx.x] = ss; __syncthreads();
    for (int s = 128; s > 0; s >>= 1) {
        if (threadIdx.x < s) red[threadIdx.x] += red[threadIdx.x+s];
        __syncthreads();
    }
    float sc = rsqrtf(red[0]/(float)CK_D + 1e-5f);
    float* orow = o + (size_t)t*CK_D;
    __half* hrow = oh + (size_t)t*CK_D;
    for (int i = threadIdx.x; i < CK_D; i += 256) {
        float r = xr[i]*sc*w[i];
        orow[i] = r;
        hrow[i] = __float2half_rn(r);
    }
}

// ---------------------------------------------------------------------------
// Fused q/k/v LoRA downs (single read of X)
// ---------------------------------------------------------------------------
__global__ void k_lora_down3(const float* __restrict__ X,
                             const float* __restrict__ A1, const float* __restrict__ A2,
                             const float* __restrict__ A3,
                             float* __restrict__ U1, float* __restrict__ U2,
                             float* __restrict__ U3) {
    int t = blockIdx.x;
    __shared__ float sx[CK_D];
    for (int i = threadIdx.x; i < CK_D; i += 256) sx[i] = X[(size_t)t*CK_D + i];
    __syncthreads();
    int w = threadIdx.x >> 5, lane = threadIdx.x & 31;
    for (int rr = w; rr < 48; rr += 8) {
        int m = rr >> 4, r = rr & 15;
        const float* ar = (m == 0 ? A1 : m == 1 ? A2 : A3) + (size_t)r*CK_D;
        float p = 0.f;
        for (int d = lane; d < CK_D; d += 32) p += sx[d]*ar[d];
        for (int o = 16; o; o >>= 1) p += __shfl_down_sync(0xffffffffu, p, o);
        if (lane == 0) (m == 0 ? U1 : m == 1 ? U2 : U3)[t*CK_R + r] = p;
    }
}

__global__ void k_lora_down(const float* __restrict__ X, const float* __restrict__ A,
                            float* __restrict__ U) {
    int t = blockIdx.x;
    __shared__ float sx[CK_D];
    for (int i = threadIdx.x; i < CK_D; i += 256) sx[i] = X[(size_t)t*CK_D + i];
    __syncthreads();
    int w = threadIdx.x >> 5, lane = threadIdx.x & 31;
    for (int r = w; r < CK_R; r += 8) {
        const float* ar = A + (size_t)r*CK_D;
        float p = 0.f;
        for (int d = lane; d < CK_D; d += 32) p += sx[d]*ar[d];
        for (int o = 16; o; o >>= 1) p += __shfl_down_sync(0xffffffffu, p, o);
        if (lane == 0) U[t*CK_R + r] = p;
    }
}

// ---------------------------------------------------------------------------
// RoPE: read fp32, write fp16
// ---------------------------------------------------------------------------
__global__ void k_rope(const float* __restrict__ x, const float* __restrict__ cs,
                       const float* __restrict__ sn, int nh, int total,
                       __half* __restrict__ oh) {
    int i = blockIdx.x*256 + threadIdx.x;
    if (i >= total) return;
    int d2 = i & 63;
    int h  = (i >> 6) % nh;
    int t  = i / (64*nh);
    int s  = t & (CK_S - 1);
    float c  = cs[s*64 + d2];
    float si = sn[s*64 + d2];
    size_t off = ((size_t)t*nh + h)*CK_HD + 2*d2;
    float x1 = x[off], x2 = x[off + 1];
    *(__half2*)(oh + off) = __floats2half2_rn(x1*c - x2*si, x1*si + x2*c);
}

// ---------------------------------------------------------------------------
// Causal softmax (MUFU-free exp): fp32 scores in, fp16 attn out
// ---------------------------------------------------------------------------
__global__ void k_softmax(const float* __restrict__ sc, __half* __restrict__ sch) {
    int row = blockIdx.x;
    int s = row & (CK_S - 1);
    const float* p = sc + (size_t)row*CK_S;
    __half* ph = sch + (size_t)row*CK_S;
    int L = s + 1;
    int tid = threadIdx.x;
    float v0 = (tid       < L) ? p[tid]       : -1e30f;
    float v1 = (tid + 256 < L) ? p[tid + 256] : -1e30f;
    __shared__ float red[256];
    red[tid] = fmaxf(v0, v1); __syncthreads();
    for (int st = 128; st; st >>= 1) {
        if (tid < st) red[tid] = fmaxf(red[tid], red[tid+st]);
        __syncthreads();
    }
    float m = red[0]; __syncthreads();
    float e0 = (tid       < L) ? fexp(v0 - m) : 0.f;
    float e1 = (tid + 256 < L) ? fexp(v1 - m) : 0.f;
    red[tid] = e0 + e1; __syncthreads();
    for (int st = 128; st; st >>= 1) {
        if (tid < st) red[tid] += red[tid+st];
        __syncthreads();
    }
    float inv = 1.f / red[0];
    ph[tid]       = __float2half_rn(e0 * inv);
    ph[tid + 256] = __float2half_rn(e1 * inv);
}

// ---------------------------------------------------------------------------
// Gate
// ---------------------------------------------------------------------------
__global__ void k_gate(const float* __restrict__ hn, const float* __restrict__ gw,
                       float* __restrict__ route) {
    int t = blockIdx.x;
    __shared__ float sl[8];
    int w = threadIdx.x >> 5, lane = threadIdx.x & 31;
    const float* xr = hn + (size_t)t*CK_D;
    const float* gr = gw + (size_t)w*CK_D;
    float p = 0.f;
    for (int d = lane; d < CK_D; d += 32) p += xr[d]*gr[d];
    for (int o = 16; o; o >>= 1) p += __shfl_down_sync(0xffffffffu, p, o);
    if (lane == 0) sl[w] = p;
    __syncthreads();
    if (threadIdx.x == 0) {
        int i0 = 0;
        for (int e = 1; e < 8; e++) if (sl[e] > sl[i0]) i0 = e;
        int i1 = -1;
        for (int e = 0; e < 8; e++) { if (e == i0) continue; if (i1 < 0 || sl[e] > sl[i1]) i1 = e; }
        float m = sl[i0];
        float v0 = expf(sl[i0]-m), v1 = expf(sl[i1]-m);
        float inv = 1.f/(v0+v1);
        float* rr = route + (size_t)t*CK_E;
        #pragma unroll
        for (int e = 0; e < 8; e++) rr[e] = 0.f;
        rr[i0] = v0*inv; rr[i1] = v1*inv;
    }
}

// ---------------------------------------------------------------------------
// Expert LoRA downs
// ---------------------------------------------------------------------------
__global__ void k_expert_down(const float* __restrict__ X, const float* __restrict__ A1,
                              const float* __restrict__ A3, const float* __restrict__ route,
                              float* __restrict__ U1, float* __restrict__ U3) {
    int t = blockIdx.x, e = blockIdx.y;
    if (route[t*CK_E + e] == 0.f) return;
    __shared__ float sx[CK_D];
    for (int i = threadIdx.x; i < CK_D; i += 256) sx[i] = X[(size_t)t*CK_D + i];
    __syncthreads();
    int w = threadIdx.x >> 5, lane = threadIdx.x & 31;
    const float* a1 = A1 + (size_t)e*CK_R*CK_D;
    const float* a3 = A3 + (size_t)e*CK_R*CK_D;
    for (int r = w; r < CK_R; r += 8) {
        float p1 = 0.f, p3 = 0.f;
        for (int d = lane; d < CK_D; d += 32) {
            float xv = sx[d];
            p1 += xv*a1[(size_t)r*CK_D + d];
            p3 += xv*a3[(size_t)r*CK_D + d];
        }
        for (int o = 16; o; o >>= 1) {
            p1 += __shfl_down_sync(0xffffffffu, p1, o);
            p3 += __shfl_down_sync(0xffffffffu, p3, o);
        }
        if (lane == 0) {
            U1[((size_t)t*CK_E + e)*CK_R + r] = p1;
            U3[((size_t)t*CK_E + e)*CK_R + r] = p3;
        }
    }
}

// ---------------------------------------------------------------------------
// Fused per-token MoE combine (fp16 h1/h3; fexp + paired rcp silu)
// ---------------------------------------------------------------------------
__device__ __forceinline__ void h8f(const __half* p, float* f) {
    uint4 q = *(const uint4*)p;
    const __half2* hp = (const __half2*)&q;
    #pragma unroll
    for (int j = 0; j < 4; j++) {
        float2 t = __half22float2(hp[j]);
        f[2*j] = t.x; f[2*j+1] = t.y;
    }
}

__global__ void __launch_bounds__(256) k_moe_expert(
    const __half* __restrict__ h1, const __half* __restrict__ h3,
    const float* __restrict__ ua1, const float* __restrict__ ua3,
    const __half* __restrict__ eB1, const __half* __restrict__ eB3,
    const __half* __restrict__ eA2, const float* __restrict__ route,
    __half* __restrict__ ghs, float* __restrict__ v2)
{
    const int t = blockIdx.x;
    const int tid = threadIdx.x;
    const int wid = tid >> 5, lane = tid & 31;
    const int NI = CK_FFN/256;   // 22
    float ghacc[CK_FFN/256];
    #pragma unroll
    for (int i = 0; i < NI; i++) ghacc[i] = 0.f;
    __shared__ float su1[16], su3[16];
    __shared__ float part[8][16];
    const __half* h1r = h1 + (size_t)t*CK_FFN;
    const __half* h3r = h3 + (size_t)t*CK_FFN;

    #pragma unroll 1
    for (int e = 0; e < CK_E; e++) {
        float wgt = route[t*CK_E + e];
        if (wgt == 0.f) {
            if (tid < 16) v2[(size_t)t*(CK_E*CK_R) + e*16 + tid] = 0.f;
            continue;
        }
        if (tid < 16) {
            su1[tid] = ua1[((size_t)t*CK_E + e)*16 + tid];
            su3[tid] = ua3[((size_t)t*CK_E + e)*16 + tid];
        }
        __syncthreads();
        float u1[16], u3[16];
        #pragma unroll
        for (int r = 0; r < 16; r++) { u1[r] = su1[r]; u3[r] = su3[r]; }
        float accr[16];
        #pragma unroll
        for (int r = 0; r < 16; r++) accr[r] = 0.f;
        const __half* B1 = eB1 + (size_t)e*CK_FFN*16;
        const __half* B3 = eB3 + (size_t)e*CK_FFN*16;
        const __half* A2 = eA2 + (size_t)e*16*CK_FFN;
        #pragma unroll 1
        for (int ii = 0; ii < NI; ii += 2) {
            float prod[2], esig[2];
            const int fA = ii*256 + tid, fB = fA + 256;
            #pragma unroll
            for (int hi = 0; hi < 2; hi++) {
                int f = hi ? fB : fA;
                float b1v[16], b3v[16];
                h8f(B1 + (size_t)f*16,     b1v);
                h8f(B1 + (size_t)f*16 + 8, b1v + 8);
                h8f(B3 + (size_t)f*16,     b3v);
                h8f(B3 + (size_t)f*16 + 8, b3v + 8);
                float b1 = 0.f, b3 = 0.f;
                #pragma unroll
                for (int r = 0; r < 16; r++) { b1 += u1[r]*b1v[r]; b3 += u3[r]*b3v[r]; }
                float g1 = __half2float(h1r[f]) + CK_LS*b1;
                float g3 = __half2float(h3r[f]) + CK_LS*b3;
                prod[hi] = g1*g3;
                esig[hi] = fexp(-g1);
            }
            float da = 1.f + esig[0], db = 1.f + esig[1];
            float rr;
            asm("rcp.approx.f32 %0, %1;" : "=f"(rr) : "f"(da*db));
            float gh[2];
            gh[0] = prod[0]*(rr*db);
            gh[1] = prod[1]*(rr*da);
            ghacc[ii]   += wgt*gh[0];
            ghacc[ii+1] += wgt*gh[1];
            #pragma unroll
            for (int hi = 0; hi < 2; hi++) {
                int f = hi ? fB : fA;
                #pragma unroll
                for (int r = 0; r < 16; r++)
                    accr[r] += gh[hi] * __half2float(A2[(size_t)r*CK_FFN + f]);
            }
        }
        #pragma unroll
        for (int r = 0; r < 16; r++) {
            float v = accr[r];
            #pragma unroll
            for (int o = 16; o; o >>= 1) v += __shfl_down_sync(0xffffffffu, v, o);
            if (lane == 0) part[wid][r] = v;
        }
        __syncthreads();
        if (tid < 16) {
            float s2 = 0.f;
            #pragma unroll
            for (int ww = 0; ww < 8; ww++) s2 += part[ww][tid];
            v2[(size_t)t*(CK_E*CK_R) + e*16 + tid] = wgt*CK_LS*s2;
        }
        __syncthreads();
    }
    __half* go = ghs + (size_t)t*CK_FFN;
    #pragma unroll
    for (int ii = 0; ii < NI; ii++) go[ii*256 + tid] = __float2half_rn(ghacc[ii]);
}

// ---------------------------------------------------------------------------
// fpre = data2 + v2 @ eB2^T
// ---------------------------------------------------------------------------
__global__ void k_moe_up(const float* __restrict__ d2, const float* __restrict__ v2,
                         const __half* __restrict__ eB2, const float* __restrict__ route,
                         float* __restrict__ out) {
    int t = blockIdx.x, tid = threadIdx.x;
    __shared__ float sv[128];
    __shared__ int act[8];
    if (tid < 128) sv[tid] = v2[(size_t)t*128 + tid];
    if (tid < 8)   act[tid] = (route[t*CK_E + tid] != 0.f) ? 1 : 0;
    __syncthreads();
    for (int d = tid; d < CK_D; d += 256) {
        float s = d2[(size_t)t*CK_D + d];
        #pragma unroll 1
        for (int e = 0; e < 8; e++) {
            if (!act[e]) continue;
            float bv[16];
            const __half* bp = eB2 + ((size_t)e*CK_D + d)*16;
            h8f(bp, bv); h8f(bp + 8, bv + 8);
            #pragma unroll
            for (int r = 0; r < 16; r++) s += sv[e*16+r]*bv[r];
        }
        out[(size_t)t*CK_D + d] = s;
    }
}

// ---------------------------------------------------------------------------
// Launch
// ---------------------------------------------------------------------------
extern "C" void kernel_launch(void* const* d_in, const int* in_sizes, int n_in,
                              void* d_out, int out_size) {
    (void)in_sizes; (void)n_in; (void)out_size;
    const float* data  = (const float*)d_in[0];
    const float* rc    = (const float*)d_in[2];
    const float* rs    = (const float*)d_in[3];
    const float* att_w = (const float*)d_in[4];
    const float* ffn_w = (const float*)d_in[5];
    const float* wq    = (const float*)d_in[6];
    const float* wk    = (const float*)d_in[7];
    const float* wv    = (const float*)d_in[8];
    const float* wo    = (const float*)d_in[9];
    const float* lqA   = (const float*)d_in[10];
    const float* lqB   = (const float*)d_in[11];
    const float* lkA   = (const float*)d_in[12];
    const float* lkB   = (const float*)d_in[13];
    const float* lvA   = (const float*)d_in[14];
    const float* lvB   = (const float*)d_in[15];
    const float* loA   = (const float*)d_in[16];
    const float* loB   = (const float*)d_in[17];
    const float* w1    = (const float*)d_in[18];
    const float* w2    = (const float*)d_in[19];
    const float* w3    = (const float*)d_in[20];
    const float* gatew = (const float*)d_in[21];
    const float* eA1   = (const float*)d_in[22];
    const float* eB1   = (const float*)d_in[23];
    const float* eA2   = (const float*)d_in[24];
    const float* eB2   = (const float*)d_in[25];
    const float* eA3   = (const float*)d_in[26];
    const float* eB3   = (const float*)d_in[27];
    float* out = (float*)d_out;

    float *p_h,*p_hn,*p_xq,*p_xk,*p_xv,*p_sc,*p_ao,*p_d2,*p_uq,*p_uk,*p_uv,*p_uo;
    float *p_route,*p_ua1,*p_ua3,*p_v2,*p_fpre;
    cudaGetSymbolAddress((void**)&p_h,    g_h);
    cudaGetSymbolAddress((void**)&p_hn,   g_hn);
    cudaGetSymbolAddress((void**)&p_xq,   g_xq);
    cudaGetSymbolAddress((void**)&p_xk,   g_xk);
    cudaGetSymbolAddress((void**)&p_xv,   g_xv);
    cudaGetSymbolAddress((void**)&p_sc,   g_sc);
    cudaGetSymbolAddress((void**)&p_ao,   g_ao);
    cudaGetSymbolAddress((void**)&p_d2,   g_d2);
    cudaGetSymbolAddress((void**)&p_uq,   g_uq);
    cudaGetSymbolAddress((void**)&p_uk,   g_uk);
    cudaGetSymbolAddress((void**)&p_uv,   g_uv);
    cudaGetSymbolAddress((void**)&p_uo,   g_uo);
    cudaGetSymbolAddress((void**)&p_route,g_route);
    cudaGetSymbolAddress((void**)&p_ua1,  g_ua1);
    cudaGetSymbolAddress((void**)&p_ua3,  g_ua3);
    cudaGetSymbolAddress((void**)&p_v2,   g_v2);
    cudaGetSymbolAddress((void**)&p_fpre, g_fpre);

    __half *wqh,*wkh,*wvh,*woh,*w1h,*w3h,*w2h;
    __half *xh,*aoh,*hnh,*gsh,*xqh,*xkh,*vth,*sch,*h1h,*h3h;
    __half *eB1h,*eB3h,*eA2h,*eB2h;
    cudaGetSymbolAddress((void**)&wqh, g_wqh);
    cudaGetSymbolAddress((void**)&wkh, g_wkh);
    cudaGetSymbolAddress((void**)&wvh, g_wvh);
    cudaGetSymbolAddress((void**)&woh, g_woh);
    cudaGetSymbolAddress((void**)&w1h, g_w1h);
    cudaGetSymbolAddress((void**)&w3h, g_w3h);
    cudaGetSymbolAddress((void**)&w2h, g_w2h);
    cudaGetSymbolAddress((void**)&xh,  g_xh);
    cudaGetSymbolAddress((void**)&aoh, g_aoh);
    cudaGetSymbolAddress((void**)&hnh, g_hnh);
    cudaGetSymbolAddress((void**)&gsh, g_gsh);
    cudaGetSymbolAddress((void**)&xqh, g_xqh);
    cudaGetSymbolAddress((void**)&xkh, g_xkh);
    cudaGetSymbolAddress((void**)&vth, g_vth);
    cudaGetSymbolAddress((void**)&sch, g_sch);
    cudaGetSymbolAddress((void**)&h1h, g_h1h);
    cudaGetSymbolAddress((void**)&h3h, g_h3h);
    cudaGetSymbolAddress((void**)&eB1h, g_eB1h);
    cudaGetSymbolAddress((void**)&eB3h, g_eB3h);
    cudaGetSymbolAddress((void**)&eA2h, g_eA2h);
    cudaGetSymbolAddress((void**)&eB2h, g_eB2h);

    cudaFuncSetAttribute(k_hgemm4,   cudaFuncAttributeMaxDynamicSharedMemorySize, HG_SMEM);
    cudaFuncSetAttribute(k_scores_h, cudaFuncAttributeMaxDynamicSharedMemorySize, SC_SMEM);
    cudaFuncSetAttribute(k_avh,      cudaFuncAttributeMaxDynamicSharedMemorySize, HG_SMEM);

    // --- weight/expert-mat conversions ---
    k_half<<<NWQ/2048,256>>>(wq, wqh, NWQ);
    k_half<<<NWK/2048,256>>>(wk, wkh, NWK);
    k_half<<<NWK/2048,256>>>(wv, wvh, NWK);
    k_half<<<NWQ/2048,256>>>(wo, woh, NWQ);
    k_half<<<NW1/2048,256>>>(w1, w1h, NW1);
    k_half<<<NW1/2048,256>>>(w3, w3h, NW1);
    k_half<<<NW1/2048,256>>>(w2, w2h, NW1);
    k_half<<<NEB/2048,256>>>(eB1, eB1h, NEB);
    k_half<<<NEB/2048,256>>>(eB3, eB3h, NEB);
    k_half<<<NEB/2048,256>>>(eA2, eA2h, NEB);
    k_half<<<NB2/2048,256>>>(eB2, eB2h, NB2);

    // --- attention path ---
    k_rmsnorm<<<CK_T,256>>>(data, att_w, p_h, xh);
    k_lora_down3<<<CK_T,256>>>(p_h, lqA, lkA, lvA, p_uq, p_uk, p_uv);
    k_hgemm4<<<dim3(CK_D/128, CK_T/128),256,HG_SMEM>>>(xh, wqh, p_xq, nullptr, CK_T, CK_D, CK_D, p_uq, 16, lqB, CK_LS, nullptr);
    k_hgemm4<<<dim3(512/128,  CK_T/128),256,HG_SMEM>>>(xh, wkh, p_xk, nullptr, CK_T, 512,  CK_D, p_uk, 16, lkB, CK_LS, nullptr);
    k_hgemm4<<<dim3(512/128,  CK_T/128),256,HG_SMEM>>>(xh, wvh, p_xv, nullptr, CK_T, 512,  CK_D, p_uv, 16, lvB, CK_LS, nullptr);
    k_rope<<<(CK_T*CK_H*64 + 255)/256, 256>>>(p_xq, rc, rs, CK_H,  CK_T*CK_H*64,  xqh);
    k_rope<<<(CK_T*CK_KV*64 + 255)/256,256>>>(p_xk, rc, rs, CK_KV, CK_T*CK_KV*64, xkh);
    k_vt<<<dim3(CK_S/32, CK_HD/32, CK_B*CK_KV),256>>>(p_xv, vth);
    k_scores_h<<<dim3(CK_S/128, CK_S/128, CK_B*CK_H),256,SC_SMEM>>>(xqh, xkh, p_sc);
    k_softmax<<<CK_B*CK_H*CK_S,256>>>(p_sc, sch);
    k_avh<<<dim3(1, CK_S/128, CK_B*CK_H),256,HG_SMEM>>>(sch, vth, p_ao, aoh);
    k_lora_down<<<CK_T,256>>>(p_ao, loA, p_uo);
    k_hgemm4<<<dim3(CK_D/128, CK_T/128),256,HG_SMEM>>>(aoh, woh, p_d2, nullptr, CK_T, CK_D, CK_D, p_uo, 16, loB, CK_LS, data);

    // --- MoE path ---
    k_rmsnorm<<<CK_T,256>>>(p_d2, ffn_w, p_hn, hnh);
    k_gate<<<CK_T,256>>>(p_hn, gatew, p_route);
    k_expert_down<<<dim3(CK_T, CK_E),256>>>(p_hn, eA1, eA3, p_route, p_ua1, p_ua3);
    k_hgemm4<<<dim3(CK_FFN/128, CK_T/128),256,HG_SMEM>>>(hnh, w1h, nullptr, h1h, CK_T, CK_FFN, CK_D, nullptr, 0, nullptr, 0.f, nullptr);
    k_hgemm4<<<dim3(CK_FFN/128, CK_T/128),256,HG_SMEM>>>(hnh, w3h, nullptr, h3h, CK_T, CK_FFN, CK_D, nullptr, 0, nullptr, 0.f, nullptr);
    k_moe_expert<<<CK_T,256>>>(h1h, h3h, p_ua1, p_ua3, eB1h, eB3h, eA2h, p_route, gsh, p_v2);
    k_moe_up<<<CK_T,256>>>(p_d2, p_v2, eB2h, p_route, p_fpre);
    k_hgemm4<<<dim3(CK_D/128, CK_T/128),256,HG_SMEM>>>(gsh, w2h, out, nullptr, CK_T, CK_D, CK_FFN, nullptr, 0, nullptr, 0.f, p_fpre);
}

// round 12
// speedup vs baseline: 1.8214x; 1.0193x over previous
#include <cuda_runtime.h>
#include <cuda_fp16.h>
#include <math.h>
#include <stdint.h>

#define CK_B   4
#define CK_S   512
#define CK_D   2048
#define CK_H   16
#define CK_KV  4
#define CK_HD  128
#define CK_T   2048          // B*S
#define CK_FFN 5632
#define CK_E   8
#define CK_R   16
#define CK_LS  2.0f          // 32/16

// ---------------------------------------------------------------------------
// fp32 scratch
// ---------------------------------------------------------------------------
__device__ float g_h   [CK_T*CK_D];
__device__ float g_hn  [CK_T*CK_D];
__device__ float g_sc  [(size_t)CK_B*CK_H*CK_S*CK_S];
__device__ float g_d2  [CK_T*CK_D];
__device__ float g_uq  [CK_T*CK_R];
__device__ float g_uk  [CK_T*CK_R];
__device__ float g_uv  [CK_T*CK_R];
__device__ float g_uo  [CK_T*CK_R];
__device__ float g_route[CK_T*CK_E];
__device__ float g_ua1 [CK_T*CK_E*CK_R];
__device__ float g_ua3 [CK_T*CK_E*CK_R];
__device__ float g_v2  [CK_T*CK_E*CK_R];
__device__ float g_fpre[CK_T*CK_D];

// ---------------------------------------------------------------------------
// fp16 scratch
// ---------------------------------------------------------------------------
#define NWQ (CK_D*CK_D)
#define NWK (512*CK_D)
#define NW1 (CK_FFN*CK_D)
#define NEB (CK_E*CK_FFN*CK_R)
#define NB2 (CK_E*CK_D*CK_R)
__device__ __align__(16) __half g_wqh[NWQ];
__device__ __align__(16) __half g_wkh[NWK];
__device__ __align__(16) __half g_wvh[NWK];
__device__ __align__(16) __half g_woh[NWQ];
__device__ __align__(16) __half g_w1h[NW1];
__device__ __align__(16) __half g_w3h[NW1];
__device__ __align__(16) __half g_w2h[NW1];
__device__ __align__(16) __half g_xh [CK_T*CK_D];               // h fp16
__device__ __align__(16) __half g_aoh[CK_T*CK_D];               // ao fp16
__device__ __align__(16) __half g_hnh[CK_T*CK_D];               // hn fp16
__device__ __align__(16) __half g_gsh[(size_t)CK_T*CK_FFN];     // ghs fp16
__device__ __align__(16) __half g_xqh[CK_T*CK_D];               // rope(q)
__device__ __align__(16) __half g_xkh[CK_T*CK_KV*CK_HD];        // rope(k)
__device__ __align__(16) __half g_xvh[CK_T*CK_KV*CK_HD];        // v fp16
__device__ __align__(16) __half g_vth[CK_T*CK_KV*CK_HD];        // V^T
__device__ __align__(16) __half g_sch[(size_t)CK_B*CK_H*CK_S*CK_S]; // attn
__device__ __align__(16) __half g_h1h[(size_t)CK_T*CK_FFN];
__device__ __align__(16) __half g_h3h[(size_t)CK_T*CK_FFN];
__device__ __align__(16) __half g_eB1h[NEB], g_eB3h[NEB], g_eA2h[NEB];
__device__ __align__(16) __half g_eB2h[NB2];

// ===========================================================================
// helpers
// ===========================================================================
__device__ __forceinline__ uint32_t smem_u32(const void* p) {
    uint32_t a;
    asm("{ .reg .u64 t; cvta.to.shared.u64 t, %1; cvt.u32.u64 %0, t; }" : "=r"(a) : "l"(p));
    return a;
}
#define CP_ASYNC16(dst_u32, src_ptr) \
    asm volatile("cp.async.cg.shared.global [%0], [%1], 16;" :: "r"(dst_u32), "l"(src_ptr))
#define CP_COMMIT() asm volatile("cp.async.commit_group;" ::: "memory")
#define CP_WAIT(n)  asm volatile("cp.async.wait_group %0;" :: "n"(n) : "memory")

__device__ __forceinline__ void mma16816(float* d, const uint32_t* a,
                                         uint32_t b0, uint32_t b1) {
    asm volatile(
        "mma.sync.aligned.m16n8k16.row.col.f32.f16.f16.f32 "
        "{%0,%1,%2,%3}, {%4,%5,%6,%7}, {%8,%9}, {%0,%1,%2,%3};"
        : "+f"(d[0]), "+f"(d[1]), "+f"(d[2]), "+f"(d[3])
        : "r"(a[0]), "r"(a[1]), "r"(a[2]), "r"(a[3]), "r"(b0), "r"(b1));
}

__device__ __forceinline__ void store4h(__half* p, float4 v) {
    *(__half2*)(p + 0) = __floats2half2_rn(v.x, v.y);
    *(__half2*)(p + 2) = __floats2half2_rn(v.z, v.w);
}

// MUFU-free e^x
__device__ __forceinline__ float fexp(float x) {
    float t = fminf(fmaxf(x * 1.4426950408889634f, -30.f), 30.f);
    float n = rintf(t);
    float f = t - n;
    float p = 1.f + f*(0.6931471806f + f*(0.2402265069f + f*(0.0555041087f
            + f*(0.0096181291f + f*0.0013333558f))));
    return __int_as_float(((int)n + 127) << 23) * p;
}

// ---------------------------------------------------------------------------
// k_conv_all: all fp32->fp16 weight conversions in ONE kernel
// segments: wq,wk,wv,wo,w1,w3,w2,eB1,eB3,eA2,eB2
// ---------------------------------------------------------------------------
#define CB0 ((size_t)NWQ)
#define CB1 (CB0 + NWK)
#define CB2 (CB1 + NWK)
#define CB3 (CB2 + NWQ)
#define CB4 (CB3 + NW1)
#define CB5 (CB4 + NW1)
#define CB6 (CB5 + NW1)
#define CB7 (CB6 + NEB)
#define CB8 (CB7 + NEB)
#define CB9 (CB8 + NEB)
#define CBT (CB9 + NB2)     // total = 47,513,600

__global__ void k_conv_all(
    const float* s0, const float* s1, const float* s2, const float* s3,
    const float* s4, const float* s5, const float* s6, const float* s7,
    const float* s8, const float* s9, const float* s10,
    __half* d0, __half* d1, __half* d2, __half* d3, __half* d4, __half* d5,
    __half* d6, __half* d7, __half* d8, __half* d9, __half* d10)
{
    size_t i = ((size_t)blockIdx.x*256 + threadIdx.x)*8;
    if (i >= CBT) return;
    const float* s; __half* d; size_t off;
    if      (i < CB0) { s = s0;  d = d0;  off = i; }
    else if (i < CB1) { s = s1;  d = d1;  off = i - CB0; }
    else if (i < CB2) { s = s2;  d = d2;  off = i - CB1; }
    else if (i < CB3) { s = s3;  d = d3;  off = i - CB2; }
    else if (i < CB4) { s = s4;  d = d4;  off = i - CB3; }
    else if (i < CB5) { s = s5;  d = d5;  off = i - CB4; }
    else if (i < CB6) { s = s6;  d = d6;  off = i - CB5; }
    else if (i < CB7) { s = s7;  d = d7;  off = i - CB6; }
    else if (i < CB8) { s = s8;  d = d8;  off = i - CB7; }
    else if (i < CB9) { s = s9;  d = d9;  off = i - CB8; }
    else              { s = s10; d = d10; off = i - CB9; }
    store4h(d + off,     *(const float4*)(s + off));
    store4h(d + off + 4, *(const float4*)(s + off + 4));
}

// ===========================================================================
// k_hgemm4: 1-pass fp16 tensor-core GEMM, cp.async double-buffered
//   out = A @ W^T [+ lscale*U@V^T]
//   epilogue: C fp32 (+res), or Ch fp16 (optionally with fused RoPE)
// ===========================================================================
#define HG_LD   40
#define HG_TILE (128*HG_LD)
#define HG_TILEB (HG_TILE*2)
#define HG_SMEM (4*HG_TILEB)     // 40960 bytes

__global__ void __launch_bounds__(256, 2) k_hgemm4(
    const __half* __restrict__ A, const __half* __restrict__ W,
    float* __restrict__ C, __half* __restrict__ Ch, int M, int N, int K,
    const float* __restrict__ U, int ustride, const float* __restrict__ V,
    float lscale, const float* __restrict__ res,
    const float* __restrict__ rope_c, const float* __restrict__ rope_s)
{
    extern __shared__ __align__(16) __half sm[];
    __half* pA = sm;
    __half* pW = sm + 2*HG_TILE;
    const uint32_t sbA = smem_u32(sm);
    const uint32_t sbW = sbA + 2*HG_TILEB;

    const int tid  = threadIdx.x;
    const int wid  = tid >> 5, lane = tid & 31;
    const int g    = lane >> 2, tg = lane & 3;
    const int warpM = wid & 3;
    const int warpN = wid >> 2;
    const int bm = blockIdx.y * 128;
    const int bn = blockIdx.x * 128;

    float acc[2][8][4];
    #pragma unroll
    for (int mi = 0; mi < 2; mi++)
        #pragma unroll
        for (int ni = 0; ni < 8; ni++)
            #pragma unroll
            for (int q = 0; q < 4; q++) acc[mi][ni][q] = 0.f;

    const int NC = K / 32;
    const int total = NC + (U ? 1 : 0);

    auto load_async = [&](int c, int buf) {
        const int k0 = c * 32;
        const uint32_t bo = (uint32_t)buf * HG_TILEB;
        #pragma unroll
        for (int it = 0; it < 2; it++) {
            int id = it*256 + tid;
            int r = id >> 2, sg = (id & 3) * 8;
            uint32_t so = bo + (uint32_t)(r*HG_LD + sg)*2;
            CP_ASYNC16(sbA + so, A + (size_t)(bm + r)*K + k0 + sg);
            CP_ASYNC16(sbW + so, W + (size_t)(bn + r)*K + k0 + sg);
        }
        CP_COMMIT();
    };

    auto load_lora = [&](int buf) {
        __half* dA = pA + buf*HG_TILE;
        __half* dW = pW + buf*HG_TILE;
        #pragma unroll
        for (int l = 0; l < 4; l++) {
            int id = l*256 + tid;
            int r = id >> 3, c4 = (id & 7)*4;
            float4 va = make_float4(0.f,0.f,0.f,0.f);
            float4 vw = make_float4(0.f,0.f,0.f,0.f);
            if (c4 < 16) {
                va = *(const float4*)(U + (size_t)(bm + r)*ustride + c4);
                va.x *= lscale; va.y *= lscale; va.z *= lscale; va.w *= lscale;
                vw = *(const float4*)(V + (size_t)(bn + r)*16 + c4);
            }
            store4h(dA + r*HG_LD + c4, va);
            store4h(dW + r*HG_LD + c4, vw);
        }
    };

    load_async(0, 0);

    for (int c = 0; c < total; c++) {
        const int cur = c & 1, nb = (c + 1) & 1;
        const bool have_next = (c + 1 < total);
        const bool next_async = (c + 1 < NC);
        if (have_next) {
            if (next_async) load_async(c + 1, nb);
            else            load_lora(nb);
        }
        if (c < NC) {
            if (have_next && next_async) { CP_WAIT(1); }
            else                         { CP_WAIT(0); }
        }
        __syncthreads();

        const __half* bA = pA + cur*HG_TILE;
        const __half* bW = pW + cur*HG_TILE;

        #pragma unroll
        for (int ks = 0; ks < 2; ks++) {
            const int col0 = ks*16 + tg*2;
            uint32_t a[2][4];
            #pragma unroll
            for (int mi = 0; mi < 2; mi++) {
                int r0 = warpM*32 + mi*16 + g;
                a[mi][0] = *(const uint32_t*)(bA + r0*HG_LD + col0);
                a[mi][1] = *(const uint32_t*)(bA + (r0+8)*HG_LD + col0);
                a[mi][2] = *(const uint32_t*)(bA + r0*HG_LD + col0 + 8);
                a[mi][3] = *(const uint32_t*)(bA + (r0+8)*HG_LD + col0 + 8);
            }
            #pragma unroll
            for (int ni = 0; ni < 8; ni++) {
                int rn = warpN*64 + ni*8 + g;
                uint32_t b0 = *(const uint32_t*)(bW + rn*HG_LD + col0);
                uint32_t b1 = *(const uint32_t*)(bW + rn*HG_LD + col0 + 8);
                #pragma unroll
                for (int mi = 0; mi < 2; mi++)
                    mma16816(acc[mi][ni], a[mi], b0, b1);
            }
        }
        __syncthreads();
    }

    #pragma unroll
    for (int mi = 0; mi < 2; mi++) {
        size_t r0 = (size_t)(bm + warpM*32 + mi*16 + g);
        #pragma unroll
        for (int ni = 0; ni < 8; ni++) {
            size_t c0 = (size_t)(bn + warpN*64 + ni*8 + tg*2);
            if (Ch) {
                float o[4] = {acc[mi][ni][0], acc[mi][ni][1],
                              acc[mi][ni][2], acc[mi][ni][3]};
                if (rope_c) {
                    int d2 = ((int)c0 & 127) >> 1;
                    int sA = (int)r0 & (CK_S - 1);
                    int sB = (int)(r0 + 8) & (CK_S - 1);
                    float ca = rope_c[sA*64 + d2], sa = rope_s[sA*64 + d2];
                    float cb = rope_c[sB*64 + d2], sb = rope_s[sB*64 + d2];
                    float x1 = o[0], x2 = o[1];
                    o[0] = x1*ca - x2*sa; o[1] = x1*sa + x2*ca;
                    x1 = o[2]; x2 = o[3];
                    o[2] = x1*cb - x2*sb; o[3] = x1*sb + x2*cb;
                }
                *(__half2*)(Ch + r0*N + c0)     = __floats2half2_rn(o[0], o[1]);
                *(__half2*)(Ch + (r0+8)*N + c0) = __floats2half2_rn(o[2], o[3]);
            } else {
                float2 o0 = make_float2(acc[mi][ni][0], acc[mi][ni][1]);
                float2 o1 = make_float2(acc[mi][ni][2], acc[mi][ni][3]);
                if (res) {
                    float2 r0v = *(const float2*)(res + r0*N + c0);
                    float2 r1v = *(const float2*)(res + (r0+8)*N + c0);
                    o0.x += r0v.x; o0.y += r0v.y;
                    o1.x += r1v.x; o1.y += r1v.y;
                }
                *(float2*)(C + r0*N + c0)     = o0;
                *(float2*)(C + (r0+8)*N + c0) = o1;
            }
        }
    }
}

// ===========================================================================
// k_scores_h: scores = Q@K^T / sqrt(HD), fp16 tensor cores, causal tile skip
// ===========================================================================
#define SC_LD 136
#define SC_SMEM (2*128*SC_LD*2)

__global__ void __launch_bounds__(256) k_scores_h(const __half* __restrict__ q,
                                                  const __half* __restrict__ k,
                                                  float* __restrict__ sc) {
    const int t0 = blockIdx.x*128, s0 = blockIdx.y*128;
    if (t0 > s0) return;
    const int bh = blockIdx.z, b = bh >> 4, h = bh & 15, kv = h >> 2;
    extern __shared__ __align__(16) __half sm[];
    __half* Qs = sm;
    __half* Ks = sm + 128*SC_LD;

    const int tid = threadIdx.x;
    const int wid = tid >> 5, lane = tid & 31;
    const int g = lane >> 2, tg = lane & 3;
    const int warpM = wid & 3, warpN = wid >> 2;

    #pragma unroll
    for (int it = 0; it < 8; it++) {
        int id = it*256 + tid;
        int r = id >> 4, c8 = (id & 15)*8;
        *(uint4*)(Qs + r*SC_LD + c8) =
            *(const uint4*)(q + ((size_t)(b*CK_S + s0 + r)*CK_D + h*CK_HD + c8));
        *(uint4*)(Ks + r*SC_LD + c8) =
            *(const uint4*)(k + ((size_t)(b*CK_S + t0 + r)*(CK_KV*CK_HD) + kv*CK_HD + c8));
    }
    __syncthreads();

    float acc[2][8][4];
    #pragma unroll
    for (int mi = 0; mi < 2; mi++)
        #pragma unroll
        for (int ni = 0; ni < 8; ni++)
            #pragma unroll
            for (int qq = 0; qq < 4; qq++) acc[mi][ni][qq] = 0.f;

    #pragma unroll
    for (int ks = 0; ks < 8; ks++) {
        const int col0 = ks*16 + tg*2;
        uint32_t a[2][4];
        #pragma unroll
        for (int mi = 0; mi < 2; mi++) {
            int r0 = warpM*32 + mi*16 + g;
            a[mi][0] = *(const uint32_t*)(Qs + r0*SC_LD + col0);
            a[mi][1] = *(const uint32_t*)(Qs + (r0+8)*SC_LD + col0);
            a[mi][2] = *(const uint32_t*)(Qs + r0*SC_LD + col0 + 8);
            a[mi][3] = *(const uint32_t*)(Qs + (r0+8)*SC_LD + col0 + 8);
        }
        #pragma unroll
        for (int ni = 0; ni < 8; ni++) {
            int rn = warpN*64 + ni*8 + g;
            uint32_t b0 = *(const uint32_t*)(Ks + rn*SC_LD + col0);
            uint32_t b1 = *(const uint32_t*)(Ks + rn*SC_LD + col0 + 8);
            #pragma unroll
            for (int mi = 0; mi < 2; mi++)
                mma16816(acc[mi][ni], a[mi], b0, b1);
        }
    }

    const float scl = 0.08838834764831845f;
    float* out = sc + (size_t)bh*CK_S*CK_S;
    #pragma unroll
    for (int mi = 0; mi < 2; mi++) {
        size_t r0 = (size_t)(s0 + warpM*32 + mi*16 + g);
        #pragma unroll
        for (int ni = 0; ni < 8; ni++) {
            size_t c0 = (size_t)(t0 + warpN*64 + ni*8 + tg*2);
            *(float2*)(out + r0*CK_S + c0) =
                make_float2(acc[mi][ni][0]*scl, acc[mi][ni][1]*scl);
            *(float2*)(out + (r0+8)*CK_S + c0) =
                make_float2(acc[mi][ni][2]*scl, acc[mi][ni][3]*scl);
        }
    }
}

// ===========================================================================
// k_avh: out(fp16) = attn(fp16) @ V^T(fp16), causal K-bound
// ===========================================================================
__global__ void __launch_bounds__(256, 2) k_avh(const __half* __restrict__ attn,
                                                const __half* __restrict__ vt,
                                                __half* __restrict__ outh) {
    extern __shared__ __align__(16) __half sm[];
    __half* pA = sm;
    __half* pW = sm + 2*HG_TILE;
    const uint32_t sbA = smem_u32(sm);
    const uint32_t sbW = sbA + 2*HG_TILEB;

    const int s0 = blockIdx.y * 128;
    const int bh = blockIdx.z, b = bh >> 4, h = bh & 15, kv = h >> 2;
    const __half* Ab = attn + (size_t)bh*CK_S*CK_S;
    const __half* Wb = vt + ((size_t)(b*CK_KV + kv)*CK_HD)*CK_S;

    const int tid = threadIdx.x;
    const int wid = tid >> 5, lane = tid & 31;
    const int g = lane >> 2, tg = lane & 3;
    const int warpM = wid & 3, warpN = wid >> 2;

    float acc[2][8][4];
    #pragma unroll
    for (int mi = 0; mi < 2; mi++)
        #pragma unroll
        for (int ni = 0; ni < 8; ni++)
            #pragma unroll
            for (int q = 0; q < 4; q++) acc[mi][ni][q] = 0.f;

    const int NC = (s0 + 128) / 32;

    auto load_async = [&](int c, int buf) {
        const int k0 = c * 32;
        const uint32_t bo = (uint32_t)buf * HG_TILEB;
        #pragma unroll
        for (int it = 0; it < 2; it++) {
            int id = it*256 + tid;
            int r = id >> 2, sg = (id & 3) * 8;
            uint32_t so = bo + (uint32_t)(r*HG_LD + sg)*2;
            CP_ASYNC16(sbA + so, Ab + (size_t)(s0 + r)*CK_S + k0 + sg);
            CP_ASYNC16(sbW + so, Wb + (size_t)r*CK_S + k0 + sg);
        }
        CP_COMMIT();
    };

    load_async(0, 0);
    for (int c = 0; c < NC; c++) {
        const int cur = c & 1;
        if (c + 1 < NC) { load_async(c + 1, (c+1)&1); CP_WAIT(1); }
        else            { CP_WAIT(0); }
        __syncthreads();

        const __half* bA = pA + cur*HG_TILE;
        const __half* bW = pW + cur*HG_TILE;
        #pragma unroll
        for (int ks = 0; ks < 2; ks++) {
            const int col0 = ks*16 + tg*2;
            uint32_t a[2][4];
            #pragma unroll
            for (int mi = 0; mi < 2; mi++) {
                int r0 = warpM*32 + mi*16 + g;
                a[mi][0] = *(const uint32_t*)(bA + r0*HG_LD + col0);
                a[mi][1] = *(const uint32_t*)(bA + (r0+8)*HG_LD + col0);
                a[mi][2] = *(const uint32_t*)(bA + r0*HG_LD + col0 + 8);
                a[mi][3] = *(const uint32_t*)(bA + (r0+8)*HG_LD + col0 + 8);
            }
            #pragma unroll
            for (int ni = 0; ni < 8; ni++) {
                int rn = warpN*64 + ni*8 + g;
                uint32_t b0 = *(const uint32_t*)(bW + rn*HG_LD + col0);
                uint32_t b1 = *(const uint32_t*)(bW + rn*HG_LD + col0 + 8);
                #pragma unroll
                for (int mi = 0; mi < 2; mi++)
                    mma16816(acc[mi][ni], a[mi], b0, b1);
            }
        }
        __syncthreads();
    }

    #pragma unroll
    for (int mi = 0; mi < 2; mi++) {
        int s = s0 + warpM*32 + mi*16 + g;
        #pragma unroll
        for (int ni = 0; ni < 8; ni++) {
            int c0 = warpN*64 + ni*8 + tg*2;
            size_t off0 = ((size_t)(b*CK_S + s)*CK_H + h)*CK_HD + c0;
            size_t off1 = ((size_t)(b*CK_S + s + 8)*CK_H + h)*CK_HD + c0;
            *(__half2*)(outh + off0) = __floats2half2_rn(acc[mi][ni][0], acc[mi][ni][1]);
            *(__half2*)(outh + off1) = __floats2half2_rn(acc[mi][ni][2], acc[mi][ni][3]);
        }
    }
}

// ---------------------------------------------------------------------------
// k_vt: V fp16 [t][kv*HD] -> V^T fp16 [b][kv][hd][s]
// ---------------------------------------------------------------------------
__global__ void k_vt(const __half* __restrict__ xv, __half* __restrict__ vt) {
    int bkv = blockIdx.z, b = bkv >> 2, kv = bkv & 3;
    int s0 = blockIdx.x*32, h0 = blockIdx.y*32;
    __shared__ __half t[32][33];
    int x = threadIdx.x & 31, y = threadIdx.x >> 5;
    for (int i = y; i < 32; i += 8)
        t[i][x] = xv[(size_t)(b*CK_S + s0 + i)*(CK_KV*CK_HD) + kv*CK_HD + h0 + x];
    __syncthreads();
    for (int i = y; i < 32; i += 8)
        vt[((size_t)bkv*CK_HD + h0 + i)*CK_S + s0 + x] = t[x][i];
}

// ---------------------------------------------------------------------------
// RMSNorm (fp32 out + fp16 out)
// ---------------------------------------------------------------------------
__global__ void k_rmsnorm(const float* __restrict__ x, const float* __restrict__ w,
                          float* __restrict__ o, __half* __restrict__ oh) {
    int t = blockIdx.x;
    const float* xr = x + (size_t)t*CK_D;
    float ss = 0.f;
    for (int i = threadIdx.x; i < CK_D; i += 256) { float v = xr[i]; ss += v*v; }
    __shared__ float red[256];
    red[threadIdx.x] = ss; __syncthreads();
    for (int s = 128; s > 0; s >>= 1) {
        if (threadIdx.x < s) red[threadIdx.x] += red[threadIdx.x+s];
        __syncthreads();
    }
    float sc = rsqrtf(red[0]/(float)CK_D + 1e-5f);
    float* orow = o + (size_t)t*CK_D;
    __half* hrow = oh + (size_t)t*CK_D;
    for (int i = threadIdx.x; i < CK_D; i += 256) {
        float r = xr[i]*sc*w[i];
        orow[i] = r;
        hrow[i] = __float2half_rn(r);
    }
}

// ---------------------------------------------------------------------------
// Fused q/k/v LoRA downs (fp32 X)
// ---------------------------------------------------------------------------
__global__ void k_lora_down3(const float* __restrict__ X,
                             const float* __restrict__ A1, const float* __restrict__ A2,
                             const float* __restrict__ A3,
                             float* __restrict__ U1, float* __restrict__ U2,
                             float* __restrict__ U3) {
    int t = blockIdx.x;
    __shared__ float sx[CK_D];
    for (int i = threadIdx.x; i < CK_D; i += 256) sx[i] = X[(size_t)t*CK_D + i];
    __syncthreads();
    int w = threadIdx.x >> 5, lane = threadIdx.x & 31;
    for (int rr = w; rr < 48; rr += 8) {
        int m = rr >> 4, r = rr & 15;
        const float* ar = (m == 0 ? A1 : m == 1 ? A2 : A3) + (size_t)r*CK_D;
        float p = 0.f;
        for (int d = lane; d < CK_D; d += 32) p += sx[d]*ar[d];
        for (int o = 16; o; o >>= 1) p += __shfl_down_sync(0xffffffffu, p, o);
        if (lane == 0) (m == 0 ? U1 : m == 1 ? U2 : U3)[t*CK_R + r] = p;
    }
}

// LoRA down with fp16 X input
__global__ void k_lora_down_h(const __half* __restrict__ X, const float* __restrict__ A,
                              float* __restrict__ U) {
    int t = blockIdx.x;
    __shared__ float sx[CK_D];
    for (int i = threadIdx.x; i < CK_D; i += 256)
        sx[i] = __half2float(X[(size_t)t*CK_D + i]);
    __syncthreads();
    int w = threadIdx.x >> 5, lane = threadIdx.x & 31;
    for (int r = w; r < CK_R; r += 8) {
        const float* ar = A + (size_t)r*CK_D;
        float p = 0.f;
        for (int d = lane; d < CK_D; d += 32) p += sx[d]*ar[d];
        for (int o = 16; o; o >>= 1) p += __shfl_down_sync(0xffffffffu, p, o);
        if (lane == 0) U[t*CK_R + r] = p;
    }
}

// ---------------------------------------------------------------------------
// Causal softmax (MUFU-free exp): fp32 scores in, fp16 attn out
// ---------------------------------------------------------------------------
__global__ void k_softmax(const float* __restrict__ sc, __half* __restrict__ sch) {
    int row = blockIdx.x;
    int s = row & (CK_S - 1);
    const float* p = sc + (size_t)row*CK_S;
    __half* ph = sch + (size_t)row*CK_S;
    int L = s + 1;
    int tid = threadIdx.x;
    float v0 = (tid       < L) ? p[tid]       : -1e30f;
    float v1 = (tid + 256 < L) ? p[tid + 256] : -1e30f;
    __shared__ float red[256];
    red[tid] = fmaxf(v0, v1); __syncthreads();
    for (int st = 128; st; st >>= 1) {
        if (tid < st) red[tid] = fmaxf(red[tid], red[tid+st]);
        __syncthreads();
    }
    float m = red[0]; __syncthreads();
    float e0 = (tid       < L) ? fexp(v0 - m) : 0.f;
    float e1 = (tid + 256 < L) ? fexp(v1 - m) : 0.f;
    red[tid] = e0 + e1; __syncthreads();
    for (int st = 128; st; st >>= 1) {
        if (tid < st) red[tid] += red[tid+st];
        __syncthreads();
    }
    float inv = 1.f / red[0];
    ph[tid]       = __float2half_rn(e0 * inv);
    ph[tid + 256] = __float2half_rn(e1 * inv);
}

// ---------------------------------------------------------------------------
// Gate
// ---------------------------------------------------------------------------
__global__ void k_gate(const float* __restrict__ hn, const float* __restrict__ gw,
                       float* __restrict__ route) {
    int t = blockIdx.x;
    __shared__ float sl[8];
    int w = threadIdx.x >> 5, lane = threadIdx.x & 31;
    const float* xr = hn + (size_t)t*CK_D;
    const float* gr = gw + (size_t)w*CK_D;
    float p = 0.f;
    for (int d = lane; d < CK_D; d += 32) p += xr[d]*gr[d];
    for (int o = 16; o; o >>= 1) p += __shfl_down_sync(0xffffffffu, p, o);
    if (lane == 0) sl[w] = p;
    __syncthreads();
    if (threadIdx.x == 0) {
        int i0 = 0;
        for (int e = 1; e < 8; e++) if (sl[e] > sl[i0]) i0 = e;
        int i1 = -1;
        for (int e = 0; e < 8; e++) { if (e == i0) continue; if (i1 < 0 || sl[e] > sl[i1]) i1 = e; }
        float m = sl[i0];
        float v0 = expf(sl[i0]-m), v1 = expf(sl[i1]-m);
        float inv = 1.f/(v0+v1);
        float* rr = route + (size_t)t*CK_E;
        #pragma unroll
        for (int e = 0; e < 8; e++) rr[e] = 0.f;
        rr[i0] = v0*inv; rr[i1] = v1*inv;
    }
}

// ---------------------------------------------------------------------------
// Expert LoRA downs
// ---------------------------------------------------------------------------
__global__ void k_expert_down(const float* __restrict__ X, const float* __restrict__ A1,
                              const float* __restrict__ A3, const float* __restrict__ route,
                              float* __restrict__ U1, float* __restrict__ U3) {
    int t = blockIdx.x, e = blockIdx.y;
    if (route[t*CK_E + e] == 0.f) return;
    __shared__ float sx[CK_D];
    for (int i = threadIdx.x; i < CK_D; i += 256) sx[i] = X[(size_t)t*CK_D + i];
    __syncthreads();
    int w = threadIdx.x >> 5, lane = threadIdx.x & 31;
    const float* a1 = A1 + (size_t)e*CK_R*CK_D;
    const float* a3 = A3 + (size_t)e*CK_R*CK_D;
    for (int r = w; r < CK_R; r += 8) {
        float p1 = 0.f, p3 = 0.f;
        for (int d = lane; d < CK_D; d += 32) {
            float xv = sx[d];
            p1 += xv*a1[(size_t)r*CK_D + d];
            p3 += xv*a3[(size_t)r*CK_D + d];
        }
        for (int o = 16; o; o >>= 1) {
            p1 += __shfl_down_sync(0xffffffffu, p1, o);
            p3 += __shfl_down_sync(0xffffffffu, p3, o);
        }
        if (lane == 0) {
            U1[((size_t)t*CK_E + e)*CK_R + r] = p1;
            U3[((size_t)t*CK_E + e)*CK_R + r] = p3;
        }
    }
}

// ---------------------------------------------------------------------------
// Fused per-token MoE combine (fp16 h1/h3; fexp + paired rcp silu)
// ---------------------------------------------------------------------------
__device__ __forceinline__ void h8f(const __half* p, float* f) {
    uint4 q = *(const uint4*)p;
    const __half2* hp = (const __half2*)&q;
    #pragma unroll
    for (int j = 0; j < 4; j++) {
        float2 t = __half22float2(hp[j]);
        f[2*j] = t.x; f[2*j+1] = t.y;
    }
}

__global__ void __launch_bounds__(256) k_moe_expert(
    const __half* __restrict__ h1, const __half* __restrict__ h3,
    const float* __restrict__ ua1, const float* __restrict__ ua3,
    const __half* __restrict__ eB1, const __half* __restrict__ eB3,
    const __half* __restrict__ eA2, const float* __restrict__ route,
    __half* __restrict__ ghs, float* __restrict__ v2)
{
    const int t = blockIdx.x;
    const int tid = threadIdx.x;
    const int wid = tid >> 5, lane = tid & 31;
    const int NI = CK_FFN/256;   // 22
    float ghacc[CK_FFN/256];
    #pragma unroll
    for (int i = 0; i < NI; i++) ghacc[i] = 0.f;
    __shared__ float su1[16], su3[16];
    __shared__ float part[8][16];
    const __half* h1r = h1 + (size_t)t*CK_FFN;
    const __half* h3r = h3 + (size_t)t*CK_FFN;

    #pragma unroll 1
    for (int e = 0; e < CK_E; e++) {
        float wgt = route[t*CK_E + e];
        if (wgt == 0.f) {
            if (tid < 16) v2[(size_t)t*(CK_E*CK_R) + e*16 + tid] = 0.f;
            continue;
        }
        if (tid < 16) {
            su1[tid] = ua1[((size_t)t*CK_E + e)*16 + tid];
            su3[tid] = ua3[((size_t)t*CK_E + e)*16 + tid];
        }
        __syncthreads();
        float u1[16], u3[16];
        #pragma unroll
        for (int r = 0; r < 16; r++) { u1[r] = su1[r]; u3[r] = su3[r]; }
        float accr[16];
        #pragma unroll
        for (int r = 0; r < 16; r++) accr[r] = 0.f;
        const __half* B1 = eB1 + (size_t)e*CK_FFN*16;
        const __half* B3 = eB3 + (size_t)e*CK_FFN*16;
        const __half* A2 = eA2 + (size_t)e*16*CK_FFN;
        #pragma unroll 1
        for (int ii = 0; ii < NI; ii += 2) {
            float prod[2], esig[2];
            const int fA = ii*256 + tid, fB = fA + 256;
            #pragma unroll
            for (int hi = 0; hi < 2; hi++) {
                int f = hi ? fB : fA;
                float b1v[16], b3v[16];
                h8f(B1 + (size_t)f*16,     b1v);
                h8f(B1 + (size_t)f*16 + 8, b1v + 8);
                h8f(B3 + (size_t)f*16,     b3v);
                h8f(B3 + (size_t)f*16 + 8, b3v + 8);
                float b1 = 0.f, b3 = 0.f;
                #pragma unroll
                for (int r = 0; r < 16; r++) { b1 += u1[r]*b1v[r]; b3 += u3[r]*b3v[r]; }
                float g1 = __half2float(h1r[f]) + CK_LS*b1;
                float g3 = __half2float(h3r[f]) + CK_LS*b3;
                prod[hi] = g1*g3;
                esig[hi] = fexp(-g1);
            }
            float da = 1.f + esig[0], db = 1.f + esig[1];
            float rr;
            asm("rcp.approx.f32 %0, %1;" : "=f"(rr) : "f"(da*db));
            float gh[2];
            gh[0] = prod[0]*(rr*db);
            gh[1] = prod[1]*(rr*da);
            ghacc[ii]   += wgt*gh[0];
            ghacc[ii+1] += wgt*gh[1];
            #pragma unroll
            for (int hi = 0; hi < 2; hi++) {
                int f = hi ? fB : fA;
                #pragma unroll
                for (int r = 0; r < 16; r++)
                    accr[r] += gh[hi] * __half2float(A2[(size_t)r*CK_FFN + f]);
            }
        }
        #pragma unroll
        for (int r = 0; r < 16; r++) {
            float v = accr[r];
            #pragma unroll
            for (int o = 16; o; o >>= 1) v += __shfl_down_sync(0xffffffffu, v, o);
            if (lane == 0) part[wid][r] = v;
        }
        __syncthreads();
        if (tid < 16) {
            float s2 = 0.f;
            #pragma unroll
            for (int ww = 0; ww < 8; ww++) s2 += part[ww][tid];
            v2[(size_t)t*(CK_E*CK_R) + e*16 + tid] = wgt*CK_LS*s2;
        }
        __syncthreads();
    }
    __half* go = ghs + (size_t)t*CK_FFN;
    #pragma unroll
    for (int ii = 0; ii < NI; ii++) go[ii*256 + tid] = __float2half_rn(ghacc[ii]);
}

// ---------------------------------------------------------------------------
// fpre = data2 + v2 @ eB2^T
// ---------------------------------------------------------------------------
__global__ void k_moe_up(const float* __restrict__ d2, const float* __restrict__ v2,
                         const __half* __restrict__ eB2, const float* __restrict__ route,
                         float* __restrict__ out) {
    int t = blockIdx.x, tid = threadIdx.x;
    __shared__ float sv[128];
    __shared__ int act[8];
    if (tid < 128) sv[tid] = v2[(size_t)t*128 + tid];
    if (tid < 8)   act[tid] = (route[t*CK_E + tid] != 0.f) ? 1 : 0;
    __syncthreads();
    for (int d = tid; d < CK_D; d += 256) {
        float s = d2[(size_t)t*CK_D + d];
        #pragma unroll 1
        for (int e = 0; e < 8; e++) {
            if (!act[e]) continue;
            float bv[16];
            const __half* bp = eB2 + ((size_t)e*CK_D + d)*16;
            h8f(bp, bv); h8f(bp + 8, bv + 8);
            #pragma unroll
            for (int r = 0; r < 16; r++) s += sv[e*16+r]*bv[r];
        }
        out[(size_t)t*CK_D + d] = s;
    }
}

// ---------------------------------------------------------------------------
// Launch
// ---------------------------------------------------------------------------
extern "C" void kernel_launch(void* const* d_in, const int* in_sizes, int n_in,
                              void* d_out, int out_size) {
    (void)in_sizes; (void)n_in; (void)out_size;
    const float* data  = (const float*)d_in[0];
    const float* rc    = (const float*)d_in[2];
    const float* rs    = (const float*)d_in[3];
    const float* att_w = (const float*)d_in[4];
    const float* ffn_w = (const float*)d_in[5];
    const float* wq    = (const float*)d_in[6];
    const float* wk    = (const float*)d_in[7];
    const float* wv    = (const float*)d_in[8];
    const float* wo    = (const float*)d_in[9];
    const float* lqA   = (const float*)d_in[10];
    const float* lqB   = (const float*)d_in[11];
    const float* lkA   = (const float*)d_in[12];
    const float* lkB   = (const float*)d_in[13];
    const float* lvA   = (const float*)d_in[14];
    const float* lvB   = (const float*)d_in[15];
    const float* loA   = (const float*)d_in[16];
    const float* loB   = (const float*)d_in[17];
    const float* w1    = (const float*)d_in[18];
    const float* w2    = (const float*)d_in[19];
    const float* w3    = (const float*)d_in[20];
    const float* gatew = (const float*)d_in[21];
    const float* eA1   = (const float*)d_in[22];
    const float* eB1   = (const float*)d_in[23];
    const float* eA2   = (const float*)d_in[24];
    const float* eB2   = (const float*)d_in[25];
    const float* eA3   = (const float*)d_in[26];
    const float* eB3   = (const float*)d_in[27];
    float* out = (float*)d_out;

    float *p_h,*p_hn,*p_sc,*p_d2,*p_uq,*p_uk,*p_uv,*p_uo;
    float *p_route,*p_ua1,*p_ua3,*p_v2,*p_fpre;
    cudaGetSymbolAddress((void**)&p_h,    g_h);
    cudaGetSymbolAddress((void**)&p_hn,   g_hn);
    cudaGetSymbolAddress((void**)&p_sc,   g_sc);
    cudaGetSymbolAddress((void**)&p_d2,   g_d2);
    cudaGetSymbolAddress((void**)&p_uq,   g_uq);
    cudaGetSymbolAddress((void**)&p_uk,   g_uk);
    cudaGetSymbolAddress((void**)&p_uv,   g_uv);
    cudaGetSymbolAddress((void**)&p_uo,   g_uo);
    cudaGetSymbolAddress((void**)&p_route,g_route);
    cudaGetSymbolAddress((void**)&p_ua1,  g_ua1);
    cudaGetSymbolAddress((void**)&p_ua3,  g_ua3);
    cudaGetSymbolAddress((void**)&p_v2,   g_v2);
    cudaGetSymbolAddress((void**)&p_fpre, g_fpre);

    __half *wqh,*wkh,*wvh,*woh,*w1h,*w3h,*w2h;
    __half *xh,*aoh,*hnh,*gsh,*xqh,*xkh,*xvh,*vth,*sch,*h1h,*h3h;
    __half *eB1h,*eB3h,*eA2h,*eB2h;
    cudaGetSymbolAddress((void**)&wqh, g_wqh);
    cudaGetSymbolAddress((void**)&wkh, g_wkh);
    cudaGetSymbolAddress((void**)&wvh, g_wvh);
    cudaGetSymbolAddress((void**)&woh, g_woh);
    cudaGetSymbolAddress((void**)&w1h, g_w1h);
    cudaGetSymbolAddress((void**)&w3h, g_w3h);
    cudaGetSymbolAddress((void**)&w2h, g_w2h);
    cudaGetSymbolAddress((void**)&xh,  g_xh);
    cudaGetSymbolAddress((void**)&aoh, g_aoh);
    cudaGetSymbolAddress((void**)&hnh, g_hnh);
    cudaGetSymbolAddress((void**)&gsh, g_gsh);
    cudaGetSymbolAddress((void**)&xqh, g_xqh);
    cudaGetSymbolAddress((void**)&xkh, g_xkh);
    cudaGetSymbolAddress((void**)&xvh, g_xvh);
    cudaGetSymbolAddress((void**)&vth, g_vth);
    cudaGetSymbolAddress((void**)&sch, g_sch);
    cudaGetSymbolAddress((void**)&h1h, g_h1h);
    cudaGetSymbolAddress((void**)&h3h, g_h3h);
    cudaGetSymbolAddress((void**)&eB1h, g_eB1h);
    cudaGetSymbolAddress((void**)&eB3h, g_eB3h);
    cudaGetSymbolAddress((void**)&eA2h, g_eA2h);
    cudaGetSymbolAddress((void**)&eB2h, g_eB2h);

    cudaFuncSetAttribute(k_hgemm4,   cudaFuncAttributeMaxDynamicSharedMemorySize, HG_SMEM);
    cudaFuncSetAttribute(k_scores_h, cudaFuncAttributeMaxDynamicSharedMemorySize, SC_SMEM);
    cudaFuncSetAttribute(k_avh,      cudaFuncAttributeMaxDynamicSharedMemorySize, HG_SMEM);

    // --- all weight conversions in one launch ---
    k_conv_all<<<(int)((CBT/8 + 255)/256),256>>>(
        wq, wk, wv, wo, w1, w3, w2, eB1, eB3, eA2, eB2,
        wqh, wkh, wvh, woh, w1h, w3h, w2h, eB1h, eB3h, eA2h, eB2h);

    // --- attention path ---
    k_rmsnorm<<<CK_T,256>>>(data, att_w, p_h, xh);
    k_lora_down3<<<CK_T,256>>>(p_h, lqA, lkA, lvA, p_uq, p_uk, p_uv);
    k_hgemm4<<<dim3(CK_D/128, CK_T/128),256,HG_SMEM>>>(xh, wqh, nullptr, xqh, CK_T, CK_D, CK_D, p_uq, 16, lqB, CK_LS, nullptr, rc, rs);
    k_hgemm4<<<dim3(512/128,  CK_T/128),256,HG_SMEM>>>(xh, wkh, nullptr, xkh, CK_T, 512,  CK_D, p_uk, 16, lkB, CK_LS, nullptr, rc, rs);
    k_hgemm4<<<dim3(512/128,  CK_T/128),256,HG_SMEM>>>(xh, wvh, nullptr, xvh, CK_T, 512,  CK_D, p_uv, 16, lvB, CK_LS, nullptr, nullptr, nullptr);
    k_vt<<<dim3(CK_S/32, CK_HD/32, CK_B*CK_KV),256>>>(xvh, vth);
    k_scores_h<<<dim3(CK_S/128, CK_S/128, CK_B*CK_H),256,SC_SMEM>>>(xqh, xkh, p_sc);
    k_softmax<<<CK_B*CK_H*CK_S,256>>>(p_sc, sch);
    k_avh<<<dim3(1, CK_S/128, CK_B*CK_H),256,HG_SMEM>>>(sch, vth, aoh);
    k_lora_down_h<<<CK_T,256>>>(aoh, loA, p_uo);
    k_hgemm4<<<dim3(CK_D/128, CK_T/128),256,HG_SMEM>>>(aoh, woh, p_d2, nullptr, CK_T, CK_D, CK_D, p_uo, 16, loB, CK_LS, data, nullptr, nullptr);

    // --- MoE path ---
    k_rmsnorm<<<CK_T,256>>>(p_d2, ffn_w, p_hn, hnh);
    k_gate<<<CK_T,256>>>(p_hn, gatew, p_route);
    k_expert_down<<<dim3(CK_T, CK_E),256>>>(p_hn, eA1, eA3, p_route, p_ua1, p_ua3);
    k_hgemm4<<<dim3(CK_FFN/128, CK_T/128),256,HG_SMEM>>>(hnh, w1h, nullptr, h1h, CK_T, CK_FFN, CK_D, nullptr, 0, nullptr, 0.f, nullptr, nullptr, nullptr);
    k_hgemm4<<<dim3(CK_FFN/128, CK_T/128),256,HG_SMEM>>>(hnh, w3h, nullptr, h3h, CK_T, CK_FFN, CK_D, nullptr, 0, nullptr, 0.f, nullptr, nullptr, nullptr);
    k_moe_expert<<<CK_T,256>>>(h1h, h3h, p_ua1, p_ua3, eB1h, eB3h, eA2h, p_route, gsh, p_v2);
    k_moe_up<<<CK_T,256>>>(p_d2, p_v2, eB2h, p_route, p_fpre);
    k_hgemm4<<<dim3(CK_D/128, CK_T/128),256,HG_SMEM>>>(gsh, w2h, out, nullptr, CK_T, CK_D, CK_FFN, nullptr, 0, nullptr, 0.f, p_fpre, nullptr, nullptr);
}

// round 13
// speedup vs baseline: 1.9146x; 1.0512x over previous
#include <cuda_runtime.h>
#include <cuda_fp16.h>
#include <math.h>
#include <stdint.h>

#define CK_B   4
#define CK_S   512
#define CK_D   2048
#define CK_H   16
#define CK_KV  4
#define CK_HD  128
#define CK_T   2048          // B*S
#define CK_FFN 5632
#define CK_E   8
#define CK_R   16
#define CK_LS  2.0f          // 32/16

// ---------------------------------------------------------------------------
// fp32 scratch
// ---------------------------------------------------------------------------
__device__ float g_h   [CK_T*CK_D];
__device__ float g_hn  [CK_T*CK_D];
__device__ float g_sc  [(size_t)CK_B*CK_H*CK_S*CK_S];
__device__ float g_d2  [CK_T*CK_D];
__device__ float g_uq  [CK_T*CK_R];
__device__ float g_uk  [CK_T*CK_R];
__device__ float g_uv  [CK_T*CK_R];
__device__ float g_uo  [CK_T*CK_R];
__device__ float g_route[CK_T*CK_E];
__device__ float g_ua1 [CK_T*CK_E*CK_R];
__device__ float g_ua3 [CK_T*CK_E*CK_R];
__device__ float g_v2  [CK_T*CK_E*CK_R];
__device__ float g_fpre[CK_T*CK_D];

// ---------------------------------------------------------------------------
// fp16 scratch
// ---------------------------------------------------------------------------
#define NWQ (CK_D*CK_D)
#define NWK (512*CK_D)
#define NW1 (CK_FFN*CK_D)
#define NEB (CK_E*CK_FFN*CK_R)
#define NB2 (CK_E*CK_D*CK_R)
__device__ __align__(16) __half g_wqh[NWQ];
__device__ __align__(16) __half g_wkh[NWK];
__device__ __align__(16) __half g_wvh[NWK];
__device__ __align__(16) __half g_woh[NWQ];
__device__ __align__(16) __half g_w1h[NW1];
__device__ __align__(16) __half g_w3h[NW1];
__device__ __align__(16) __half g_w2h[NW1];
__device__ __align__(16) __half g_xh [CK_T*CK_D];               // h fp16
__device__ __align__(16) __half g_aoh[CK_T*CK_D];               // ao fp16
__device__ __align__(16) __half g_hnh[CK_T*CK_D];               // hn fp16
__device__ __align__(16) __half g_gsh[(size_t)CK_T*CK_FFN];     // ghs fp16
__device__ __align__(16) __half g_xqh[CK_T*CK_D];               // rope(q)
__device__ __align__(16) __half g_xkh[CK_T*CK_KV*CK_HD];        // rope(k)
__device__ __align__(16) __half g_xvh[CK_T*CK_KV*CK_HD];        // v fp16
__device__ __align__(16) __half g_vth[CK_T*CK_KV*CK_HD];        // V^T
__device__ __align__(16) __half g_sch[(size_t)CK_B*CK_H*CK_S*CK_S]; // attn
__device__ __align__(16) __half g_h1h[(size_t)CK_T*CK_FFN];
__device__ __align__(16) __half g_h3h[(size_t)CK_T*CK_FFN];
__device__ __align__(16) __half g_eB1h[NEB], g_eB3h[NEB], g_eA2h[NEB];
__device__ __align__(16) __half g_eB2h[NB2];

// ===========================================================================
// helpers
// ===========================================================================
__device__ __forceinline__ uint32_t smem_u32(const void* p) {
    uint32_t a;
    asm("{ .reg .u64 t; cvta.to.shared.u64 t, %1; cvt.u32.u64 %0, t; }" : "=r"(a) : "l"(p));
    return a;
}
#define CP_ASYNC16(dst_u32, src_ptr) \
    asm volatile("cp.async.cg.shared.global [%0], [%1], 16;" :: "r"(dst_u32), "l"(src_ptr))
#define CP_COMMIT() asm volatile("cp.async.commit_group;" ::: "memory")
#define CP_WAIT(n)  asm volatile("cp.async.wait_group %0;" :: "n"(n) : "memory")

__device__ __forceinline__ void mma16816(float* d, const uint32_t* a,
                                         uint32_t b0, uint32_t b1) {
    asm volatile(
        "mma.sync.aligned.m16n8k16.row.col.f32.f16.f16.f32 "
        "{%0,%1,%2,%3}, {%4,%5,%6,%7}, {%8,%9}, {%0,%1,%2,%3};"
        : "+f"(d[0]), "+f"(d[1]), "+f"(d[2]), "+f"(d[3])
        : "r"(a[0]), "r"(a[1]), "r"(a[2]), "r"(a[3]), "r"(b0), "r"(b1));
}

__device__ __forceinline__ void store4h(__half* p, float4 v) {
    *(__half2*)(p + 0) = __floats2half2_rn(v.x, v.y);
    *(__half2*)(p + 2) = __floats2half2_rn(v.z, v.w);
}

// MUFU-free e^x
__device__ __forceinline__ float fexp(float x) {
    float t = fminf(fmaxf(x * 1.4426950408889634f, -30.f), 30.f);
    float n = rintf(t);
    float f = t - n;
    float p = 1.f + f*(0.6931471806f + f*(0.2402265069f + f*(0.0555041087f
            + f*(0.0096181291f + f*0.0013333558f))));
    return __int_as_float(((int)n + 127) << 23) * p;
}

// ---------------------------------------------------------------------------
// k_conv_all: all fp32->fp16 weight conversions in ONE kernel
// ---------------------------------------------------------------------------
#define CB0 ((size_t)NWQ)
#define CB1 (CB0 + NWK)
#define CB2 (CB1 + NWK)
#define CB3 (CB2 + NWQ)
#define CB4 (CB3 + NW1)
#define CB5 (CB4 + NW1)
#define CB6 (CB5 + NW1)
#define CB7 (CB6 + NEB)
#define CB8 (CB7 + NEB)
#define CB9 (CB8 + NEB)
#define CBT (CB9 + NB2)

__global__ void k_conv_all(
    const float* s0, const float* s1, const float* s2, const float* s3,
    const float* s4, const float* s5, const float* s6, const float* s7,
    const float* s8, const float* s9, const float* s10,
    __half* d0, __half* d1, __half* d2, __half* d3, __half* d4, __half* d5,
    __half* d6, __half* d7, __half* d8, __half* d9, __half* d10)
{
    size_t i = ((size_t)blockIdx.x*256 + threadIdx.x)*8;
    if (i >= CBT) return;
    const float* s; __half* d; size_t off;
    if      (i < CB0) { s = s0;  d = d0;  off = i; }
    else if (i < CB1) { s = s1;  d = d1;  off = i - CB0; }
    else if (i < CB2) { s = s2;  d = d2;  off = i - CB1; }
    else if (i < CB3) { s = s3;  d = d3;  off = i - CB2; }
    else if (i < CB4) { s = s4;  d = d4;  off = i - CB3; }
    else if (i < CB5) { s = s5;  d = d5;  off = i - CB4; }
    else if (i < CB6) { s = s6;  d = d6;  off = i - CB5; }
    else if (i < CB7) { s = s7;  d = d7;  off = i - CB6; }
    else if (i < CB8) { s = s8;  d = d8;  off = i - CB7; }
    else if (i < CB9) { s = s9;  d = d9;  off = i - CB8; }
    else              { s = s10; d = d10; off = i - CB9; }
    store4h(d + off,     *(const float4*)(s + off));
    store4h(d + off + 4, *(const float4*)(s + off + 4));
}

// ===========================================================================
// k_hgemm4: 1-pass fp16 tensor-core GEMM, cp.async double-buffered, K-chunk 64
//   out = A @ W^T [+ lscale*U@V^T]
//   epilogue: C fp32 (+res), or Ch fp16 (optionally with fused RoPE)
// ===========================================================================
#define HG_LD   72                   // 64 + 8 pad
#define HG_TILE (128*HG_LD)          // 9216 halves
#define HG_TILEB (HG_TILE*2)         // 18432 B
#define HG_SMEM (4*HG_TILEB)         // 73728 B (2 CTAs -> 147 KB/SM)

__global__ void __launch_bounds__(256, 2) k_hgemm4(
    const __half* __restrict__ A, const __half* __restrict__ W,
    float* __restrict__ C, __half* __restrict__ Ch, int M, int N, int K,
    const float* __restrict__ U, int ustride, const float* __restrict__ V,
    float lscale, const float* __restrict__ res,
    const float* __restrict__ rope_c, const float* __restrict__ rope_s)
{
    extern __shared__ __align__(16) __half sm[];
    __half* pA = sm;
    __half* pW = sm + 2*HG_TILE;
    const uint32_t sbA = smem_u32(sm);
    const uint32_t sbW = sbA + 2*HG_TILEB;

    const int tid  = threadIdx.x;
    const int wid  = tid >> 5, lane = tid & 31;
    const int g    = lane >> 2, tg = lane & 3;
    const int warpM = wid & 3;
    const int warpN = wid >> 2;
    const int bm = blockIdx.y * 128;
    const int bn = blockIdx.x * 128;

    float acc[2][8][4];
    #pragma unroll
    for (int mi = 0; mi < 2; mi++)
        #pragma unroll
        for (int ni = 0; ni < 8; ni++)
            #pragma unroll
            for (int q = 0; q < 4; q++) acc[mi][ni][q] = 0.f;

    const int NC = K / 64;
    const int total = NC + (U ? 1 : 0);

    // async load of one 128x64 chunk per operand
    auto load_async = [&](int c, int buf) {
        const int k0 = c * 64;
        const uint32_t bo = (uint32_t)buf * HG_TILEB;
        #pragma unroll
        for (int it = 0; it < 4; it++) {
            int id = it*256 + tid;
            int r = id >> 3, sg = (id & 7) * 8;
            uint32_t so = bo + (uint32_t)(r*HG_LD + sg)*2;
            CP_ASYNC16(sbA + so, A + (size_t)(bm + r)*K + k0 + sg);
            CP_ASYNC16(sbW + so, W + (size_t)(bn + r)*K + k0 + sg);
        }
        CP_COMMIT();
    };

    // LoRA tail chunk: K=16 real, zero-padded to 64
    auto load_lora = [&](int buf) {
        __half* dA = pA + buf*HG_TILE;
        __half* dW = pW + buf*HG_TILE;
        #pragma unroll
        for (int l = 0; l < 8; l++) {
            int id = l*256 + tid;
            int r = id >> 4, c4 = (id & 15)*4;
            float4 va = make_float4(0.f,0.f,0.f,0.f);
            float4 vw = make_float4(0.f,0.f,0.f,0.f);
            if (c4 < 16) {
                va = *(const float4*)(U + (size_t)(bm + r)*ustride + c4);
                va.x *= lscale; va.y *= lscale; va.z *= lscale; va.w *= lscale;
                vw = *(const float4*)(V + (size_t)(bn + r)*16 + c4);
            }
            store4h(dA + r*HG_LD + c4, va);
            store4h(dW + r*HG_LD + c4, vw);
        }
    };

    load_async(0, 0);

    for (int c = 0; c < total; c++) {
        const int cur = c & 1, nb = (c + 1) & 1;
        const bool have_next = (c + 1 < total);
        const bool next_async = (c + 1 < NC);
        if (have_next) {
            if (next_async) load_async(c + 1, nb);
            else            load_lora(nb);
        }
        if (c < NC) {
            if (have_next && next_async) { CP_WAIT(1); }
            else                         { CP_WAIT(0); }
        }
        __syncthreads();

        const __half* bA = pA + cur*HG_TILE;
        const __half* bW = pW + cur*HG_TILE;

        #pragma unroll
        for (int ks = 0; ks < 4; ks++) {
            const int col0 = ks*16 + tg*2;
            uint32_t a[2][4];
            #pragma unroll
            for (int mi = 0; mi < 2; mi++) {
                int r0 = warpM*32 + mi*16 + g;
                a[mi][0] = *(const uint32_t*)(bA + r0*HG_LD + col0);
                a[mi][1] = *(const uint32_t*)(bA + (r0+8)*HG_LD + col0);
                a[mi][2] = *(const uint32_t*)(bA + r0*HG_LD + col0 + 8);
                a[mi][3] = *(const uint32_t*)(bA + (r0+8)*HG_LD + col0 + 8);
            }
            #pragma unroll
            for (int ni = 0; ni < 8; ni++) {
                int rn = warpN*64 + ni*8 + g;
                uint32_t b0 = *(const uint32_t*)(bW + rn*HG_LD + col0);
                uint32_t b1 = *(const uint32_t*)(bW + rn*HG_LD + col0 + 8);
                #pragma unroll
                for (int mi = 0; mi < 2; mi++)
                    mma16816(acc[mi][ni], a[mi], b0, b1);
            }
        }
        __syncthreads();
    }

    #pragma unroll
    for (int mi = 0; mi < 2; mi++) {
        size_t r0 = (size_t)(bm + warpM*32 + mi*16 + g);
        #pragma unroll
        for (int ni = 0; ni < 8; ni++) {
            size_t c0 = (size_t)(bn + warpN*64 + ni*8 + tg*2);
            if (Ch) {
                float o[4] = {acc[mi][ni][0], acc[mi][ni][1],
                              acc[mi][ni][2], acc[mi][ni][3]};
                if (rope_c) {
                    int d2 = ((int)c0 & 127) >> 1;
                    int sA = (int)r0 & (CK_S - 1);
                    int sB = (int)(r0 + 8) & (CK_S - 1);
                    float ca = rope_c[sA*64 + d2], sa = rope_s[sA*64 + d2];
                    float cb = rope_c[sB*64 + d2], sb = rope_s[sB*64 + d2];
                    float x1 = o[0], x2 = o[1];
                    o[0] = x1*ca - x2*sa; o[1] = x1*sa + x2*ca;
                    x1 = o[2]; x2 = o[3];
                    o[2] = x1*cb - x2*sb; o[3] = x1*sb + x2*cb;
                }
                *(__half2*)(Ch + r0*N + c0)     = __floats2half2_rn(o[0], o[1]);
                *(__half2*)(Ch + (r0+8)*N + c0) = __floats2half2_rn(o[2], o[3]);
            } else {
                float2 o0 = make_float2(acc[mi][ni][0], acc[mi][ni][1]);
                float2 o1 = make_float2(acc[mi][ni][2], acc[mi][ni][3]);
                if (res) {
                    float2 r0v = *(const float2*)(res + r0*N + c0);
                    float2 r1v = *(const float2*)(res + (r0+8)*N + c0);
                    o0.x += r0v.x; o0.y += r0v.y;
                    o1.x += r1v.x; o1.y += r1v.y;
                }
                *(float2*)(C + r0*N + c0)     = o0;
                *(float2*)(C + (r0+8)*N + c0) = o1;
            }
        }
    }
}

// ===========================================================================
// k_scores_h: scores = Q@K^T / sqrt(HD), fp16 tensor cores, causal tile skip
// ===========================================================================
#define SC_LD 136
#define SC_SMEM (2*128*SC_LD*2)

__global__ void __launch_bounds__(256) k_scores_h(const __half* __restrict__ q,
                                                  const __half* __restrict__ k,
                                                  float* __restrict__ sc) {
    const int t0 = blockIdx.x*128, s0 = blockIdx.y*128;
    if (t0 > s0) return;
    const int bh = blockIdx.z, b = bh >> 4, h = bh & 15, kv = h >> 2;
    extern __shared__ __align__(16) __half sm[];
    __half* Qs = sm;
    __half* Ks = sm + 128*SC_LD;

    const int tid = threadIdx.x;
    const int wid = tid >> 5, lane = tid & 31;
    const int g = lane >> 2, tg = lane & 3;
    const int warpM = wid & 3, warpN = wid >> 2;

    #pragma unroll
    for (int it = 0; it < 8; it++) {
        int id = it*256 + tid;
        int r = id >> 4, c8 = (id & 15)*8;
        *(uint4*)(Qs + r*SC_LD + c8) =
            *(const uint4*)(q + ((size_t)(b*CK_S + s0 + r)*CK_D + h*CK_HD + c8));
        *(uint4*)(Ks + r*SC_LD + c8) =
            *(const uint4*)(k + ((size_t)(b*CK_S + t0 + r)*(CK_KV*CK_HD) + kv*CK_HD + c8));
    }
    __syncthreads();

    float acc[2][8][4];
    #pragma unroll
    for (int mi = 0; mi < 2; mi++)
        #pragma unroll
        for (int ni = 0; ni < 8; ni++)
            #pragma unroll
            for (int qq = 0; qq < 4; qq++) acc[mi][ni][qq] = 0.f;

    #pragma unroll
    for (int ks = 0; ks < 8; ks++) {
        const int col0 = ks*16 + tg*2;
        uint32_t a[2][4];
        #pragma unroll
        for (int mi = 0; mi < 2; mi++) {
            int r0 = warpM*32 + mi*16 + g;
            a[mi][0] = *(const uint32_t*)(Qs + r0*SC_LD + col0);
            a[mi][1] = *(const uint32_t*)(Qs + (r0+8)*SC_LD + col0);
            a[mi][2] = *(const uint32_t*)(Qs + r0*SC_LD + col0 + 8);
            a[mi][3] = *(const uint32_t*)(Qs + (r0+8)*SC_LD + col0 + 8);
        }
        #pragma unroll
        for (int ni = 0; ni < 8; ni++) {
            int rn = warpN*64 + ni*8 + g;
            uint32_t b0 = *(const uint32_t*)(Ks + rn*SC_LD + col0);
            uint32_t b1 = *(const uint32_t*)(Ks + rn*SC_LD + col0 + 8);
            #pragma unroll
            for (int mi = 0; mi < 2; mi++)
                mma16816(acc[mi][ni], a[mi], b0, b1);
        }
    }

    const float scl = 0.08838834764831845f;
    float* out = sc + (size_t)bh*CK_S*CK_S;
    #pragma unroll
    for (int mi = 0; mi < 2; mi++) {
        size_t r0 = (size_t)(s0 + warpM*32 + mi*16 + g);
        #pragma unroll
        for (int ni = 0; ni < 8; ni++) {
            size_t c0 = (size_t)(t0 + warpN*64 + ni*8 + tg*2);
            *(float2*)(out + r0*CK_S + c0) =
                make_float2(acc[mi][ni][0]*scl, acc[mi][ni][1]*scl);
            *(float2*)(out + (r0+8)*CK_S + c0) =
                make_float2(acc[mi][ni][2]*scl, acc[mi][ni][3]*scl);
        }
    }
}

// ===========================================================================
// k_avh: out(fp16) = attn(fp16) @ V^T(fp16), causal K-bound (K-chunk 32)
// ===========================================================================
#define AV_LD   40
#define AV_TILE (128*AV_LD)
#define AV_TILEB (AV_TILE*2)
#define AV_SMEM (4*AV_TILEB)

__global__ void __launch_bounds__(256, 2) k_avh(const __half* __restrict__ attn,
                                                const __half* __restrict__ vt,
                                                __half* __restrict__ outh) {
    extern __shared__ __align__(16) __half sm[];
    __half* pA = sm;
    __half* pW = sm + 2*AV_TILE;
    const uint32_t sbA = smem_u32(sm);
    const uint32_t sbW = sbA + 2*AV_TILEB;

    const int s0 = blockIdx.y * 128;
    const int bh = blockIdx.z, b = bh >> 4, h = bh & 15, kv = h >> 2;
    const __half* Ab = attn + (size_t)bh*CK_S*CK_S;
    const __half* Wb = vt + ((size_t)(b*CK_KV + kv)*CK_HD)*CK_S;

    const int tid = threadIdx.x;
    const int wid = tid >> 5, lane = tid & 31;
    const int g = lane >> 2, tg = lane & 3;
    const int warpM = wid & 3, warpN = wid >> 2;

    float acc[2][8][4];
    #pragma unroll
    for (int mi = 0; mi < 2; mi++)
        #pragma unroll
        for (int ni = 0; ni < 8; ni++)
            #pragma unroll
            for (int q = 0; q < 4; q++) acc[mi][ni][q] = 0.f;

    const int NC = (s0 + 128) / 32;

    auto load_async = [&](int c, int buf) {
        const int k0 = c * 32;
        const uint32_t bo = (uint32_t)buf * AV_TILEB;
        #pragma unroll
        for (int it = 0; it < 2; it++) {
            int id = it*256 + tid;
            int r = id >> 2, sg = (id & 3) * 8;
            uint32_t so = bo + (uint32_t)(r*AV_LD + sg)*2;
            CP_ASYNC16(sbA + so, Ab + (size_t)(s0 + r)*CK_S + k0 + sg);
            CP_ASYNC16(sbW + so, Wb + (size_t)r*CK_S + k0 + sg);
        }
        CP_COMMIT();
    };

    load_async(0, 0);
    for (int c = 0; c < NC; c++) {
        const int cur = c & 1;
        if (c + 1 < NC) { load_async(c + 1, (c+1)&1); CP_WAIT(1); }
        else            { CP_WAIT(0); }
        __syncthreads();

        const __half* bA = pA + cur*AV_TILE;
        const __half* bW = pW + cur*AV_TILE;
        #pragma unroll
        for (int ks = 0; ks < 2; ks++) {
            const int col0 = ks*16 + tg*2;
            uint32_t a[2][4];
            #pragma unroll
            for (int mi = 0; mi < 2; mi++) {
                int r0 = warpM*32 + mi*16 + g;
                a[mi][0] = *(const uint32_t*)(bA + r0*AV_LD + col0);
                a[mi][1] = *(const uint32_t*)(bA + (r0+8)*AV_LD + col0);
                a[mi][2] = *(const uint32_t*)(bA + r0*AV_LD + col0 + 8);
                a[mi][3] = *(const uint32_t*)(bA + (r0+8)*AV_LD + col0 + 8);
            }
            #pragma unroll
            for (int ni = 0; ni < 8; ni++) {
                int rn = warpN*64 + ni*8 + g;
                uint32_t b0 = *(const uint32_t*)(bW + rn*AV_LD + col0);
                uint32_t b1 = *(const uint32_t*)(bW + rn*AV_LD + col0 + 8);
                #pragma unroll
                for (int mi = 0; mi < 2; mi++)
                    mma16816(acc[mi][ni], a[mi], b0, b1);
            }
        }
        __syncthreads();
    }

    #pragma unroll
    for (int mi = 0; mi < 2; mi++) {
        int s = s0 + warpM*32 + mi*16 + g;
        #pragma unroll
        for (int ni = 0; ni < 8; ni++) {
            int c0 = warpN*64 + ni*8 + tg*2;
            size_t off0 = ((size_t)(b*CK_S + s)*CK_H + h)*CK_HD + c0;
            size_t off1 = ((size_t)(b*CK_S + s + 8)*CK_H + h)*CK_HD + c0;
            *(__half2*)(outh + off0) = __floats2half2_rn(acc[mi][ni][0], acc[mi][ni][1]);
            *(__half2*)(outh + off1) = __floats2half2_rn(acc[mi][ni][2], acc[mi][ni][3]);
        }
    }
}

// ---------------------------------------------------------------------------
// k_vt: V fp16 [t][kv*HD] -> V^T fp16 [b][kv][hd][s]
// ---------------------------------------------------------------------------
__global__ void k_vt(const __half* __restrict__ xv, __half* __restrict__ vt) {
    int bkv = blockIdx.z, b = bkv >> 2, kv = bkv & 3;
    int s0 = blockIdx.x*32, h0 = blockIdx.y*32;
    __shared__ __half t[32][33];
    int x = threadIdx.x & 31, y = threadIdx.x >> 5;
    for (int i = y; i < 32; i += 8)
        t[i][x] = xv[(size_t)(b*CK_S + s0 + i)*(CK_KV*CK_HD) + kv*CK_HD + h0 + x];
    __syncthreads();
    for (int i = y; i < 32; i += 8)
        vt[((size_t)bkv*CK_HD + h0 + i)*CK_S + s0 + x] = t[x][i];
}

// ---------------------------------------------------------------------------
// RMSNorm (fp32 out + fp16 out)
// ---------------------------------------------------------------------------
__global__ void k_rmsnorm(const float* __restrict__ x, const float* __restrict__ w,
                          float* __restrict__ o, __half* __restrict__ oh) {
    int t = blockIdx.x;
    const float* xr = x + (size_t)t*CK_D;
    float ss = 0.f;
    for (int i = threadIdx.x; i < CK_D; i += 256) { float v = xr[i]; ss += v*v; }
    __shared__ float red[256];
    red[threadIdx.x] = ss; __syncthreads();
    for (int s = 128; s > 0; s >>= 1) {
        if (threadIdx.x < s) red[threadIdx.x] += red[threadIdx.x+s];
        __syncthreads();
    }
    float sc = rsqrtf(red[0]/(float)CK_D + 1e-5f);
    float* orow = o + (size_t)t*CK_D;
    __half* hrow = oh + (size_t)t*CK_D;
    for (int i = threadIdx.x; i < CK_D; i += 256) {
        float r = xr[i]*sc*w[i];
        orow[i] = r;
        hrow[i] = __float2half_rn(r);
    }
}

// ---------------------------------------------------------------------------
// Fused q/k/v LoRA downs (fp32 X)
// ---------------------------------------------------------------------------
__global__ void k_lora_down3(const float* __restrict__ X,
                             const float* __restrict__ A1, const float* __restrict__ A2,
                             const float* __restrict__ A3,
                             float* __restrict__ U1, float* __restrict__ U2,
                             float* __restrict__ U3) {
    int t = blockIdx.x;
    __shared__ float sx[CK_D];
    for (int i = threadIdx.x; i < CK_D; i += 256) sx[i] = X[(size_t)t*CK_D + i];
    __syncthreads();
    int w = threadIdx.x >> 5, lane = threadIdx.x & 31;
    for (int rr = w; rr < 48; rr += 8) {
        int m = rr >> 4, r = rr & 15;
        const float* ar = (m == 0 ? A1 : m == 1 ? A2 : A3) + (size_t)r*CK_D;
        float p = 0.f;
        for (int d = lane; d < CK_D; d += 32) p += sx[d]*ar[d];
        for (int o = 16; o; o >>= 1) p += __shfl_down_sync(0xffffffffu, p, o);
        if (lane == 0) (m == 0 ? U1 : m == 1 ? U2 : U3)[t*CK_R + r] = p;
    }
}

// LoRA down with fp16 X input
__global__ void k_lora_down_h(const __half* __restrict__ X, const float* __restrict__ A,
                              float* __restrict__ U) {
    int t = blockIdx.x;
    __shared__ float sx[CK_D];
    for (int i = threadIdx.x; i < CK_D; i += 256)
        sx[i] = __half2float(X[(size_t)t*CK_D + i]);
    __syncthreads();
    int w = threadIdx.x >> 5, lane = threadIdx.x & 31;
    for (int r = w; r < CK_R; r += 8) {
        const float* ar = A + (size_t)r*CK_D;
        float p = 0.f;
        for (int d = lane; d < CK_D; d += 32) p += sx[d]*ar[d];
        for (int o = 16; o; o >>= 1) p += __shfl_down_sync(0xffffffffu, p, o);
        if (lane == 0) U[t*CK_R + r] = p;
    }
}

// ---------------------------------------------------------------------------
// Causal softmax (MUFU-free exp): fp32 scores in, fp16 attn out
// ---------------------------------------------------------------------------
__global__ void k_softmax(const float* __restrict__ sc, __half* __restrict__ sch) {
    int row = blockIdx.x;
    int s = row & (CK_S - 1);
    const float* p = sc + (size_t)row*CK_S;
    __half* ph = sch + (size_t)row*CK_S;
    int L = s + 1;
    int tid = threadIdx.x;
    float v0 = (tid       < L) ? p[tid]       : -1e30f;
    float v1 = (tid + 256 < L) ? p[tid + 256] : -1e30f;
    __shared__ float red[256];
    red[tid] = fmaxf(v0, v1); __syncthreads();
    for (int st = 128; st; st >>= 1) {
        if (tid < st) red[tid] = fmaxf(red[tid], red[tid+st]);
        __syncthreads();
    }
    float m = red[0]; __syncthreads();
    float e0 = (tid       < L) ? fexp(v0 - m) : 0.f;
    float e1 = (tid + 256 < L) ? fexp(v1 - m) : 0.f;
    red[tid] = e0 + e1; __syncthreads();
    for (int st = 128; st; st >>= 1) {
        if (tid < st) red[tid] += red[tid+st];
        __syncthreads();
    }
    float inv = 1.f / red[0];
    ph[tid]       = __float2half_rn(e0 * inv);
    ph[tid + 256] = __float2half_rn(e1 * inv);
}

// ---------------------------------------------------------------------------
// Gate
// ---------------------------------------------------------------------------
__global__ void k_gate(const float* __restrict__ hn, const float* __restrict__ gw,
                       float* __restrict__ route) {
    int t = blockIdx.x;
    __shared__ float sl[8];
    int w = threadIdx.x >> 5, lane = threadIdx.x & 31;
    const float* xr = hn + (size_t)t*CK_D;
    const float* gr = gw + (size_t)w*CK_D;
    float p = 0.f;
    for (int d = lane; d < CK_D; d += 32) p += xr[d]*gr[d];
    for (int o = 16; o; o >>= 1) p += __shfl_down_sync(0xffffffffu, p, o);
    if (lane == 0) sl[w] = p;
    __syncthreads();
    if (threadIdx.x == 0) {
        int i0 = 0;
        for (int e = 1; e < 8; e++) if (sl[e] > sl[i0]) i0 = e;
        int i1 = -1;
        for (int e = 0; e < 8; e++) { if (e == i0) continue; if (i1 < 0 || sl[e] > sl[i1]) i1 = e; }
        float m = sl[i0];
        float v0 = expf(sl[i0]-m), v1 = expf(sl[i1]-m);
        float inv = 1.f/(v0+v1);
        float* rr = route + (size_t)t*CK_E;
        #pragma unroll
        for (int e = 0; e < 8; e++) rr[e] = 0.f;
        rr[i0] = v0*inv; rr[i1] = v1*inv;
    }
}

// ---------------------------------------------------------------------------
// Expert LoRA downs
// ---------------------------------------------------------------------------
__global__ void k_expert_down(const float* __restrict__ X, const float* __restrict__ A1,
                              const float* __restrict__ A3, const float* __restrict__ route,
                              float* __restrict__ U1, float* __restrict__ U3) {
    int t = blockIdx.x, e = blockIdx.y;
    if (route[t*CK_E + e] == 0.f) return;
    __shared__ float sx[CK_D];
    for (int i = threadIdx.x; i < CK_D; i += 256) sx[i] = X[(size_t)t*CK_D + i];
    __syncthreads();
    int w = threadIdx.x >> 5, lane = threadIdx.x & 31;
    const float* a1 = A1 + (size_t)e*CK_R*CK_D;
    const float* a3 = A3 + (size_t)e*CK_R*CK_D;
    for (int r = w; r < CK_R; r += 8) {
        float p1 = 0.f, p3 = 0.f;
        for (int d = lane; d < CK_D; d += 32) {
            float xv = sx[d];
            p1 += xv*a1[(size_t)r*CK_D + d];
            p3 += xv*a3[(size_t)r*CK_D + d];
        }
        for (int o = 16; o; o >>= 1) {
            p1 += __shfl_down_sync(0xffffffffu, p1, o);
            p3 += __shfl_down_sync(0xffffffffu, p3, o);
        }
        if (lane == 0) {
            U1[((size_t)t*CK_E + e)*CK_R + r] = p1;
            U3[((size_t)t*CK_E + e)*CK_R + r] = p3;
        }
    }
}

// ---------------------------------------------------------------------------
// Fused per-token MoE combine (fp16 h1/h3; fexp + paired rcp silu)
// ---------------------------------------------------------------------------
__device__ __forceinline__ void h8f(const __half* p, float* f) {
    uint4 q = *(const uint4*)p;
    const __half2* hp = (const __half2*)&q;
    #pragma unroll
    for (int j = 0; j < 4; j++) {
        float2 t = __half22float2(hp[j]);
        f[2*j] = t.x; f[2*j+1] = t.y;
    }
}

__global__ void __launch_bounds__(256) k_moe_expert(
    const __half* __restrict__ h1, const __half* __restrict__ h3,
    const float* __restrict__ ua1, const float* __restrict__ ua3,
    const __half* __restrict__ eB1, const __half* __restrict__ eB3,
    const __half* __restrict__ eA2, const float* __restrict__ route,
    __half* __restrict__ ghs, float* __restrict__ v2)
{
    const int t = blockIdx.x;
    const int tid = threadIdx.x;
    const int wid = tid >> 5, lane = tid & 31;
    const int NI = CK_FFN/256;   // 22
    float ghacc[CK_FFN/256];
    #pragma unroll
    for (int i = 0; i < NI; i++) ghacc[i] = 0.f;
    __shared__ float su1[16], su3[16];
    __shared__ float part[8][16];
    const __half* h1r = h1 + (size_t)t*CK_FFN;
    const __half* h3r = h3 + (size_t)t*CK_FFN;

    #pragma unroll 1
    for (int e = 0; e < CK_E; e++) {
        float wgt = route[t*CK_E + e];
        if (wgt == 0.f) {
            if (tid < 16) v2[(size_t)t*(CK_E*CK_R) + e*16 + tid] = 0.f;
            continue;
        }
        if (tid < 16) {
            su1[tid] = ua1[((size_t)t*CK_E + e)*16 + tid];
            su3[tid] = ua3[((size_t)t*CK_E + e)*16 + tid];
        }
        __syncthreads();
        float u1[16], u3[16];
        #pragma unroll
        for (int r = 0; r < 16; r++) { u1[r] = su1[r]; u3[r] = su3[r]; }
        float accr[16];
        #pragma unroll
        for (int r = 0; r < 16; r++) accr[r] = 0.f;
        const __half* B1 = eB1 + (size_t)e*CK_FFN*16;
        const __half* B3 = eB3 + (size_t)e*CK_FFN*16;
        const __half* A2 = eA2 + (size_t)e*16*CK_FFN;
        #pragma unroll 1
        for (int ii = 0; ii < NI; ii += 2) {
            float prod[2], esig[2];
            const int fA = ii*256 + tid, fB = fA + 256;
            #pragma unroll
            for (int hi = 0; hi < 2; hi++) {
                int f = hi ? fB : fA;
                float b1v[16], b3v[16];
                h8f(B1 + (size_t)f*16,     b1v);
                h8f(B1 + (size_t)f*16 + 8, b1v + 8);
                h8f(B3 + (size_t)f*16,     b3v);
                h8f(B3 + (size_t)f*16 + 8, b3v + 8);
                float b1 = 0.f, b3 = 0.f;
                #pragma unroll
                for (int r = 0; r < 16; r++) { b1 += u1[r]*b1v[r]; b3 += u3[r]*b3v[r]; }
                float g1 = __half2float(h1r[f]) + CK_LS*b1;
                float g3 = __half2float(h3r[f]) + CK_LS*b3;
                prod[hi] = g1*g3;
                esig[hi] = fexp(-g1);
            }
            float da = 1.f + esig[0], db = 1.f + esig[1];
            float rr;
            asm("rcp.approx.f32 %0, %1;" : "=f"(rr) : "f"(da*db));
            float gh[2];
            gh[0] = prod[0]*(rr*db);
            gh[1] = prod[1]*(rr*da);
            ghacc[ii]   += wgt*gh[0];
            ghacc[ii+1] += wgt*gh[1];
            #pragma unroll
            for (int hi = 0; hi < 2; hi++) {
                int f = hi ? fB : fA;
                #pragma unroll
                for (int r = 0; r < 16; r++)
                    accr[r] += gh[hi] * __half2float(A2[(size_t)r*CK_FFN + f]);
            }
        }
        #pragma unroll
        for (int r = 0; r < 16; r++) {
            float v = accr[r];
            #pragma unroll
            for (int o = 16; o; o >>= 1) v += __shfl_down_sync(0xffffffffu, v, o);
            if (lane == 0) part[wid][r] = v;
        }
        __syncthreads();
        if (tid < 16) {
            float s2 = 0.f;
            #pragma unroll
            for (int ww = 0; ww < 8; ww++) s2 += part[ww][tid];
            v2[(size_t)t*(CK_E*CK_R) + e*16 + tid] = wgt*CK_LS*s2;
        }
        __syncthreads();
    }
    __half* go = ghs + (size_t)t*CK_FFN;
    #pragma unroll
    for (int ii = 0; ii < NI; ii++) go[ii*256 + tid] = __float2half_rn(ghacc[ii]);
}

// ---------------------------------------------------------------------------
// fpre = data2 + v2 @ eB2^T
// ---------------------------------------------------------------------------
__global__ void k_moe_up(const float* __restrict__ d2, const float* __restrict__ v2,
                         const __half* __restrict__ eB2, const float* __restrict__ route,
                         float* __restrict__ out) {
    int t = blockIdx.x, tid = threadIdx.x;
    __shared__ float sv[128];
    __shared__ int act[8];
    if (tid < 128) sv[tid] = v2[(size_t)t*128 + tid];
    if (tid < 8)   act[tid] = (route[t*CK_E + tid] != 0.f) ? 1 : 0;
    __syncthreads();
    for (int d = tid; d < CK_D; d += 256) {
        float s = d2[(size_t)t*CK_D + d];
        #pragma unroll 1
        for (int e = 0; e < 8; e++) {
            if (!act[e]) continue;
            float bv[16];
            const __half* bp = eB2 + ((size_t)e*CK_D + d)*16;
            h8f(bp, bv); h8f(bp + 8, bv + 8);
            #pragma unroll
            for (int r = 0; r < 16; r++) s += sv[e*16+r]*bv[r];
        }
        out[(size_t)t*CK_D + d] = s;
    }
}

// ---------------------------------------------------------------------------
// Launch
// ---------------------------------------------------------------------------
extern "C" void kernel_launch(void* const* d_in, const int* in_sizes, int n_in,
                              void* d_out, int out_size) {
    (void)in_sizes; (void)n_in; (void)out_size;
    const float* data  = (const float*)d_in[0];
    const float* rc    = (const float*)d_in[2];
    const float* rs    = (const float*)d_in[3];
    const float* att_w = (const float*)d_in[4];
    const float* ffn_w = (const float*)d_in[5];
    const float* wq    = (const float*)d_in[6];
    const float* wk    = (const float*)d_in[7];
    const float* wv    = (const float*)d_in[8];
    const float* wo    = (const float*)d_in[9];
    const float* lqA   = (const float*)d_in[10];
    const float* lqB   = (const float*)d_in[11];
    const float* lkA   = (const float*)d_in[12];
    const float* lkB   = (const float*)d_in[13];
    const float* lvA   = (const float*)d_in[14];
    const float* lvB   = (const float*)d_in[15];
    const float* loA   = (const float*)d_in[16];
    const float* loB   = (const float*)d_in[17];
    const float* w1    = (const float*)d_in[18];
    const float* w2    = (const float*)d_in[19];
    const float* w3    = (const float*)d_in[20];
    const float* gatew = (const float*)d_in[21];
    const float* eA1   = (const float*)d_in[22];
    const float* eB1   = (const float*)d_in[23];
    const float* eA2   = (const float*)d_in[24];
    const float* eB2   = (const float*)d_in[25];
    const float* eA3   = (const float*)d_in[26];
    const float* eB3   = (const float*)d_in[27];
    float* out = (float*)d_out;

    float *p_h,*p_hn,*p_sc,*p_d2,*p_uq,*p_uk,*p_uv,*p_uo;
    float *p_route,*p_ua1,*p_ua3,*p_v2,*p_fpre;
    cudaGetSymbolAddress((void**)&p_h,    g_h);
    cudaGetSymbolAddress((void**)&p_hn,   g_hn);
    cudaGetSymbolAddress((void**)&p_sc,   g_sc);
    cudaGetSymbolAddress((void**)&p_d2,   g_d2);
    cudaGetSymbolAddress((void**)&p_uq,   g_uq);
    cudaGetSymbolAddress((void**)&p_uk,   g_uk);
    cudaGetSymbolAddress((void**)&p_uv,   g_uv);
    cudaGetSymbolAddress((void**)&p_uo,   g_uo);
    cudaGetSymbolAddress((void**)&p_route,g_route);
    cudaGetSymbolAddress((void**)&p_ua1,  g_ua1);
    cudaGetSymbolAddress((void**)&p_ua3,  g_ua3);
    cudaGetSymbolAddress((void**)&p_v2,   g_v2);
    cudaGetSymbolAddress((void**)&p_fpre, g_fpre);

    __half *wqh,*wkh,*wvh,*woh,*w1h,*w3h,*w2h;
    __half *xh,*aoh,*hnh,*gsh,*xqh,*xkh,*xvh,*vth,*sch,*h1h,*h3h;
    __half *eB1h,*eB3h,*eA2h,*eB2h;
    cudaGetSymbolAddress((void**)&wqh, g_wqh);
    cudaGetSymbolAddress((void**)&wkh, g_wkh);
    cudaGetSymbolAddress((void**)&wvh, g_wvh);
    cudaGetSymbolAddress((void**)&woh, g_woh);
    cudaGetSymbolAddress((void**)&w1h, g_w1h);
    cudaGetSymbolAddress((void**)&w3h, g_w3h);
    cudaGetSymbolAddress((void**)&w2h, g_w2h);
    cudaGetSymbolAddress((void**)&xh,  g_xh);
    cudaGetSymbolAddress((void**)&aoh, g_aoh);
    cudaGetSymbolAddress((void**)&hnh, g_hnh);
    cudaGetSymbolAddress((void**)&gsh, g_gsh);
    cudaGetSymbolAddress((void**)&xqh, g_xqh);
    cudaGetSymbolAddress((void**)&xkh, g_xkh);
    cudaGetSymbolAddress((void**)&xvh, g_xvh);
    cudaGetSymbolAddress((void**)&vth, g_vth);
    cudaGetSymbolAddress((void**)&sch, g_sch);
    cudaGetSymbolAddress((void**)&h1h, g_h1h);
    cudaGetSymbolAddress((void**)&h3h, g_h3h);
    cudaGetSymbolAddress((void**)&eB1h, g_eB1h);
    cudaGetSymbolAddress((void**)&eB3h, g_eB3h);
    cudaGetSymbolAddress((void**)&eA2h, g_eA2h);
    cudaGetSymbolAddress((void**)&eB2h, g_eB2h);

    cudaFuncSetAttribute(k_hgemm4,   cudaFuncAttributeMaxDynamicSharedMemorySize, HG_SMEM);
    cudaFuncSetAttribute(k_scores_h, cudaFuncAttributeMaxDynamicSharedMemorySize, SC_SMEM);
    cudaFuncSetAttribute(k_avh,      cudaFuncAttributeMaxDynamicSharedMemorySize, AV_SMEM);

    // --- all weight conversions in one launch ---
    k_conv_all<<<(int)((CBT/8 + 255)/256),256>>>(
        wq, wk, wv, wo, w1, w3, w2, eB1, eB3, eA2, eB2,
        wqh, wkh, wvh, woh, w1h, w3h, w2h, eB1h, eB3h, eA2h, eB2h);

    // --- attention path ---
    k_rmsnorm<<<CK_T,256>>>(data, att_w, p_h, xh);
    k_lora_down3<<<CK_T,256>>>(p_h, lqA, lkA, lvA, p_uq, p_uk, p_uv);
    k_hgemm4<<<dim3(CK_D/128, CK_T/128),256,HG_SMEM>>>(xh, wqh, nullptr, xqh, CK_T, CK_D, CK_D, p_uq, 16, lqB, CK_LS, nullptr, rc, rs);
    k_hgemm4<<<dim3(512/128,  CK_T/128),256,HG_SMEM>>>(xh, wkh, nullptr, xkh, CK_T, 512,  CK_D, p_uk, 16, lkB, CK_LS, nullptr, rc, rs);
    k_hgemm4<<<dim3(512/128,  CK_T/128),256,HG_SMEM>>>(xh, wvh, nullptr, xvh, CK_T, 512,  CK_D, p_uv, 16, lvB, CK_LS, nullptr, nullptr, nullptr);
    k_vt<<<dim3(CK_S/32, CK_HD/32, CK_B*CK_KV),256>>>(xvh, vth);
    k_scores_h<<<dim3(CK_S/128, CK_S/128, CK_B*CK_H),256,SC_SMEM>>>(xqh, xkh, p_sc);
    k_softmax<<<CK_B*CK_H*CK_S,256>>>(p_sc, sch);
    k_avh<<<dim3(1, CK_S/128, CK_B*CK_H),256,AV_SMEM>>>(sch, vth, aoh);
    k_lora_down_h<<<CK_T,256>>>(aoh, loA, p_uo);
    k_hgemm4<<<dim3(CK_D/128, CK_T/128),256,HG_SMEM>>>(aoh, woh, p_d2, nullptr, CK_T, CK_D, CK_D, p_uo, 16, loB, CK_LS, data, nullptr, nullptr);

    // --- MoE path ---
    k_rmsnorm<<<CK_T,256>>>(p_d2, ffn_w, p_hn, hnh);
    k_gate<<<CK_T,256>>>(p_hn, gatew, p_route);
    k_expert_down<<<dim3(CK_T, CK_E),256>>>(p_hn, eA1, eA3, p_route, p_ua1, p_ua3);
    k_hgemm4<<<dim3(CK_FFN/128, CK_T/128),256,HG_SMEM>>>(hnh, w1h, nullptr, h1h, CK_T, CK_FFN, CK_D, nullptr, 0, nullptr, 0.f, nullptr, nullptr, nullptr);
    k_hgemm4<<<dim3(CK_FFN/128, CK_T/128),256,HG_SMEM>>>(hnh, w3h, nullptr, h3h, CK_T, CK_FFN, CK_D, nullptr, 0, nullptr, 0.f, nullptr, nullptr, nullptr);
    k_moe_expert<<<CK_T,256>>>(h1h, h3h, p_ua1, p_ua3, eB1h, eB3h, eA2h, p_route, gsh, p_v2);
    k_moe_up<<<CK_T,256>>>(p_d2, p_v2, eB2h, p_route, p_fpre);
    k_hgemm4<<<dim3(CK_D/128, CK_T/128),256,HG_SMEM>>>(gsh, w2h, out, nullptr, CK_T, CK_D, CK_FFN, nullptr, 0, nullptr, 0.f, p_fpre, nullptr, nullptr);
}

// round 14
// speedup vs baseline: 1.9823x; 1.0354x over previous
#include <cuda_runtime.h>
#include <cuda_fp16.h>
#include <math.h>
#include <stdint.h>

#define CK_B   4
#define CK_S   512
#define CK_D   2048
#define CK_H   16
#define CK_KV  4
#define CK_HD  128
#define CK_T   2048          // B*S
#define CK_FFN 5632
#define CK_E   8
#define CK_R   16
#define CK_LS  2.0f          // 32/16

// ---------------------------------------------------------------------------
// fp32 scratch
// ---------------------------------------------------------------------------
__device__ float g_h   [CK_T*CK_D];
__device__ float g_hn  [CK_T*CK_D];
__device__ float g_sc  [(size_t)CK_B*CK_H*CK_S*CK_S];
__device__ float g_d2  [CK_T*CK_D];
__device__ float g_uq  [CK_T*CK_R];
__device__ float g_uk  [CK_T*CK_R];
__device__ float g_uv  [CK_T*CK_R];
__device__ float g_uo  [CK_T*CK_R];
__device__ float g_route[CK_T*CK_E];
__device__ float g_ua1 [CK_T*CK_E*CK_R];
__device__ float g_ua3 [CK_T*CK_E*CK_R];
__device__ float g_v2  [CK_T*CK_E*CK_R];
__device__ float g_fpre[CK_T*CK_D];

// ---------------------------------------------------------------------------
// fp16 scratch
// ---------------------------------------------------------------------------
#define NWQ (CK_D*CK_D)
#define NWK (512*CK_D)
#define NW1 (CK_FFN*CK_D)
#define NEB (CK_E*CK_FFN*CK_R)
#define NB2 (CK_E*CK_D*CK_R)
__device__ __align__(16) __half g_wqh[NWQ];
__device__ __align__(16) __half g_wkh[NWK];
__device__ __align__(16) __half g_wvh[NWK];
__device__ __align__(16) __half g_woh[NWQ];
__device__ __align__(16) __half g_w1h[NW1];
__device__ __align__(16) __half g_w3h[NW1];
__device__ __align__(16) __half g_w2h[NW1];
__device__ __align__(16) __half g_xh [CK_T*CK_D];
__device__ __align__(16) __half g_aoh[CK_T*CK_D];
__device__ __align__(16) __half g_hnh[CK_T*CK_D];
__device__ __align__(16) __half g_gsh[(size_t)CK_T*CK_FFN];
__device__ __align__(16) __half g_xqh[CK_T*CK_D];
__device__ __align__(16) __half g_xkh[CK_T*CK_KV*CK_HD];
__device__ __align__(16) __half g_xvh[CK_T*CK_KV*CK_HD];
__device__ __align__(16) __half g_vth[CK_T*CK_KV*CK_HD];
__device__ __align__(16) __half g_sch[(size_t)CK_B*CK_H*CK_S*CK_S];
__device__ __align__(16) __half g_h1h[(size_t)CK_T*CK_FFN];
__device__ __align__(16) __half g_h3h[(size_t)CK_T*CK_FFN];
__device__ __align__(16) __half g_eB1h[NEB], g_eB3h[NEB], g_eA2h[NEB];
__device__ __align__(16) __half g_eB2h[NB2];

// ===========================================================================
// helpers
// ===========================================================================
__device__ __forceinline__ uint32_t smem_u32(const void* p) {
    uint32_t a;
    asm("{ .reg .u64 t; cvta.to.shared.u64 t, %1; cvt.u32.u64 %0, t; }" : "=r"(a) : "l"(p));
    return a;
}
#define CP_ASYNC16(dst_u32, src_ptr) \
    asm volatile("cp.async.cg.shared.global [%0], [%1], 16;" :: "r"(dst_u32), "l"(src_ptr))
#define CP_COMMIT() asm volatile("cp.async.commit_group;" ::: "memory")
#define CP_WAIT(n)  asm volatile("cp.async.wait_group %0;" :: "n"(n) : "memory")

__device__ __forceinline__ void mma16816(float* d, const uint32_t* a,
                                         uint32_t b0, uint32_t b1) {
    asm volatile(
        "mma.sync.aligned.m16n8k16.row.col.f32.f16.f16.f32 "
        "{%0,%1,%2,%3}, {%4,%5,%6,%7}, {%8,%9}, {%0,%1,%2,%3};"
        : "+f"(d[0]), "+f"(d[1]), "+f"(d[2]), "+f"(d[3])
        : "r"(a[0]), "r"(a[1]), "r"(a[2]), "r"(a[3]), "r"(b0), "r"(b1));
}

__device__ __forceinline__ void ldsm_x4(uint32_t& r0, uint32_t& r1,
                                        uint32_t& r2, uint32_t& r3, uint32_t addr) {
    asm volatile("ldmatrix.sync.aligned.m8n8.x4.shared.b16 {%0,%1,%2,%3}, [%4];"
        : "=r"(r0), "=r"(r1), "=r"(r2), "=r"(r3) : "r"(addr));
}

__device__ __forceinline__ void store4h(__half* p, float4 v) {
    *(__half2*)(p + 0) = __floats2half2_rn(v.x, v.y);
    *(__half2*)(p + 2) = __floats2half2_rn(v.z, v.w);
}

// MUFU-free e^x
__device__ __forceinline__ float fexp(float x) {
    float t = fminf(fmaxf(x * 1.4426950408889634f, -30.f), 30.f);
    float n = rintf(t);
    float f = t - n;
    float p = 1.f + f*(0.6931471806f + f*(0.2402265069f + f*(0.0555041087f
            + f*(0.0096181291f + f*0.0013333558f))));
    return __int_as_float(((int)n + 127) << 23) * p;
}

// ---------------------------------------------------------------------------
// k_conv_all: all fp32->fp16 weight conversions in ONE kernel
// ---------------------------------------------------------------------------
#define CB0 ((size_t)NWQ)
#define CB1 (CB0 + NWK)
#define CB2 (CB1 + NWK)
#define CB3 (CB2 + NWQ)
#define CB4 (CB3 + NW1)
#define CB5 (CB4 + NW1)
#define CB6 (CB5 + NW1)
#define CB7 (CB6 + NEB)
#define CB8 (CB7 + NEB)
#define CB9 (CB8 + NEB)
#define CBT (CB9 + NB2)

__global__ void k_conv_all(
    const float* s0, const float* s1, const float* s2, const float* s3,
    const float* s4, const float* s5, const float* s6, const float* s7,
    const float* s8, const float* s9, const float* s10,
    __half* d0, __half* d1, __half* d2, __half* d3, __half* d4, __half* d5,
    __half* d6, __half* d7, __half* d8, __half* d9, __half* d10)
{
    size_t i = ((size_t)blockIdx.x*256 + threadIdx.x)*8;
    if (i >= CBT) return;
    const float* s; __half* d; size_t off;
    if      (i < CB0) { s = s0;  d = d0;  off = i; }
    else if (i < CB1) { s = s1;  d = d1;  off = i - CB0; }
    else if (i < CB2) { s = s2;  d = d2;  off = i - CB1; }
    else if (i < CB3) { s = s3;  d = d3;  off = i - CB2; }
    else if (i < CB4) { s = s4;  d = d4;  off = i - CB3; }
    else if (i < CB5) { s = s5;  d = d5;  off = i - CB4; }
    else if (i < CB6) { s = s6;  d = d6;  off = i - CB5; }
    else if (i < CB7) { s = s7;  d = d7;  off = i - CB6; }
    else if (i < CB8) { s = s8;  d = d8;  off = i - CB7; }
    else if (i < CB9) { s = s9;  d = d9;  off = i - CB8; }
    else              { s = s10; d = d10; off = i - CB9; }
    store4h(d + off,     *(const float4*)(s + off));
    store4h(d + off + 4, *(const float4*)(s + off + 4));
}

// ===========================================================================
// k_hgemm4: 1-pass fp16 tensor-core GEMM, cp.async double-buffered, K-chunk 64
//   fragment loads via ldmatrix.x4
// ===========================================================================
#define HG_LD   72                   // 64 + 8 pad (ldmatrix conflict-free)
#define HG_TILE (128*HG_LD)
#define HG_TILEB (HG_TILE*2)
#define HG_SMEM (4*HG_TILEB)         // 73728 B

__global__ void __launch_bounds__(256, 2) k_hgemm4(
    const __half* __restrict__ A, const __half* __restrict__ W,
    float* __restrict__ C, __half* __restrict__ Ch, int M, int N, int K,
    const float* __restrict__ U, int ustride, const float* __restrict__ V,
    float lscale, const float* __restrict__ res,
    const float* __restrict__ rope_c, const float* __restrict__ rope_s)
{
    extern __shared__ __align__(16) __half sm[];
    __half* pA = sm;
    __half* pW = sm + 2*HG_TILE;
    const uint32_t sbA = smem_u32(sm);
    const uint32_t sbW = sbA + 2*HG_TILEB;

    const int tid  = threadIdx.x;
    const int wid  = tid >> 5, lane = tid & 31;
    const int g    = lane >> 2, tg = lane & 3;
    const int warpM = wid & 3;
    const int warpN = wid >> 2;
    const int bm = blockIdx.y * 128;
    const int bn = blockIdx.x * 128;

    // ldmatrix lane offsets (bytes)
    const int lt = lane >> 3, lr = lane & 7;
    const uint32_t offA = (uint32_t)((((lt & 1)*8 + lr)*HG_LD + (lt >> 1)*8) * 2);
    const uint32_t offB = (uint32_t)((((lt >> 1)*8 + lr)*HG_LD + (lt & 1)*8) * 2);
    const uint32_t rowA0 = (uint32_t)((warpM*32     )*HG_LD*2);
    const uint32_t rowA1 = (uint32_t)((warpM*32 + 16)*HG_LD*2);

    float acc[2][8][4];
    #pragma unroll
    for (int mi = 0; mi < 2; mi++)
        #pragma unroll
        for (int ni = 0; ni < 8; ni++)
            #pragma unroll
            for (int q = 0; q < 4; q++) acc[mi][ni][q] = 0.f;

    const int NC = K / 64;
    const int total = NC + (U ? 1 : 0);

    auto load_async = [&](int c, int buf) {
        const int k0 = c * 64;
        const uint32_t bo = (uint32_t)buf * HG_TILEB;
        #pragma unroll
        for (int it = 0; it < 4; it++) {
            int id = it*256 + tid;
            int r = id >> 3, sg = (id & 7) * 8;
            uint32_t so = bo + (uint32_t)(r*HG_LD + sg)*2;
            CP_ASYNC16(sbA + so, A + (size_t)(bm + r)*K + k0 + sg);
            CP_ASYNC16(sbW + so, W + (size_t)(bn + r)*K + k0 + sg);
        }
        CP_COMMIT();
    };

    auto load_lora = [&](int buf) {
        __half* dA = pA + buf*HG_TILE;
        __half* dW = pW + buf*HG_TILE;
        #pragma unroll
        for (int l = 0; l < 8; l++) {
            int id = l*256 + tid;
            int r = id >> 4, c4 = (id & 15)*4;
            float4 va = make_float4(0.f,0.f,0.f,0.f);
            float4 vw = make_float4(0.f,0.f,0.f,0.f);
            if (c4 < 16) {
                va = *(const float4*)(U + (size_t)(bm + r)*ustride + c4);
                va.x *= lscale; va.y *= lscale; va.z *= lscale; va.w *= lscale;
                vw = *(const float4*)(V + (size_t)(bn + r)*16 + c4);
            }
            store4h(dA + r*HG_LD + c4, va);
            store4h(dW + r*HG_LD + c4, vw);
        }
    };

    load_async(0, 0);

    for (int c = 0; c < total; c++) {
        const int cur = c & 1, nb = (c + 1) & 1;
        const bool have_next = (c + 1 < total);
        const bool next_async = (c + 1 < NC);
        if (have_next) {
            if (next_async) load_async(c + 1, nb);
            else            load_lora(nb);
        }
        if (c < NC) {
            if (have_next && next_async) { CP_WAIT(1); }
            else                         { CP_WAIT(0); }
        }
        __syncthreads();

        const uint32_t sA = sbA + (uint32_t)cur*HG_TILEB;
        const uint32_t sW = sbW + (uint32_t)cur*HG_TILEB;

        #pragma unroll
        for (int ks = 0; ks < 4; ks++) {
            const uint32_t colOff = (uint32_t)(ks*16*2);
            uint32_t a[2][4];
            ldsm_x4(a[0][0], a[0][1], a[0][2], a[0][3], sA + rowA0 + offA + colOff);
            ldsm_x4(a[1][0], a[1][1], a[1][2], a[1][3], sA + rowA1 + offA + colOff);
            #pragma unroll
            for (int np = 0; np < 4; np++) {
                uint32_t b00, b01, b10, b11;
                uint32_t rowB = (uint32_t)((warpN*64 + np*16)*HG_LD*2);
                ldsm_x4(b00, b01, b10, b11, sW + rowB + offB + colOff);
                #pragma unroll
                for (int mi = 0; mi < 2; mi++) {
                    mma16816(acc[mi][2*np],   a[mi], b00, b01);
                    mma16816(acc[mi][2*np+1], a[mi], b10, b11);
                }
            }
        }
        __syncthreads();
    }

    #pragma unroll
    for (int mi = 0; mi < 2; mi++) {
        size_t r0 = (size_t)(bm + warpM*32 + mi*16 + g);
        #pragma unroll
        for (int ni = 0; ni < 8; ni++) {
            size_t c0 = (size_t)(bn + warpN*64 + ni*8 + tg*2);
            if (Ch) {
                float o[4] = {acc[mi][ni][0], acc[mi][ni][1],
                              acc[mi][ni][2], acc[mi][ni][3]};
                if (rope_c) {
                    int d2 = ((int)c0 & 127) >> 1;
                    int sA2 = (int)r0 & (CK_S - 1);
                    int sB2 = (int)(r0 + 8) & (CK_S - 1);
                    float ca = rope_c[sA2*64 + d2], sa = rope_s[sA2*64 + d2];
                    float cb = rope_c[sB2*64 + d2], sb = rope_s[sB2*64 + d2];
                    float x1 = o[0], x2 = o[1];
                    o[0] = x1*ca - x2*sa; o[1] = x1*sa + x2*ca;
                    x1 = o[2]; x2 = o[3];
                    o[2] = x1*cb - x2*sb; o[3] = x1*sb + x2*cb;
                }
                *(__half2*)(Ch + r0*N + c0)     = __floats2half2_rn(o[0], o[1]);
                *(__half2*)(Ch + (r0+8)*N + c0) = __floats2half2_rn(o[2], o[3]);
            } else {
                float2 o0 = make_float2(acc[mi][ni][0], acc[mi][ni][1]);
                float2 o1 = make_float2(acc[mi][ni][2], acc[mi][ni][3]);
                if (res) {
                    float2 r0v = *(const float2*)(res + r0*N + c0);
                    float2 r1v = *(const float2*)(res + (r0+8)*N + c0);
                    o0.x += r0v.x; o0.y += r0v.y;
                    o1.x += r1v.x; o1.y += r1v.y;
                }
                *(float2*)(C + r0*N + c0)     = o0;
                *(float2*)(C + (r0+8)*N + c0) = o1;
            }
        }
    }
}

// ===========================================================================
// k_scores_h: scores = Q@K^T / sqrt(HD), ldmatrix fragments, causal tile skip
// ===========================================================================
#define SC_LD 136
#define SC_SMEM (2*128*SC_LD*2)

__global__ void __launch_bounds__(256) k_scores_h(const __half* __restrict__ q,
                                                  const __half* __restrict__ k,
                                                  float* __restrict__ sc) {
    const int t0 = blockIdx.x*128, s0 = blockIdx.y*128;
    if (t0 > s0) return;
    const int bh = blockIdx.z, b = bh >> 4, h = bh & 15, kv = h >> 2;
    extern __shared__ __align__(16) __half sm[];
    __half* Qs = sm;
    __half* Ks = sm + 128*SC_LD;
    const uint32_t sbQ = smem_u32(Qs);
    const uint32_t sbK = smem_u32(Ks);

    const int tid = threadIdx.x;
    const int wid = tid >> 5, lane = tid & 31;
    const int g = lane >> 2, tg = lane & 3;
    const int warpM = wid & 3, warpN = wid >> 2;
    const int lt = lane >> 3, lr = lane & 7;
    const uint32_t offA = (uint32_t)((((lt & 1)*8 + lr)*SC_LD + (lt >> 1)*8) * 2);
    const uint32_t offB = (uint32_t)((((lt >> 1)*8 + lr)*SC_LD + (lt & 1)*8) * 2);
    const uint32_t rowA0 = (uint32_t)((warpM*32     )*SC_LD*2);
    const uint32_t rowA1 = (uint32_t)((warpM*32 + 16)*SC_LD*2);

    #pragma unroll
    for (int it = 0; it < 8; it++) {
        int id = it*256 + tid;
        int r = id >> 4, c8 = (id & 15)*8;
        *(uint4*)(Qs + r*SC_LD + c8) =
            *(const uint4*)(q + ((size_t)(b*CK_S + s0 + r)*CK_D + h*CK_HD + c8));
        *(uint4*)(Ks + r*SC_LD + c8) =
            *(const uint4*)(k + ((size_t)(b*CK_S + t0 + r)*(CK_KV*CK_HD) + kv*CK_HD + c8));
    }
    __syncthreads();

    float acc[2][8][4];
    #pragma unroll
    for (int mi = 0; mi < 2; mi++)
        #pragma unroll
        for (int ni = 0; ni < 8; ni++)
            #pragma unroll
            for (int qq = 0; qq < 4; qq++) acc[mi][ni][qq] = 0.f;

    #pragma unroll
    for (int ks = 0; ks < 8; ks++) {
        const uint32_t colOff = (uint32_t)(ks*16*2);
        uint32_t a[2][4];
        ldsm_x4(a[0][0], a[0][1], a[0][2], a[0][3], sbQ + rowA0 + offA + colOff);
        ldsm_x4(a[1][0], a[1][1], a[1][2], a[1][3], sbQ + rowA1 + offA + colOff);
        #pragma unroll
        for (int np = 0; np < 4; np++) {
            uint32_t b00, b01, b10, b11;
            uint32_t rowB = (uint32_t)((warpN*64 + np*16)*SC_LD*2);
            ldsm_x4(b00, b01, b10, b11, sbK + rowB + offB + colOff);
            #pragma unroll
            for (int mi = 0; mi < 2; mi++) {
                mma16816(acc[mi][2*np],   a[mi], b00, b01);
                mma16816(acc[mi][2*np+1], a[mi], b10, b11);
            }
        }
    }

    const float scl = 0.08838834764831845f;
    float* out = sc + (size_t)bh*CK_S*CK_S;
    #pragma unroll
    for (int mi = 0; mi < 2; mi++) {
        size_t r0 = (size_t)(s0 + warpM*32 + mi*16 + g);
        #pragma unroll
        for (int ni = 0; ni < 8; ni++) {
            size_t c0 = (size_t)(t0 + warpN*64 + ni*8 + tg*2);
            *(float2*)(out + r0*CK_S + c0) =
                make_float2(acc[mi][ni][0]*scl, acc[mi][ni][1]*scl);
            *(float2*)(out + (r0+8)*CK_S + c0) =
                make_float2(acc[mi][ni][2]*scl, acc[mi][ni][3]*scl);
        }
    }
}

// ===========================================================================
// k_avh: out(fp16) = attn(fp16) @ V^T(fp16), ldmatrix fragments, causal K-bound
// ===========================================================================
#define AV_LD   40
#define AV_TILE (128*AV_LD)
#define AV_TILEB (AV_TILE*2)
#define AV_SMEM (4*AV_TILEB)

__global__ void __launch_bounds__(256, 2) k_avh(const __half* __restrict__ attn,
                                                const __half* __restrict__ vt,
                                                __half* __restrict__ outh) {
    extern __shared__ __align__(16) __half sm[];
    const uint32_t sbA = smem_u32(sm);
    const uint32_t sbW = sbA + 2*AV_TILEB;

    const int s0 = blockIdx.y * 128;
    const int bh = blockIdx.z, b = bh >> 4, h = bh & 15, kv = h >> 2;
    const __half* Ab = attn + (size_t)bh*CK_S*CK_S;
    const __half* Wb = vt + ((size_t)(b*CK_KV + kv)*CK_HD)*CK_S;

    const int tid = threadIdx.x;
    const int wid = tid >> 5, lane = tid & 31;
    const int g = lane >> 2, tg = lane & 3;
    const int warpM = wid & 3, warpN = wid >> 2;
    const int lt = lane >> 3, lr = lane & 7;
    const uint32_t offA = (uint32_t)((((lt & 1)*8 + lr)*AV_LD + (lt >> 1)*8) * 2);
    const uint32_t offB = (uint32_t)((((lt >> 1)*8 + lr)*AV_LD + (lt & 1)*8) * 2);
    const uint32_t rowA0 = (uint32_t)((warpM*32     )*AV_LD*2);
    const uint32_t rowA1 = (uint32_t)((warpM*32 + 16)*AV_LD*2);

    float acc[2][8][4];
    #pragma unroll
    for (int mi = 0; mi < 2; mi++)
        #pragma unroll
        for (int ni = 0; ni < 8; ni++)
            #pragma unroll
            for (int q = 0; q < 4; q++) acc[mi][ni][q] = 0.f;

    const int NC = (s0 + 128) / 32;

    auto load_async = [&](int c, int buf) {
        const int k0 = c * 32;
        const uint32_t bo = (uint32_t)buf * AV_TILEB;
        #pragma unroll
        for (int it = 0; it < 2; it++) {
            int id = it*256 + tid;
            int r = id >> 2, sg = (id & 3) * 8;
            uint32_t so = bo + (uint32_t)(r*AV_LD + sg)*2;
            CP_ASYNC16(sbA + so, Ab + (size_t)(s0 + r)*CK_S + k0 + sg);
            CP_ASYNC16(sbW + so, Wb + (size_t)r*CK_S + k0 + sg);
        }
        CP_COMMIT();
    };

    load_async(0, 0);
    for (int c = 0; c < NC; c++) {
        const int cur = c & 1;
        if (c + 1 < NC) { load_async(c + 1, (c+1)&1); CP_WAIT(1); }
        else            { CP_WAIT(0); }
        __syncthreads();

        const uint32_t sA = sbA + (uint32_t)cur*AV_TILEB;
        const uint32_t sW = sbW + (uint32_t)cur*AV_TILEB;
        #pragma unroll
        for (int ks = 0; ks < 2; ks++) {
            const uint32_t colOff = (uint32_t)(ks*16*2);
            uint32_t a[2][4];
            ldsm_x4(a[0][0], a[0][1], a[0][2], a[0][3], sA + rowA0 + offA + colOff);
            ldsm_x4(a[1][0], a[1][1], a[1][2], a[1][3], sA + rowA1 + offA + colOff);
            #pragma unroll
            for (int np = 0; np < 4; np++) {
                uint32_t b00, b01, b10, b11;
                uint32_t rowB = (uint32_t)((warpN*64 + np*16)*AV_LD*2);
                ldsm_x4(b00, b01, b10, b11, sW + rowB + offB + colOff);
                #pragma unroll
                for (int mi = 0; mi < 2; mi++) {
                    mma16816(acc[mi][2*np],   a[mi], b00, b01);
                    mma16816(acc[mi][2*np+1], a[mi], b10, b11);
                }
            }
        }
        __syncthreads();
    }

    #pragma unroll
    for (int mi = 0; mi < 2; mi++) {
        int s = s0 + warpM*32 + mi*16 + g;
        #pragma unroll
        for (int ni = 0; ni < 8; ni++) {
            int c0 = warpN*64 + ni*8 + tg*2;
            size_t off0 = ((size_t)(b*CK_S + s)*CK_H + h)*CK_HD + c0;
            size_t off1 = ((size_t)(b*CK_S + s + 8)*CK_H + h)*CK_HD + c0;
            *(__half2*)(outh + off0) = __floats2half2_rn(acc[mi][ni][0], acc[mi][ni][1]);
            *(__half2*)(outh + off1) = __floats2half2_rn(acc[mi][ni][2], acc[mi][ni][3]);
        }
    }
}

// ---------------------------------------------------------------------------
// k_vt: V fp16 [t][kv*HD] -> V^T fp16 [b][kv][hd][s]
// ---------------------------------------------------------------------------
__global__ void k_vt(const __half* __restrict__ xv, __half* __restrict__ vt) {
    int bkv = blockIdx.z, b = bkv >> 2, kv = bkv & 3;
    int s0 = blockIdx.x*32, h0 = blockIdx.y*32;
    __shared__ __half t[32][33];
    int x = threadIdx.x & 31, y = threadIdx.x >> 5;
    for (int i = y; i < 32; i += 8)
        t[i][x] = xv[(size_t)(b*CK_S + s0 + i)*(CK_KV*CK_HD) + kv*CK_HD + h0 + x];
    __syncthreads();
    for (int i = y; i < 32; i += 8)
        vt[((size_t)bkv*CK_HD + h0 + i)*CK_S + s0 + x] = t[x][i];
}

// ---------------------------------------------------------------------------
// RMSNorm (fp32 out + fp16 out)
// ---------------------------------------------------------------------------
__global__ void k_rmsnorm(const float* __restrict__ x, const float* __restrict__ w,
                          float* __restrict__ o, __half* __restrict__ oh) {
    int t = blockIdx.x;
    const float* xr = x + (size_t)t*CK_D;
    float ss = 0.f;
    for (int i = threadIdx.x; i < CK_D; i += 256) { float v = xr[i]; ss += v*v; }
    __shared__ float red[256];
    red[threadIdx.x] = ss; __syncthreads();
    for (int s = 128; s > 0; s >>= 1) {
        if (threadIdx.x < s) red[threadIdx.x] += red[threadIdx.x+s];
        __syncthreads();
    }
    float sc = rsqrtf(red[0]/(float)CK_D + 1e-5f);
    float* orow = o + (size_t)t*CK_D;
    __half* hrow = oh + (size_t)t*CK_D;
    for (int i = threadIdx.x; i < CK_D; i += 256) {
        float r = xr[i]*sc*w[i];
        orow[i] = r;
        hrow[i] = __float2half_rn(r);
    }
}

// ---------------------------------------------------------------------------
// Fused q/k/v LoRA downs (fp32 X)
// ---------------------------------------------------------------------------
__global__ void k_lora_down3(const float* __restrict__ X,
                             const float* __restrict__ A1, const float* __restrict__ A2,
                             const float* __restrict__ A3,
                             float* __restrict__ U1, float* __restrict__ U2,
                             float* __restrict__ U3) {
    int t = blockIdx.x;
    __shared__ float sx[CK_D];
    for (int i = threadIdx.x; i < CK_D; i += 256) sx[i] = X[(size_t)t*CK_D + i];
    __syncthreads();
    int w = threadIdx.x >> 5, lane = threadIdx.x & 31;
    for (int rr = w; rr < 48; rr += 8) {
        int m = rr >> 4, r = rr & 15;
        const float* ar = (m == 0 ? A1 : m == 1 ? A2 : A3) + (size_t)r*CK_D;
        float p = 0.f;
        for (int d = lane; d < CK_D; d += 32) p += sx[d]*ar[d];
        for (int o = 16; o; o >>= 1) p += __shfl_down_sync(0xffffffffu, p, o);
        if (lane == 0) (m == 0 ? U1 : m == 1 ? U2 : U3)[t*CK_R + r] = p;
    }
}

// LoRA down with fp16 X input
__global__ void k_lora_down_h(const __half* __restrict__ X, const float* __restrict__ A,
                              float* __restrict__ U) {
    int t = blockIdx.x;
    __shared__ float sx[CK_D];
    for (int i = threadIdx.x; i < CK_D; i += 256)
        sx[i] = __half2float(X[(size_t)t*CK_D + i]);
    __syncthreads();
    int w = threadIdx.x >> 5, lane = threadIdx.x & 31;
    for (int r = w; r < CK_R; r += 8) {
        const float* ar = A + (size_t)r*CK_D;
        float p = 0.f;
        for (int d = lane; d < CK_D; d += 32) p += sx[d]*ar[d];
        for (int o = 16; o; o >>= 1) p += __shfl_down_sync(0xffffffffu, p, o);
        if (lane == 0) U[t*CK_R + r] = p;
    }
}

// ---------------------------------------------------------------------------
// Causal softmax (MUFU-free exp): fp32 scores in, fp16 attn out
// ---------------------------------------------------------------------------
__global__ void k_softmax(const float* __restrict__ sc, __half* __restrict__ sch) {
    int row = blockIdx.x;
    int s = row & (CK_S - 1);
    const float* p = sc + (size_t)row*CK_S;
    __half* ph = sch + (size_t)row*CK_S;
    int L = s + 1;
    int tid = threadIdx.x;
    float v0 = (tid       < L) ? p[tid]       : -1e30f;
    float v1 = (tid + 256 < L) ? p[tid + 256] : -1e30f;
    __shared__ float red[256];
    red[tid] = fmaxf(v0, v1); __syncthreads();
    for (int st = 128; st; st >>= 1) {
        if (tid < st) red[tid] = fmaxf(red[tid], red[tid+st]);
        __syncthreads();
    }
    float m = red[0]; __syncthreads();
    float e0 = (tid       < L) ? fexp(v0 - m) : 0.f;
    float e1 = (tid + 256 < L) ? fexp(v1 - m) : 0.f;
    red[tid] = e0 + e1; __syncthreads();
    for (int st = 128; st; st >>= 1) {
        if (tid < st) red[tid] += red[tid+st];
        __syncthreads();
    }
    float inv = 1.f / red[0];
    ph[tid]       = __float2half_rn(e0 * inv);
    ph[tid + 256] = __float2half_rn(e1 * inv);
}

// ---------------------------------------------------------------------------
// Gate
// ---------------------------------------------------------------------------
__global__ void k_gate(const float* __restrict__ hn, const float* __restrict__ gw,
                       float* __restrict__ route) {
    int t = blockIdx.x;
    __shared__ float sl[8];
    int w = threadIdx.x >> 5, lane = threadIdx.x & 31;
    const float* xr = hn + (size_t)t*CK_D;
    const float* gr = gw + (size_t)w*CK_D;
    float p = 0.f;
    for (int d = lane; d < CK_D; d += 32) p += xr[d]*gr[d];
    for (int o = 16; o; o >>= 1) p += __shfl_down_sync(0xffffffffu, p, o);
    if (lane == 0) sl[w] = p;
    __syncthreads();
    if (threadIdx.x == 0) {
        int i0 = 0;
        for (int e = 1; e < 8; e++) if (sl[e] > sl[i0]) i0 = e;
        int i1 = -1;
        for (int e = 0; e < 8; e++) { if (e == i0) continue; if (i1 < 0 || sl[e] > sl[i1]) i1 = e; }
        float m = sl[i0];
        float v0 = expf(sl[i0]-m), v1 = expf(sl[i1]-m);
        float inv = 1.f/(v0+v1);
        float* rr = route + (size_t)t*CK_E;
        #pragma unroll
        for (int e = 0; e < 8; e++) rr[e] = 0.f;
        rr[i0] = v0*inv; rr[i1] = v1*inv;
    }
}

// ---------------------------------------------------------------------------
// Expert LoRA downs
// ---------------------------------------------------------------------------
__global__ void k_expert_down(const float* __restrict__ X, const float* __restrict__ A1,
                              const float* __restrict__ A3, const float* __restrict__ route,
                              float* __restrict__ U1, float* __restrict__ U3) {
    int t = blockIdx.x, e = blockIdx.y;
    if (route[t*CK_E + e] == 0.f) return;
    __shared__ float sx[CK_D];
    for (int i = threadIdx.x; i < CK_D; i += 256) sx[i] = X[(size_t)t*CK_D + i];
    __syncthreads();
    int w = threadIdx.x >> 5, lane = threadIdx.x & 31;
    const float* a1 = A1 + (size_t)e*CK_R*CK_D;
    const float* a3 = A3 + (size_t)e*CK_R*CK_D;
    for (int r = w; r < CK_R; r += 8) {
        float p1 = 0.f, p3 = 0.f;
        for (int d = lane; d < CK_D; d += 32) {
            float xv = sx[d];
            p1 += xv*a1[(size_t)r*CK_D + d];
            p3 += xv*a3[(size_t)r*CK_D + d];
        }
        for (int o = 16; o; o >>= 1) {
            p1 += __shfl_down_sync(0xffffffffu, p1, o);
            p3 += __shfl_down_sync(0xffffffffu, p3, o);
        }
        if (lane == 0) {
            U1[((size_t)t*CK_E + e)*CK_R + r] = p1;
            U3[((size_t)t*CK_E + e)*CK_R + r] = p3;
        }
    }
}

// ---------------------------------------------------------------------------
// Fused per-token MoE combine (fp16 h1/h3; fexp + paired rcp silu)
// ---------------------------------------------------------------------------
__device__ __forceinline__ void h8f(const __half* p, float* f) {
    uint4 q = *(const uint4*)p;
    const __half2* hp = (const __half2*)&q;
    #pragma unroll
    for (int j = 0; j < 4; j++) {
        float2 t = __half22float2(hp[j]);
        f[2*j] = t.x; f[2*j+1] = t.y;
    }
}

__global__ void __launch_bounds__(256) k_moe_expert(
    const __half* __restrict__ h1, const __half* __restrict__ h3,
    const float* __restrict__ ua1, const float* __restrict__ ua3,
    const __half* __restrict__ eB1, const __half* __restrict__ eB3,
    const __half* __restrict__ eA2, const float* __restrict__ route,
    __half* __restrict__ ghs, float* __restrict__ v2)
{
    const int t = blockIdx.x;
    const int tid = threadIdx.x;
    const int wid = tid >> 5, lane = tid & 31;
    const int NI = CK_FFN/256;   // 22
    float ghacc[CK_FFN/256];
    #pragma unroll
    for (int i = 0; i < NI; i++) ghacc[i] = 0.f;
    __shared__ float su1[16], su3[16];
    __shared__ float part[8][16];
    const __half* h1r = h1 + (size_t)t*CK_FFN;
    const __half* h3r = h3 + (size_t)t*CK_FFN;

    #pragma unroll 1
    for (int e = 0; e < CK_E; e++) {
        float wgt = route[t*CK_E + e];
        if (wgt == 0.f) {
            if (tid < 16) v2[(size_t)t*(CK_E*CK_R) + e*16 + tid] = 0.f;
            continue;
        }
        if (tid < 16) {
            su1[tid] = ua1[((size_t)t*CK_E + e)*16 + tid];
            su3[tid] = ua3[((size_t)t*CK_E + e)*16 + tid];
        }
        __syncthreads();
        float u1[16], u3[16];
        #pragma unroll
        for (int r = 0; r < 16; r++) { u1[r] = su1[r]; u3[r] = su3[r]; }
        float accr[16];
        #pragma unroll
        for (int r = 0; r < 16; r++) accr[r] = 0.f;
        const __half* B1 = eB1 + (size_t)e*CK_FFN*16;
        const __half* B3 = eB3 + (size_t)e*CK_FFN*16;
        const __half* A2 = eA2 + (size_t)e*16*CK_FFN;
        #pragma unroll 1
        for (int ii = 0; ii < NI; ii += 2) {
            float prod[2], esig[2];
            const int fA = ii*256 + tid, fB = fA + 256;
            #pragma unroll
            for (int hi = 0; hi < 2; hi++) {
                int f = hi ? fB : fA;
                float b1v[16], b3v[16];
                h8f(B1 + (size_t)f*16,     b1v);
                h8f(B1 + (size_t)f*16 + 8, b1v + 8);
                h8f(B3 + (size_t)f*16,     b3v);
                h8f(B3 + (size_t)f*16 + 8, b3v + 8);
                float b1 = 0.f, b3 = 0.f;
                #pragma unroll
                for (int r = 0; r < 16; r++) { b1 += u1[r]*b1v[r]; b3 += u3[r]*b3v[r]; }
                float g1 = __half2float(h1r[f]) + CK_LS*b1;
                float g3 = __half2float(h3r[f]) + CK_LS*b3;
                prod[hi] = g1*g3;
                esig[hi] = fexp(-g1);
            }
            float da = 1.f + esig[0], db = 1.f + esig[1];
            float rr;
            asm("rcp.approx.f32 %0, %1;" : "=f"(rr) : "f"(da*db));
            float gh[2];
            gh[0] = prod[0]*(rr*db);
            gh[1] = prod[1]*(rr*da);
            ghacc[ii]   += wgt*gh[0];
            ghacc[ii+1] += wgt*gh[1];
            #pragma unroll
            for (int hi = 0; hi < 2; hi++) {
                int f = hi ? fB : fA;
                #pragma unroll
                for (int r = 0; r < 16; r++)
                    accr[r] += gh[hi] * __half2float(A2[(size_t)r*CK_FFN + f]);
            }
        }
        #pragma unroll
        for (int r = 0; r < 16; r++) {
            float v = accr[r];
            #pragma unroll
            for (int o = 16; o; o >>= 1) v += __shfl_down_sync(0xffffffffu, v, o);
            if (lane == 0) part[wid][r] = v;
        }
        __syncthreads();
        if (tid < 16) {
            float s2 = 0.f;
            #pragma unroll
            for (int ww = 0; ww < 8; ww++) s2 += part[ww][tid];
            v2[(size_t)t*(CK_E*CK_R) + e*16 + tid] = wgt*CK_LS*s2;
        }
        __syncthreads();
    }
    __half* go = ghs + (size_t)t*CK_FFN;
    #pragma unroll
    for (int ii = 0; ii < NI; ii++) go[ii*256 + tid] = __float2half_rn(ghacc[ii]);
}

// ---------------------------------------------------------------------------
// fpre = data2 + v2 @ eB2^T
// ---------------------------------------------------------------------------
__global__ void k_moe_up(const float* __restrict__ d2, const float* __restrict__ v2,
                         const __half* __restrict__ eB2, const float* __restrict__ route,
                         float* __restrict__ out) {
    int t = blockIdx.x, tid = threadIdx.x;
    __shared__ float sv[128];
    __shared__ int act[8];
    if (tid < 128) sv[tid] = v2[(size_t)t*128 + tid];
    if (tid < 8)   act[tid] = (route[t*CK_E + tid] != 0.f) ? 1 : 0;
    __syncthreads();
    for (int d = tid; d < CK_D; d += 256) {
        float s = d2[(size_t)t*CK_D + d];
        #pragma unroll 1
        for (int e = 0; e < 8; e++) {
            if (!act[e]) continue;
            float bv[16];
            const __half* bp = eB2 + ((size_t)e*CK_D + d)*16;
            h8f(bp, bv); h8f(bp + 8, bv + 8);
            #pragma unroll
            for (int r = 0; r < 16; r++) s += sv[e*16+r]*bv[r];
        }
        out[(size_t)t*CK_D + d] = s;
    }
}

// ---------------------------------------------------------------------------
// Launch
// ---------------------------------------------------------------------------
extern "C" void kernel_launch(void* const* d_in, const int* in_sizes, int n_in,
                              void* d_out, int out_size) {
    (void)in_sizes; (void)n_in; (void)out_size;
    const float* data  = (const float*)d_in[0];
    const float* rc    = (const float*)d_in[2];
    const float* rs    = (const float*)d_in[3];
    const float* att_w = (const float*)d_in[4];
    const float* ffn_w = (const float*)d_in[5];
    const float* wq    = (const float*)d_in[6];
    const float* wk    = (const float*)d_in[7];
    const float* wv    = (const float*)d_in[8];
    const float* wo    = (const float*)d_in[9];
    const float* lqA   = (const float*)d_in[10];
    const float* lqB   = (const float*)d_in[11];
    const float* lkA   = (const float*)d_in[12];
    const float* lkB   = (const float*)d_in[13];
    const float* lvA   = (const float*)d_in[14];
    const float* lvB   = (const float*)d_in[15];
    const float* loA   = (const float*)d_in[16];
    const float* loB   = (const float*)d_in[17];
    const float* w1    = (const float*)d_in[18];
    const float* w2    = (const float*)d_in[19];
    const float* w3    = (const float*)d_in[20];
    const float* gatew = (const float*)d_in[21];
    const float* eA1   = (const float*)d_in[22];
    const float* eB1   = (const float*)d_in[23];
    const float* eA2   = (const float*)d_in[24];
    const float* eB2   = (const float*)d_in[25];
    const float* eA3   = (const float*)d_in[26];
    const float* eB3   = (const float*)d_in[27];
    float* out = (float*)d_out;

    float *p_h,*p_hn,*p_sc,*p_d2,*p_uq,*p_uk,*p_uv,*p_uo;
    float *p_route,*p_ua1,*p_ua3,*p_v2,*p_fpre;
    cudaGetSymbolAddress((void**)&p_h,    g_h);
    cudaGetSymbolAddress((void**)&p_hn,   g_hn);
    cudaGetSymbolAddress((void**)&p_sc,   g_sc);
    cudaGetSymbolAddress((void**)&p_d2,   g_d2);
    cudaGetSymbolAddress((void**)&p_uq,   g_uq);
    cudaGetSymbolAddress((void**)&p_uk,   g_uk);
    cudaGetSymbolAddress((void**)&p_uv,   g_uv);
    cudaGetSymbolAddress((void**)&p_uo,   g_uo);
    cudaGetSymbolAddress((void**)&p_route,g_route);
    cudaGetSymbolAddress((void**)&p_ua1,  g_ua1);
    cudaGetSymbolAddress((void**)&p_ua3,  g_ua3);
    cudaGetSymbolAddress((void**)&p_v2,   g_v2);
    cudaGetSymbolAddress((void**)&p_fpre, g_fpre);

    __half *wqh,*wkh,*wvh,*woh,*w1h,*w3h,*w2h;
    __half *xh,*aoh,*hnh,*gsh,*xqh,*xkh,*xvh,*vth,*sch,*h1h,*h3h;
    __half *eB1h,*eB3h,*eA2h,*eB2h;
    cudaGetSymbolAddress((void**)&wqh, g_wqh);
    cudaGetSymbolAddress((void**)&wkh, g_wkh);
    cudaGetSymbolAddress((void**)&wvh, g_wvh);
    cudaGetSymbolAddress((void**)&woh, g_woh);
    cudaGetSymbolAddress((void**)&w1h, g_w1h);
    cudaGetSymbolAddress((void**)&w3h, g_w3h);
    cudaGetSymbolAddress((void**)&w2h, g_w2h);
    cudaGetSymbolAddress((void**)&xh,  g_xh);
    cudaGetSymbolAddress((void**)&aoh, g_aoh);
    cudaGetSymbolAddress((void**)&hnh, g_hnh);
    cudaGetSymbolAddress((void**)&gsh, g_gsh);
    cudaGetSymbolAddress((void**)&xqh, g_xqh);
    cudaGetSymbolAddress((void**)&xkh, g_xkh);
    cudaGetSymbolAddress((void**)&xvh, g_xvh);
    cudaGetSymbolAddress((void**)&vth, g_vth);
    cudaGetSymbolAddress((void**)&sch, g_sch);
    cudaGetSymbolAddress((void**)&h1h, g_h1h);
    cudaGetSymbolAddress((void**)&h3h, g_h3h);
    cudaGetSymbolAddress((void**)&eB1h, g_eB1h);
    cudaGetSymbolAddress((void**)&eB3h, g_eB3h);
    cudaGetSymbolAddress((void**)&eA2h, g_eA2h);
    cudaGetSymbolAddress((void**)&eB2h, g_eB2h);

    cudaFuncSetAttribute(k_hgemm4,   cudaFuncAttributeMaxDynamicSharedMemorySize, HG_SMEM);
    cudaFuncSetAttribute(k_scores_h, cudaFuncAttributeMaxDynamicSharedMemorySize, SC_SMEM);
    cudaFuncSetAttribute(k_avh,      cudaFuncAttributeMaxDynamicSharedMemorySize, AV_SMEM);

    // --- all weight conversions in one launch ---
    k_conv_all<<<(int)((CBT/8 + 255)/256),256>>>(
        wq, wk, wv, wo, w1, w3, w2, eB1, eB3, eA2, eB2,
        wqh, wkh, wvh, woh, w1h, w3h, w2h, eB1h, eB3h, eA2h, eB2h);

    // --- attention path ---
    k_rmsnorm<<<CK_T,256>>>(data, att_w, p_h, xh);
    k_lora_down3<<<CK_T,256>>>(p_h, lqA, lkA, lvA, p_uq, p_uk, p_uv);
    k_hgemm4<<<dim3(CK_D/128, CK_T/128),256,HG_SMEM>>>(xh, wqh, nullptr, xqh, CK_T, CK_D, CK_D, p_uq, 16, lqB, CK_LS, nullptr, rc, rs);
    k_hgemm4<<<dim3(512/128,  CK_T/128),256,HG_SMEM>>>(xh, wkh, nullptr, xkh, CK_T, 512,  CK_D, p_uk, 16, lkB, CK_LS, nullptr, rc, rs);
    k_hgemm4<<<dim3(512/128,  CK_T/128),256,HG_SMEM>>>(xh, wvh, nullptr, xvh, CK_T, 512,  CK_D, p_uv, 16, lvB, CK_LS, nullptr, nullptr, nullptr);
    k_vt<<<dim3(CK_S/32, CK_HD/32, CK_B*CK_KV),256>>>(xvh, vth);
    k_scores_h<<<dim3(CK_S/128, CK_S/128, CK_B*CK_H),256,SC_SMEM>>>(xqh, xkh, p_sc);
    k_softmax<<<CK_B*CK_H*CK_S,256>>>(p_sc, sch);
    k_avh<<<dim3(1, CK_S/128, CK_B*CK_H),256,AV_SMEM>>>(sch, vth, aoh);
    k_lora_down_h<<<CK_T,256>>>(aoh, loA, p_uo);
    k_hgemm4<<<dim3(CK_D/128, CK_T/128),256,HG_SMEM>>>(aoh, woh, p_d2, nullptr, CK_T, CK_D, CK_D, p_uo, 16, loB, CK_LS, data, nullptr, nullptr);

    // --- MoE path ---
    k_rmsnorm<<<CK_T,256>>>(p_d2, ffn_w, p_hn, hnh);
    k_gate<<<CK_T,256>>>(p_hn, gatew, p_route);
    k_expert_down<<<dim3(CK_T, CK_E),256>>>(p_hn, eA1, eA3, p_route, p_ua1, p_ua3);
    k_hgemm4<<<dim3(CK_FFN/128, CK_T/128),256,HG_SMEM>>>(hnh, w1h, nullptr, h1h, CK_T, CK_FFN, CK_D, nullptr, 0, nullptr, 0.f, nullptr, nullptr, nullptr);
    k_hgemm4<<<dim3(CK_FFN/128, CK_T/128),256,HG_SMEM>>>(hnh, w3h, nullptr, h3h, CK_T, CK_FFN, CK_D, nullptr, 0, nullptr, 0.f, nullptr, nullptr, nullptr);
    k_moe_expert<<<CK_T,256>>>(h1h, h3h, p_ua1, p_ua3, eB1h, eB3h, eA2h, p_route, gsh, p_v2);
    k_moe_up<<<CK_T,256>>>(p_d2, p_v2, eB2h, p_route, p_fpre);
    k_hgemm4<<<dim3(CK_D/128, CK_T/128),256,HG_SMEM>>>(gsh, w2h, out, nullptr, CK_T, CK_D, CK_FFN, nullptr, 0, nullptr, 0.f, p_fpre, nullptr, nullptr);
}

// round 16
// speedup vs baseline: 2.0702x; 1.0443x over previous
#include <cuda_runtime.h>
#include <cuda_fp16.h>
#include <math.h>
#include <stdint.h>

#define CK_B   4
#define CK_S   512
#define CK_D   2048
#define CK_H   16
#define CK_KV  4
#define CK_HD  128
#define CK_T   2048          // B*S
#define CK_FFN 5632
#define CK_E   8
#define CK_R   16
#define CK_LS  2.0f          // 32/16

// ---------------------------------------------------------------------------
// fp32 scratch
// ---------------------------------------------------------------------------
__device__ float g_h   [CK_T*CK_D];
__device__ float g_hn  [CK_T*CK_D];
__device__ float g_sc  [(size_t)CK_B*CK_H*CK_S*CK_S];
__device__ float g_d2  [CK_T*CK_D];
__device__ float g_uq  [CK_T*CK_R];
__device__ float g_uk  [CK_T*CK_R];
__device__ float g_uv  [CK_T*CK_R];
__device__ float g_uo  [CK_T*CK_R];
__device__ float g_route[CK_T*CK_E];
__device__ float g_ua1 [CK_T*CK_E*CK_R];
__device__ float g_ua3 [CK_T*CK_E*CK_R];
__device__ float g_v2  [CK_T*CK_E*CK_R];
__device__ float g_fpre[CK_T*CK_D];

// ---------------------------------------------------------------------------
// fp16 scratch
// ---------------------------------------------------------------------------
#define NWQ (CK_D*CK_D)
#define NWK (512*CK_D)
#define NW1 (CK_FFN*CK_D)
#define NEB (CK_E*CK_FFN*CK_R)
#define NB2 (CK_E*CK_D*CK_R)
__device__ __align__(16) __half g_wqh[NWQ];
__device__ __align__(16) __half g_wkh[NWK];
__device__ __align__(16) __half g_wvh[NWK];
__device__ __align__(16) __half g_woh[NWQ];
__device__ __align__(16) __half g_w1h[NW1];
__device__ __align__(16) __half g_w3h[NW1];
__device__ __align__(16) __half g_w2h[NW1];
__device__ __align__(16) __half g_xh [CK_T*CK_D];
__device__ __align__(16) __half g_aoh[CK_T*CK_D];
__device__ __align__(16) __half g_hnh[CK_T*CK_D];
__device__ __align__(16) __half g_gsh[(size_t)CK_T*CK_FFN];
__device__ __align__(16) __half g_xqh[CK_T*CK_D];
__device__ __align__(16) __half g_xkh[CK_T*CK_KV*CK_HD];
__device__ __align__(16) __half g_xvh[CK_T*CK_KV*CK_HD];
__device__ __align__(16) __half g_vth[CK_T*CK_KV*CK_HD];
__device__ __align__(16) __half g_sch[(size_t)CK_B*CK_H*CK_S*CK_S];
__device__ __align__(16) __half g_h1h[(size_t)CK_T*CK_FFN];
__device__ __align__(16) __half g_h3h[(size_t)CK_T*CK_FFN];
__device__ __align__(16) __half g_eB1h[NEB], g_eB3h[NEB], g_eA2h[NEB];
__device__ __align__(16) __half g_eB2h[NB2];

// ===========================================================================
// helpers
// ===========================================================================
__device__ __forceinline__ uint32_t smem_u32(const void* p) {
    uint32_t a;
    asm("{ .reg .u64 t; cvta.to.shared.u64 t, %1; cvt.u32.u64 %0, t; }" : "=r"(a) : "l"(p));
    return a;
}
#define CP_ASYNC16(dst_u32, src_ptr) \
    asm volatile("cp.async.cg.shared.global [%0], [%1], 16;" :: "r"(dst_u32), "l"(src_ptr))
#define CP_COMMIT() asm volatile("cp.async.commit_group;" ::: "memory")
#define CP_WAIT(n)  asm volatile("cp.async.wait_group %0;" :: "n"(n) : "memory")

__device__ __forceinline__ void mma16816(float* d, const uint32_t* a,
                                         uint32_t b0, uint32_t b1) {
    asm volatile(
        "mma.sync.aligned.m16n8k16.row.col.f32.f16.f16.f32 "
        "{%0,%1,%2,%3}, {%4,%5,%6,%7}, {%8,%9}, {%0,%1,%2,%3};"
        : "+f"(d[0]), "+f"(d[1]), "+f"(d[2]), "+f"(d[3])
        : "r"(a[0]), "r"(a[1]), "r"(a[2]), "r"(a[3]), "r"(b0), "r"(b1));
}

__device__ __forceinline__ void ldsm_x4(uint32_t& r0, uint32_t& r1,
                                        uint32_t& r2, uint32_t& r3, uint32_t addr) {
    asm volatile("ldmatrix.sync.aligned.m8n8.x4.shared.b16 {%0,%1,%2,%3}, [%4];"
        : "=r"(r0), "=r"(r1), "=r"(r2), "=r"(r3) : "r"(addr));
}

__device__ __forceinline__ void store4h(__half* p, float4 v) {
    *(__half2*)(p + 0) = __floats2half2_rn(v.x, v.y);
    *(__half2*)(p + 2) = __floats2half2_rn(v.z, v.w);
}

// MUFU-free e^x
__device__ __forceinline__ float fexp(float x) {
    float t = fminf(fmaxf(x * 1.4426950408889634f, -30.f), 30.f);
    float n = rintf(t);
    float f = t - n;
    float p = 1.f + f*(0.6931471806f + f*(0.2402265069f + f*(0.0555041087f
            + f*(0.0096181291f + f*0.0013333558f))));
    return __int_as_float(((int)n + 127) << 23) * p;
}

// ---------------------------------------------------------------------------
// k_conv_all: all fp32->fp16 weight conversions in ONE kernel
// ---------------------------------------------------------------------------
#define CB0 ((size_t)NWQ)
#define CB1 (CB0 + NWK)
#define CB2 (CB1 + NWK)
#define CB3 (CB2 + NWQ)
#define CB4 (CB3 + NW1)
#define CB5 (CB4 + NW1)
#define CB6 (CB5 + NW1)
#define CB7 (CB6 + NEB)
#define CB8 (CB7 + NEB)
#define CB9 (CB8 + NEB)
#define CBT (CB9 + NB2)

__global__ void k_conv_all(
    const float* s0, const float* s1, const float* s2, const float* s3,
    const float* s4, const float* s5, const float* s6, const float* s7,
    const float* s8, const float* s9, const float* s10,
    __half* d0, __half* d1, __half* d2, __half* d3, __half* d4, __half* d5,
    __half* d6, __half* d7, __half* d8, __half* d9, __half* d10)
{
    size_t i = ((size_t)blockIdx.x*256 + threadIdx.x)*8;
    if (i >= CBT) return;
    const float* s; __half* d; size_t off;
    if      (i < CB0) { s = s0;  d = d0;  off = i; }
    else if (i < CB1) { s = s1;  d = d1;  off = i - CB0; }
    else if (i < CB2) { s = s2;  d = d2;  off = i - CB1; }
    else if (i < CB3) { s = s3;  d = d3;  off = i - CB2; }
    else if (i < CB4) { s = s4;  d = d4;  off = i - CB3; }
    else if (i < CB5) { s = s5;  d = d5;  off = i - CB4; }
    else if (i < CB6) { s = s6;  d = d6;  off = i - CB5; }
    else if (i < CB7) { s = s7;  d = d7;  off = i - CB6; }
    else if (i < CB8) { s = s8;  d = d8;  off = i - CB7; }
    else if (i < CB9) { s = s9;  d = d9;  off = i - CB8; }
    else              { s = s10; d = d10; off = i - CB9; }
    store4h(d + off,     *(const float4*)(s + off));
    store4h(d + off + 4, *(const float4*)(s + off + 4));
}

// ===========================================================================
// k_hgemm4: 1-pass fp16 tensor-core GEMM, 3-stage cp.async pipeline, K-chunk 64
//   fragment loads via ldmatrix.x4
// ===========================================================================
#define HG_LD   72                   // 64 + 8 pad
#define HG_TILE (128*HG_LD)
#define HG_TILEB (HG_TILE*2)         // 18432 B
#define HG_ST   3                    // pipeline stages
#define HG_SMEM (HG_ST*2*HG_TILEB)   // 110592 B (2 CTAs -> 216 KB/SM)

__global__ void __launch_bounds__(256, 2) k_hgemm4(
    const __half* __restrict__ A, const __half* __restrict__ W,
    float* __restrict__ C, __half* __restrict__ Ch, int M, int N, int K,
    const float* __restrict__ U, int ustride, const float* __restrict__ V,
    float lscale, const float* __restrict__ res,
    const float* __restrict__ rope_c, const float* __restrict__ rope_s)
{
    extern __shared__ __align__(16) __half sm[];
    __half* pA = sm;                           // HG_ST bufs
    __half* pW = sm + HG_ST*HG_TILE;           // HG_ST bufs
    const uint32_t sbA = smem_u32(sm);
    const uint32_t sbW = sbA + HG_ST*HG_TILEB;

    const int tid  = threadIdx.x;
    const int wid  = tid >> 5, lane = tid & 31;
    const int g    = lane >> 2, tg = lane & 3;
    const int warpM = wid & 3;
    const int warpN = wid >> 2;
    const int bm = blockIdx.y * 128;
    const int bn = blockIdx.x * 128;

    const int lt = lane >> 3, lr = lane & 7;
    const uint32_t offA = (uint32_t)((((lt & 1)*8 + lr)*HG_LD + (lt >> 1)*8) * 2);
    const uint32_t offB = (uint32_t)((((lt >> 1)*8 + lr)*HG_LD + (lt & 1)*8) * 2);
    const uint32_t rowA0 = (uint32_t)((warpM*32     )*HG_LD*2);
    const uint32_t rowA1 = (uint32_t)((warpM*32 + 16)*HG_LD*2);

    float acc[2][8][4];
    #pragma unroll
    for (int mi = 0; mi < 2; mi++)
        #pragma unroll
        for (int ni = 0; ni < 8; ni++)
            #pragma unroll
            for (int q = 0; q < 4; q++) acc[mi][ni][q] = 0.f;

    const int NC = K / 64;
    const int total = NC + (U ? 1 : 0);

    auto load_async = [&](int c, int buf) {
        const int k0 = c * 64;
        const uint32_t bo = (uint32_t)buf * HG_TILEB;
        #pragma unroll
        for (int it = 0; it < 4; it++) {
            int id = it*256 + tid;
            int r = id >> 3, sg = (id & 7) * 8;
            uint32_t so = bo + (uint32_t)(r*HG_LD + sg)*2;
            CP_ASYNC16(sbA + so, A + (size_t)(bm + r)*K + k0 + sg);
            CP_ASYNC16(sbW + so, W + (size_t)(bn + r)*K + k0 + sg);
        }
        CP_COMMIT();
    };

    auto load_lora = [&](int buf) {
        __half* dA = pA + buf*HG_TILE;
        __half* dW = pW + buf*HG_TILE;
        #pragma unroll
        for (int l = 0; l < 8; l++) {
            int id = l*256 + tid;
            int r = id >> 4, c4 = (id & 15)*4;
            float4 va = make_float4(0.f,0.f,0.f,0.f);
            float4 vw = make_float4(0.f,0.f,0.f,0.f);
            if (c4 < 16) {
                va = *(const float4*)(U + (size_t)(bm + r)*ustride + c4);
                va.x *= lscale; va.y *= lscale; va.z *= lscale; va.w *= lscale;
                vw = *(const float4*)(V + (size_t)(bn + r)*16 + c4);
            }
            store4h(dA + r*HG_LD + c4, va);
            store4h(dW + r*HG_LD + c4, vw);
        }
    };

    // prologue: fill HG_ST-1 stages (K>=128 so both are regular async chunks)
    #pragma unroll
    for (int p = 0; p < HG_ST - 1; p++)
        if (p < NC) load_async(p, p % HG_ST);

    for (int c = 0; c < total; c++) {
        const int cur = c % HG_ST;
        const int nx = c + HG_ST - 1;
        bool lora_pending = false;
        if (nx < total) {
            if (nx < NC) load_async(nx, nx % HG_ST);
            else         lora_pending = true;   // fill after barrier (smem write)
        }
        if (c < NC) {
            if (nx < NC)        { CP_WAIT(HG_ST - 1); }  // groups nx, nx-1 may remain
            else if (c < NC-1)  { CP_WAIT(1); }          // group c+1 may remain
            else                { CP_WAIT(0); }
        }
        __syncthreads();
        if (lora_pending) {
            load_lora(nx % HG_ST);
            // consumed after the NEXT iteration's __syncthreads()
        }

        const uint32_t sA = sbA + (uint32_t)cur*HG_TILEB;
        const uint32_t sW = sbW + (uint32_t)cur*HG_TILEB;

        #pragma unroll
        for (int ks = 0; ks < 4; ks++) {
            const uint32_t colOff = (uint32_t)(ks*16*2);
            uint32_t a[2][4];
            ldsm_x4(a[0][0], a[0][1], a[0][2], a[0][3], sA + rowA0 + offA + colOff);
            ldsm_x4(a[1][0], a[1][1], a[1][2], a[1][3], sA + rowA1 + offA + colOff);
            #pragma unroll
            for (int np = 0; np < 4; np++) {
                uint32_t b00, b01, b10, b11;
                uint32_t rowB = (uint32_t)((warpN*64 + np*16)*HG_LD*2);
                ldsm_x4(b00, b01, b10, b11, sW + rowB + offB + colOff);
                #pragma unroll
                for (int mi = 0; mi < 2; mi++) {
                    mma16816(acc[mi][2*np],   a[mi], b00, b01);
                    mma16816(acc[mi][2*np+1], a[mi], b10, b11);
                }
            }
        }
        __syncthreads();
    }

    #pragma unroll
    for (int mi = 0; mi < 2; mi++) {
        size_t r0 = (size_t)(bm + warpM*32 + mi*16 + g);
        #pragma unroll
        for (int ni = 0; ni < 8; ni++) {
            size_t c0 = (size_t)(bn + warpN*64 + ni*8 + tg*2);
            if (Ch) {
                float o[4] = {acc[mi][ni][0], acc[mi][ni][1],
                              acc[mi][ni][2], acc[mi][ni][3]};
                if (rope_c) {
                    int d2 = ((int)c0 & 127) >> 1;
                    int sA2 = (int)r0 & (CK_S - 1);
                    int sB2 = (int)(r0 + 8) & (CK_S - 1);
                    float ca = rope_c[sA2*64 + d2], sa = rope_s[sA2*64 + d2];
                    float cb = rope_c[sB2*64 + d2], sb = rope_s[sB2*64 + d2];
                    float x1 = o[0], x2 = o[1];
                    o[0] = x1*ca - x2*sa; o[1] = x1*sa + x2*ca;
                    x1 = o[2]; x2 = o[3];
                    o[2] = x1*cb - x2*sb; o[3] = x1*sb + x2*cb;
                }
                *(__half2*)(Ch + r0*N + c0)     = __floats2half2_rn(o[0], o[1]);
                *(__half2*)(Ch + (r0+8)*N + c0) = __floats2half2_rn(o[2], o[3]);
            } else {
                float2 o0 = make_float2(acc[mi][ni][0], acc[mi][ni][1]);
                float2 o1 = make_float2(acc[mi][ni][2], acc[mi][ni][3]);
                if (res) {
                    float2 r0v = *(const float2*)(res + r0*N + c0);
                    float2 r1v = *(const float2*)(res + (r0+8)*N + c0);
                    o0.x += r0v.x; o0.y += r0v.y;
                    o1.x += r1v.x; o1.y += r1v.y;
                }
                *(float2*)(C + r0*N + c0)     = o0;
                *(float2*)(C + (r0+8)*N + c0) = o1;
            }
        }
    }
}

// ===========================================================================
// k_scores_h: scores = Q@K^T / sqrt(HD), ldmatrix fragments, causal tile skip
// ===========================================================================
#define SC_LD 136
#define SC_SMEM (2*128*SC_LD*2)

__global__ void __launch_bounds__(256) k_scores_h(const __half* __restrict__ q,
                                                  const __half* __restrict__ k,
                                                  float* __restrict__ sc) {
    const int t0 = blockIdx.x*128, s0 = blockIdx.y*128;
    if (t0 > s0) return;
    const int bh = blockIdx.z, b = bh >> 4, h = bh & 15, kv = h >> 2;
    extern __shared__ __align__(16) __half sm[];
    __half* Qs = sm;
    __half* Ks = sm + 128*SC_LD;
    const uint32_t sbQ = smem_u32(Qs);
    const uint32_t sbK = smem_u32(Ks);

    const int tid = threadIdx.x;
    const int wid = tid >> 5, lane = tid & 31;
    const int g = lane >> 2, tg = lane & 3;
    const int warpM = wid & 3, warpN = wid >> 2;
    const int lt = lane >> 3, lr = lane & 7;
    const uint32_t offA = (uint32_t)((((lt & 1)*8 + lr)*SC_LD + (lt >> 1)*8) * 2);
    const uint32_t offB = (uint32_t)((((lt >> 1)*8 + lr)*SC_LD + (lt & 1)*8) * 2);
    const uint32_t rowA0 = (uint32_t)((warpM*32     )*SC_LD*2);
    const uint32_t rowA1 = (uint32_t)((warpM*32 + 16)*SC_LD*2);

    #pragma unroll
    for (int it = 0; it < 8; it++) {
        int id = it*256 + tid;
        int r = id >> 4, c8 = (id & 15)*8;
        *(uint4*)(Qs + r*SC_LD + c8) =
            *(const uint4*)(q + ((size_t)(b*CK_S + s0 + r)*CK_D + h*CK_HD + c8));
        *(uint4*)(Ks + r*SC_LD + c8) =
            *(const uint4*)(k + ((size_t)(b*CK_S + t0 + r)*(CK_KV*CK_HD) + kv*CK_HD + c8));
    }
    __syncthreads();

    float acc[2][8][4];
    #pragma unroll
    for (int mi = 0; mi < 2; mi++)
        #pragma unroll
        for (int ni = 0; ni < 8; ni++)
            #pragma unroll
            for (int qq = 0; qq < 4; qq++) acc[mi][ni][qq] = 0.f;

    #pragma unroll
    for (int ks = 0; ks < 8; ks++) {
        const uint32_t colOff = (uint32_t)(ks*16*2);
        uint32_t a[2][4];
        ldsm_x4(a[0][0], a[0][1], a[0][2], a[0][3], sbQ + rowA0 + offA + colOff);
        ldsm_x4(a[1][0], a[1][1], a[1][2], a[1][3], sbQ + rowA1 + offA + colOff);
        #pragma unroll
        for (int np = 0; np < 4; np++) {
            uint32_t b00, b01, b10, b11;
            uint32_t rowB = (uint32_t)((warpN*64 + np*16)*SC_LD*2);
            ldsm_x4(b00, b01, b10, b11, sbK + rowB + offB + colOff);
            #pragma unroll
            for (int mi = 0; mi < 2; mi++) {
                mma16816(acc[mi][2*np],   a[mi], b00, b01);
                mma16816(acc[mi][2*np+1], a[mi], b10, b11);
            }
        }
    }

    const float scl = 0.08838834764831845f;
    float* out = sc + (size_t)bh*CK_S*CK_S;
    #pragma unroll
    for (int mi = 0; mi < 2; mi++) {
        size_t r0 = (size_t)(s0 + warpM*32 + mi*16 + g);
        #pragma unroll
        for (int ni = 0; ni < 8; ni++) {
            size_t c0 = (size_t)(t0 + warpN*64 + ni*8 + tg*2);
            *(float2*)(out + r0*CK_S + c0) =
                make_float2(acc[mi][ni][0]*scl, acc[mi][ni][1]*scl);
            *(float2*)(out + (r0+8)*CK_S + c0) =
                make_float2(acc[mi][ni][2]*scl, acc[mi][ni][3]*scl);
        }
    }
}

// ===========================================================================
// k_avh: out(fp16) = attn(fp16) @ V^T(fp16), ldmatrix, 3-stage pipeline
// ===========================================================================
#define AV_LD   40
#define AV_TILE (128*AV_LD)
#define AV_TILEB (AV_TILE*2)
#define AV_ST   3
#define AV_SMEM (AV_ST*2*AV_TILEB)   // 61440 B

__global__ void __launch_bounds__(256, 2) k_avh(const __half* __restrict__ attn,
                                                const __half* __restrict__ vt,
                                                __half* __restrict__ outh) {
    extern __shared__ __align__(16) __half sm[];
    const uint32_t sbA = smem_u32(sm);
    const uint32_t sbW = sbA + AV_ST*AV_TILEB;

    const int s0 = blockIdx.y * 128;
    const int bh = blockIdx.z, b = bh >> 4, h = bh & 15, kv = h >> 2;
    const __half* Ab = attn + (size_t)bh*CK_S*CK_S;
    const __half* Wb = vt + ((size_t)(b*CK_KV + kv)*CK_HD)*CK_S;

    const int tid = threadIdx.x;
    const int wid = tid >> 5, lane = tid & 31;
    const int g = lane >> 2, tg = lane & 3;
    const int warpM = wid & 3, warpN = wid >> 2;
    const int lt = lane >> 3, lr = lane & 7;
    const uint32_t offA = (uint32_t)((((lt & 1)*8 + lr)*AV_LD + (lt >> 1)*8) * 2);
    const uint32_t offB = (uint32_t)((((lt >> 1)*8 + lr)*AV_LD + (lt & 1)*8) * 2);
    const uint32_t rowA0 = (uint32_t)((warpM*32     )*AV_LD*2);
    const uint32_t rowA1 = (uint32_t)((warpM*32 + 16)*AV_LD*2);

    float acc[2][8][4];
    #pragma unroll
    for (int mi = 0; mi < 2; mi++)
        #pragma unroll
        for (int ni = 0; ni < 8; ni++)
            #pragma unroll
            for (int q = 0; q < 4; q++) acc[mi][ni][q] = 0.f;

    const int NC = (s0 + 128) / 32;   // >= 4, so prologue fills both stages

    auto load_async = [&](int c, int buf) {
        const int k0 = c * 32;
        const uint32_t bo = (uint32_t)buf * AV_TILEB;
        #pragma unroll
        for (int it = 0; it < 2; it++) {
            int id = it*256 + tid;
            int r = id >> 2, sg = (id & 3) * 8;
            uint32_t so = bo + (uint32_t)(r*AV_LD + sg)*2;
            CP_ASYNC16(sbA + so, Ab + (size_t)(s0 + r)*CK_S + k0 + sg);
            CP_ASYNC16(sbW + so, Wb + (size_t)r*CK_S + k0 + sg);
        }
        CP_COMMIT();
    };

    #pragma unroll
    for (int p = 0; p < AV_ST - 1; p++)
        load_async(p, p);

    for (int c = 0; c < NC; c++) {
        const int cur = c % AV_ST;
        const int nx = c + AV_ST - 1;
        if (nx < NC)           { load_async(nx, nx % AV_ST); CP_WAIT(AV_ST - 1); }
        else if (c == NC - 2)  { CP_WAIT(1); }
        else                   { CP_WAIT(0); }
        __syncthreads();

        const uint32_t sA = sbA + (uint32_t)cur*AV_TILEB;
        const uint32_t sW = sbW + (uint32_t)cur*AV_TILEB;
        #pragma unroll
        for (int ks = 0; ks < 2; ks++) {
            const uint32_t colOff = (uint32_t)(ks*16*2);
            uint32_t a[2][4];
            ldsm_x4(a[0][0], a[0][1], a[0][2], a[0][3], sA + rowA0 + offA + colOff);
            ldsm_x4(a[1][0], a[1][1], a[1][2], a[1][3], sA + rowA1 + offA + colOff);
            #pragma unroll
            for (int np = 0; np < 4; np++) {
                uint32_t b00, b01, b10, b11;
                uint32_t rowB = (uint32_t)((warpN*64 + np*16)*AV_LD*2);
                ldsm_x4(b00, b01, b10, b11, sW + rowB + offB + colOff);
                #pragma unroll
                for (int mi = 0; mi < 2; mi++) {
                    mma16816(acc[mi][2*np],   a[mi], b00, b01);
                    mma16816(acc[mi][2*np+1], a[mi], b10, b11);
                }
            }
        }
        __syncthreads();
    }

    #pragma unroll
    for (int mi = 0; mi < 2; mi++) {
        int s = s0 + warpM*32 + mi*16 + g;
        #pragma unroll
        for (int ni = 0; ni < 8; ni++) {
            int c0 = warpN*64 + ni*8 + tg*2;
            size_t off0 = ((size_t)(b*CK_S + s)*CK_H + h)*CK_HD + c0;
            size_t off1 = ((size_t)(b*CK_S + s + 8)*CK_H + h)*CK_HD + c0;
            *(__half2*)(outh + off0) = __floats2half2_rn(acc[mi][ni][0], acc[mi][ni][1]);
            *(__half2*)(outh + off1) = __floats2half2_rn(acc[mi][ni][2], acc[mi][ni][3]);
        }
    }
}

// ---------------------------------------------------------------------------
// k_vt: V fp16 [t][kv*HD] -> V^T fp16 [b][kv][hd][s]
// ---------------------------------------------------------------------------
__global__ void k_vt(const __half* __restrict__ xv, __half* __restrict__ vt) {
    int bkv = blockIdx.z, b = bkv >> 2, kv = bkv & 3;
    int s0 = blockIdx.x*32, h0 = blockIdx.y*32;
    __shared__ __half t[32][33];
    int x = threadIdx.x & 31, y = threadIdx.x >> 5;
    for (int i = y; i < 32; i += 8)
        t[i][x] = xv[(size_t)(b*CK_S + s0 + i)*(CK_KV*CK_HD) + kv*CK_HD + h0 + x];
    __syncthreads();
    for (int i = y; i < 32; i += 8)
        vt[((size_t)bkv*CK_HD + h0 + i)*CK_S + s0 + x] = t[x][i];
}

// ---------------------------------------------------------------------------
// RMSNorm (fp32 out + fp16 out)
// ---------------------------------------------------------------------------
__global__ void k_rmsnorm(const float* __restrict__ x, const float* __restrict__ w,
                          float* __restrict__ o, __half* __restrict__ oh) {
    int t = blockIdx.x;
    const float* xr = x + (size_t)t*CK_D;
    float ss = 0.f;
    for (int i = threadIdx.x; i < CK_D; i += 256) { float v = xr[i]; ss += v*v; }
    __shared__ float red[256];
    red[threadIdx.x] = ss; __syncthreads();
    for (int s = 128; s > 0; s >>= 1) {
        if (threadIdx.x < s) red[threadIdx.x] += red[threadIdx.x+s];
        __syncthreads();
    }
    float sc = rsqrtf(red[0]/(float)CK_D + 1e-5f);
    float* orow = o + (size_t)t*CK_D;
    __half* hrow = oh + (size_t)t*CK_D;
    for (int i = threadIdx.x; i < CK_D; i += 256) {
        float r = xr[i]*sc*w[i];
        orow[i] = r;
        hrow[i] = __float2half_rn(r);
    }
}

// ---------------------------------------------------------------------------
// Fused q/k/v LoRA downs (fp32 X)
// ---------------------------------------------------------------------------
__global__ void k_lora_down3(const float* __restrict__ X,
                             const float* __restrict__ A1, const float* __restrict__ A2,
                             const float* __restrict__ A3,
                             float* __restrict__ U1, float* __restrict__ U2,
                             float* __restrict__ U3) {
    int t = blockIdx.x;
    __shared__ float sx[CK_D];
    for (int i = threadIdx.x; i < CK_D; i += 256) sx[i] = X[(size_t)t*CK_D + i];
    __syncthreads();
    int w = threadIdx.x >> 5, lane = threadIdx.x & 31;
    for (int rr = w; rr < 48; rr += 8) {
        int m = rr >> 4, r = rr & 15;
        const float* ar = (m == 0 ? A1 : m == 1 ? A2 : A3) + (size_t)r*CK_D;
        float p = 0.f;
        for (int d = lane; d < CK_D; d += 32) p += sx[d]*ar[d];
        for (int o = 16; o; o >>= 1) p += __shfl_down_sync(0xffffffffu, p, o);
        if (lane == 0) (m == 0 ? U1 : m == 1 ? U2 : U3)[t*CK_R + r] = p;
    }
}

// LoRA down with fp16 X input
__global__ void k_lora_down_h(const __half* __restrict__ X, const float* __restrict__ A,
                              float* __restrict__ U) {
    int t = blockIdx.x;
    __shared__ float sx[CK_D];
    for (int i = threadIdx.x; i < CK_D; i += 256)
        sx[i] = __half2float(X[(size_t)t*CK_D + i]);
    __syncthreads();
    int w = threadIdx.x >> 5, lane = threadIdx.x & 31;
    for (int r = w; r < CK_R; r += 8) {
        const float* ar = A + (size_t)r*CK_D;
        float p = 0.f;
        for (int d = lane; d < CK_D; d += 32) p += sx[d]*ar[d];
        for (int o = 16; o; o >>= 1) p += __shfl_down_sync(0xffffffffu, p, o);
        if (lane == 0) U[t*CK_R + r] = p;
    }
}

// ---------------------------------------------------------------------------
// Causal softmax (MUFU-free exp): fp32 scores in, fp16 attn out
// ---------------------------------------------------------------------------
__global__ void k_softmax(const float* __restrict__ sc, __half* __restrict__ sch) {
    int row = blockIdx.x;
    int s = row & (CK_S - 1);
    const float* p = sc + (size_t)row*CK_S;
    __half* ph = sch + (size_t)row*CK_S;
    int L = s + 1;
    int tid = threadIdx.x;
    float v0 = (tid       < L) ? p[tid]       : -1e30f;
    float v1 = (tid + 256 < L) ? p[tid + 256] : -1e30f;
    __shared__ float red[256];
    red[tid] = fmaxf(v0, v1); __syncthreads();
    for (int st = 128; st; st >>= 1) {
        if (tid < st) red[tid] = fmaxf(red[tid], red[tid+st]);
        __syncthreads();
    }
    float m = red[0]; __syncthreads();
    float e0 = (tid       < L) ? fexp(v0 - m) : 0.f;
    float e1 = (tid + 256 < L) ? fexp(v1 - m) : 0.f;
    red[tid] = e0 + e1; __syncthreads();
    for (int st = 128; st; st >>= 1) {
        if (tid < st) red[tid] += red[tid+st];
        __syncthreads();
    }
    float inv = 1.f / red[0];
    ph[tid]       = __float2half_rn(e0 * inv);
    ph[tid + 256] = __float2half_rn(e1 * inv);
}

// ---------------------------------------------------------------------------
// Gate
// ---------------------------------------------------------------------------
__global__ void k_gate(const float* __restrict__ hn, const float* __restrict__ gw,
                       float* __restrict__ route) {
    int t = blockIdx.x;
    __shared__ float sl[8];
    int w = threadIdx.x >> 5, lane = threadIdx.x & 31;
    const float* xr = hn + (size_t)t*CK_D;
    const float* gr = gw + (size_t)w*CK_D;
    float p = 0.f;
    for (int d = lane; d < CK_D; d += 32) p += xr[d]*gr[d];
    for (int o = 16; o; o >>= 1) p += __shfl_down_sync(0xffffffffu, p, o);
    if (lane == 0) sl[w] = p;
    __syncthreads();
    if (threadIdx.x == 0) {
        int i0 = 0;
        for (int e = 1; e < 8; e++) if (sl[e] > sl[i0]) i0 = e;
        int i1 = -1;
        for (int e = 0; e < 8; e++) { if (e == i0) continue; if (i1 < 0 || sl[e] > sl[i1]) i1 = e; }
        float m = sl[i0];
        float v0 = expf(sl[i0]-m), v1 = expf(sl[i1]-m);
        float inv = 1.f/(v0+v1);
        float* rr = route + (size_t)t*CK_E;
        #pragma unroll
        for (int e = 0; e < 8; e++) rr[e] = 0.f;
        rr[i0] = v0*inv; rr[i1] = v1*inv;
    }
}

// ---------------------------------------------------------------------------
// Expert LoRA downs
// ---------------------------------------------------------------------------
__global__ void k_expert_down(const float* __restrict__ X, const float* __restrict__ A1,
                              const float* __restrict__ A3, const float* __restrict__ route,
                              float* __restrict__ U1, float* __restrict__ U3) {
    int t = blockIdx.x, e = blockIdx.y;
    if (route[t*CK_E + e] == 0.f) return;
    __shared__ float sx[CK_D];
    for (int i = threadIdx.x; i < CK_D; i += 256) sx[i] = X[(size_t)t*CK_D + i];
    __syncthreads();
    int w = threadIdx.x >> 5, lane = threadIdx.x & 31;
    const float* a1 = A1 + (size_t)e*CK_R*CK_D;
    const float* a3 = A3 + (size_t)e*CK_R*CK_D;
    for (int r = w; r < CK_R; r += 8) {
        float p1 = 0.f, p3 = 0.f;
        for (int d = lane; d < CK_D; d += 32) {
            float xv = sx[d];
            p1 += xv*a1[(size_t)r*CK_D + d];
            p3 += xv*a3[(size_t)r*CK_D + d];
        }
        for (int o = 16; o; o >>= 1) {
            p1 += __shfl_down_sync(0xffffffffu, p1, o);
            p3 += __shfl_down_sync(0xffffffffu, p3, o);
        }
        if (lane == 0) {
            U1[((size_t)t*CK_E + e)*CK_R + r] = p1;
            U3[((size_t)t*CK_E + e)*CK_R + r] = p3;
        }
    }
}

// ---------------------------------------------------------------------------
// Fused per-token MoE combine (fp16 h1/h3; fexp + paired rcp silu)
// ---------------------------------------------------------------------------
__device__ __forceinline__ void h8f(const __half* p, float* f) {
    uint4 q = *(const uint4*)p;
    const __half2* hp = (const __half2*)&q;
    #pragma unroll
    for (int j = 0; j < 4; j++) {
        float2 t = __half22float2(hp[j]);
        f[2*j] = t.x; f[2*j+1] = t.y;
    }
}

__global__ void __launch_bounds__(256) k_moe_expert(
    const __half* __restrict__ h1, const __half* __restrict__ h3,
    const float* __restrict__ ua1, const float* __restrict__ ua3,
    const __half* __restrict__ eB1, const __half* __restrict__ eB3,
    const __half* __restrict__ eA2, const float* __restrict__ route,
    __half* __restrict__ ghs, float* __restrict__ v2)
{
    const int t = blockIdx.x;
    const int tid = threadIdx.x;
    const int wid = tid >> 5, lane = tid & 31;
    const int NI = CK_FFN/256;   // 22
    float ghacc[CK_FFN/256];
    #pragma unroll
    for (int i = 0; i < NI; i++) ghacc[i] = 0.f;
    __shared__ float su1[16], su3[16];
    __shared__ float part[8][16];
    const __half* h1r = h1 + (size_t)t*CK_FFN;
    const __half* h3r = h3 + (size_t)t*CK_FFN;

    #pragma unroll 1
    for (int e = 0; e < CK_E; e++) {
        float wgt = route[t*CK_E + e];
        if (wgt == 0.f) {
            if (tid < 16) v2[(size_t)t*(CK_E*CK_R) + e*16 + tid] = 0.f;
            continue;
        }
        if (tid < 16) {
            su1[tid] = ua1[((size_t)t*CK_E + e)*16 + tid];
            su3[tid] = ua3[((size_t)t*CK_E + e)*16 + tid];
        }
        __syncthreads();
        float u1[16], u3[16];
        #pragma unroll
        for (int r = 0; r < 16; r++) { u1[r] = su1[r]; u3[r] = su3[r]; }
        float accr[16];
        #pragma unroll
        for (int r = 0; r < 16; r++) accr[r] = 0.f;
        const __half* B1 = eB1 + (size_t)e*CK_FFN*16;
        const __half* B3 = eB3 + (size_t)e*CK_FFN*16;
        const __half* A2 = eA2 + (size_t)e*16*CK_FFN;
        #pragma unroll 1
        for (int ii = 0; ii < NI; ii += 2) {
            float prod[2], esig[2];
            const int fA = ii*256 + tid, fB = fA + 256;
            #pragma unroll
            for (int hi = 0; hi < 2; hi++) {
                int f = hi ? fB : fA;
                float b1v[16], b3v[16];
                h8f(B1 + (size_t)f*16,     b1v);
                h8f(B1 + (size_t)f*16 + 8, b1v + 8);
                h8f(B3 + (size_t)f*16,     b3v);
                h8f(B3 + (size_t)f*16 + 8, b3v + 8);
                float b1 = 0.f, b3 = 0.f;
                #pragma unroll
                for (int r = 0; r < 16; r++) { b1 += u1[r]*b1v[r]; b3 += u3[r]*b3v[r]; }
                float g1 = __half2float(h1r[f]) + CK_LS*b1;
                float g3 = __half2float(h3r[f]) + CK_LS*b3;
                prod[hi] = g1*g3;
                esig[hi] = fexp(-g1);
            }
            float da = 1.f + esig[0], db = 1.f + esig[1];
            float rr;
            asm("rcp.approx.f32 %0, %1;" : "=f"(rr) : "f"(da*db));
            float gh[2];
            gh[0] = prod[0]*(rr*db);
            gh[1] = prod[1]*(rr*da);
            ghacc[ii]   += wgt*gh[0];
            ghacc[ii+1] += wgt*gh[1];
            #pragma unroll
            for (int hi = 0; hi < 2; hi++) {
                int f = hi ? fB : fA;
                #pragma unroll
                for (int r = 0; r < 16; r++)
                    accr[r] += gh[hi] * __half2float(A2[(size_t)r*CK_FFN + f]);
            }
        }
        #pragma unroll
        for (int r = 0; r < 16; r++) {
            float v = accr[r];
            #pragma unroll
            for (int o = 16; o; o >>= 1) v += __shfl_down_sync(0xffffffffu, v, o);
            if (lane == 0) part[wid][r] = v;
        }
        __syncthreads();
        if (tid < 16) {
            float s2 = 0.f;
            #pragma unroll
            for (int ww = 0; ww < 8; ww++) s2 += part[ww][tid];
            v2[(size_t)t*(CK_E*CK_R) + e*16 + tid] = wgt*CK_LS*s2;
        }
        __syncthreads();
    }
    __half* go = ghs + (size_t)t*CK_FFN;
    #pragma unroll
    for (int ii = 0; ii < NI; ii++) go[ii*256 + tid] = __float2half_rn(ghacc[ii]);
}

// ---------------------------------------------------------------------------
// fpre = data2 + v2 @ eB2^T
// ---------------------------------------------------------------------------
__global__ void k_moe_up(const float* __restrict__ d2, const float* __restrict__ v2,
                         const __half* __restrict__ eB2, const float* __restrict__ route,
                         float* __restrict__ out) {
    int t = blockIdx.x, tid = threadIdx.x;
    __shared__ float sv[128];
    __shared__ int act[8];
    if (tid < 128) sv[tid] = v2[(size_t)t*128 + tid];
    if (tid < 8)   act[tid] = (route[t*CK_E + tid] != 0.f) ? 1 : 0;
    __syncthreads();
    for (int d = tid; d < CK_D; d += 256) {
        float s = d2[(size_t)t*CK_D + d];
        #pragma unroll 1
        for (int e = 0; e < 8; e++) {
            if (!act[e]) continue;
            float bv[16];
            const __half* bp = eB2 + ((size_t)e*CK_D + d)*16;
            h8f(bp, bv); h8f(bp + 8, bv + 8);
            #pragma unroll
            for (int r = 0; r < 16; r++) s += sv[e*16+r]*bv[r];
        }
        out[(size_t)t*CK_D + d] = s;
    }
}

// ---------------------------------------------------------------------------
// Launch
// ---------------------------------------------------------------------------
extern "C" void kernel_launch(void* const* d_in, const int* in_sizes, int n_in,
                              void* d_out, int out_size) {
    (void)in_sizes; (void)n_in; (void)out_size;
    const float* data  = (const float*)d_in[0];
    const float* rc    = (const float*)d_in[2];
    const float* rs    = (const float*)d_in[3];
    const float* att_w = (const float*)d_in[4];
    const float* ffn_w = (const float*)d_in[5];
    const float* wq    = (const float*)d_in[6];
    const float* wk    = (const float*)d_in[7];
    const float* wv    = (const float*)d_in[8];
    const float* wo    = (const float*)d_in[9];
    const float* lqA   = (const float*)d_in[10];
    const float* lqB   = (const float*)d_in[11];
    const float* lkA   = (const float*)d_in[12];
    const float* lkB   = (const float*)d_in[13];
    const float* lvA   = (const float*)d_in[14];
    const float* lvB   = (const float*)d_in[15];
    const float* loA   = (const float*)d_in[16];
    const float* loB   = (const float*)d_in[17];
    const float* w1    = (const float*)d_in[18];
    const float* w2    = (const float*)d_in[19];
    const float* w3    = (const float*)d_in[20];
    const float* gatew = (const float*)d_in[21];
    const float* eA1   = (const float*)d_in[22];
    const float* eB1   = (const float*)d_in[23];
    const float* eA2   = (const float*)d_in[24];
    const float* eB2   = (const float*)d_in[25];
    const float* eA3   = (const float*)d_in[26];
    const float* eB3   = (const float*)d_in[27];
    float* out = (float*)d_out;

    float *p_h,*p_hn,*p_sc,*p_d2,*p_uq,*p_uk,*p_uv,*p_uo;
    float *p_route,*p_ua1,*p_ua3,*p_v2,*p_fpre;
    cudaGetSymbolAddress((void**)&p_h,    g_h);
    cudaGetSymbolAddress((void**)&p_hn,   g_hn);
    cudaGetSymbolAddress((void**)&p_sc,   g_sc);
    cudaGetSymbolAddress((void**)&p_d2,   g_d2);
    cudaGetSymbolAddress((void**)&p_uq,   g_uq);
    cudaGetSymbolAddress((void**)&p_uk,   g_uk);
    cudaGetSymbolAddress((void**)&p_uv,   g_uv);
    cudaGetSymbolAddress((void**)&p_uo,   g_uo);
    cudaGetSymbolAddress((void**)&p_route,g_route);
    cudaGetSymbolAddress((void**)&p_ua1,  g_ua1);
    cudaGetSymbolAddress((void**)&p_ua3,  g_ua3);
    cudaGetSymbolAddress((void**)&p_v2,   g_v2);
    cudaGetSymbolAddress((void**)&p_fpre, g_fpre);

    __half *wqh,*wkh,*wvh,*woh,*w1h,*w3h,*w2h;
    __half *xh,*aoh,*hnh,*gsh,*xqh,*xkh,*xvh,*vth,*sch,*h1h,*h3h;
    __half *eB1h,*eB3h,*eA2h,*eB2h;
    cudaGetSymbolAddress((void**)&wqh, g_wqh);
    cudaGetSymbolAddress((void**)&wkh, g_wkh);
    cudaGetSymbolAddress((void**)&wvh, g_wvh);
    cudaGetSymbolAddress((void**)&woh, g_woh);
    cudaGetSymbolAddress((void**)&w1h, g_w1h);
    cudaGetSymbolAddress((void**)&w3h, g_w3h);
    cudaGetSymbolAddress((void**)&w2h, g_w2h);
    cudaGetSymbolAddress((void**)&xh,  g_xh);
    cudaGetSymbolAddress((void**)&aoh, g_aoh);
    cudaGetSymbolAddress((void**)&hnh, g_hnh);
    cudaGetSymbolAddress((void**)&gsh, g_gsh);
    cudaGetSymbolAddress((void**)&xqh, g_xqh);
    cudaGetSymbolAddress((void**)&xkh, g_xkh);
    cudaGetSymbolAddress((void**)&xvh, g_xvh);
    cudaGetSymbolAddress((void**)&vth, g_vth);
    cudaGetSymbolAddress((void**)&sch, g_sch);
    cudaGetSymbolAddress((void**)&h1h, g_h1h);
    cudaGetSymbolAddress((void**)&h3h, g_h3h);
    cudaGetSymbolAddress((void**)&eB1h, g_eB1h);
    cudaGetSymbolAddress((void**)&eB3h, g_eB3h);
    cudaGetSymbolAddress((void**)&eA2h, g_eA2h);
    cudaGetSymbolAddress((void**)&eB2h, g_eB2h);

    cudaFuncSetAttribute(k_hgemm4,   cudaFuncAttributeMaxDynamicSharedMemorySize, HG_SMEM);
    cudaFuncSetAttribute(k_scores_h, cudaFuncAttributeMaxDynamicSharedMemorySize, SC_SMEM);
    cudaFuncSetAttribute(k_avh,      cudaFuncAttributeMaxDynamicSharedMemorySize, AV_SMEM);

    // --- all weight conversions in one launch ---
    k_conv_all<<<(int)((CBT/8 + 255)/256),256>>>(
        wq, wk, wv, wo, w1, w3, w2, eB1, eB3, eA2, eB2,
        wqh, wkh, wvh, woh, w1h, w3h, w2h, eB1h, eB3h, eA2h, eB2h);

    // --- attention path ---
    k_rmsnorm<<<CK_T,256>>>(data, att_w, p_h, xh);
    k_lora_down3<<<CK_T,256>>>(p_h, lqA, lkA, lvA, p_uq, p_uk, p_uv);
    k_hgemm4<<<dim3(CK_D/128, CK_T/128),256,HG_SMEM>>>(xh, wqh, nullptr, xqh, CK_T, CK_D, CK_D, p_uq, 16, lqB, CK_LS, nullptr, rc, rs);
    k_hgemm4<<<dim3(512/128,  CK_T/128),256,HG_SMEM>>>(xh, wkh, nullptr, xkh, CK_T, 512,  CK_D, p_uk, 16, lkB, CK_LS, nullptr, rc, rs);
    k_hgemm4<<<dim3(512/128,  CK_T/128),256,HG_SMEM>>>(xh, wvh, nullptr, xvh, CK_T, 512,  CK_D, p_uv, 16, lvB, CK_LS, nullptr, nullptr, nullptr);
    k_vt<<<dim3(CK_S/32, CK_HD/32, CK_B*CK_KV),256>>>(xvh, vth);
    k_scores_h<<<dim3(CK_S/128, CK_S/128, CK_B*CK_H),256,SC_SMEM>>>(xqh, xkh, p_sc);
    k_softmax<<<CK_B*CK_H*CK_S,256>>>(p_sc, sch);
    k_avh<<<dim3(1, CK_S/128, CK_B*CK_H),256,AV_SMEM>>>(sch, vth, aoh);
    k_lora_down_h<<<CK_T,256>>>(aoh, loA, p_uo);
    k_hgemm4<<<dim3(CK_D/128, CK_T/128),256,HG_SMEM>>>(aoh, woh, p_d2, nullptr, CK_T, CK_D, CK_D, p_uo, 16, loB, CK_LS, data, nullptr, nullptr);

    // --- MoE path ---
    k_rmsnorm<<<CK_T,256>>>(p_d2, ffn_w, p_hn, hnh);
    k_gate<<<CK_T,256>>>(p_hn, gatew, p_route);
    k_expert_down<<<dim3(CK_T, CK_E),256>>>(p_hn, eA1, eA3, p_route, p_ua1, p_ua3);
    k_hgemm4<<<dim3(CK_FFN/128, CK_T/128),256,HG_SMEM>>>(hnh, w1h, nullptr, h1h, CK_T, CK_FFN, CK_D, nullptr, 0, nullptr, 0.f, nullptr, nullptr, nullptr);
    k_hgemm4<<<dim3(CK_FFN/128, CK_T/128),256,HG_SMEM>>>(hnh, w3h, nullptr, h3h, CK_T, CK_FFN, CK_D, nullptr, 0, nullptr, 0.f, nullptr, nullptr, nullptr);
    k_moe_expert<<<CK_T,256>>>(h1h, h3h, p_ua1, p_ua3, eB1h, eB3h, eA2h, p_route, gsh, p_v2);
    k_moe_up<<<CK_T,256>>>(p_d2, p_v2, eB2h, p_route, p_fpre);
    k_hgemm4<<<dim3(CK_D/128, CK_T/128),256,HG_SMEM>>>(gsh, w2h, out, nullptr, CK_T, CK_D, CK_FFN, nullptr, 0, nullptr, 0.f, p_fpre, nullptr, nullptr);
}